// round 7
// baseline (speedup 1.0000x reference)
#include <cuda_runtime.h>
#include <cuda_bf16.h>
#include <cstdint>

#define NN 24576
#define NE 98304
#define NG 512
#define NB 512
#define LL 1000

// ---------------- scratch (device globals; runtime alloc forbidden) ----------------
__device__ float g_h1[NN*128];
__device__ float g_as1[NN*2];
__device__ float g_ad1[NN*2];
__device__ float g_m1[NN*2];
__device__ float g_den1[NN*2];
__device__ float g_e1[(NE+NN)*2];
__device__ float g_out1[NN*128];
__device__ float g_h2[NN*128];
__device__ float g_as2[NN];
__device__ float g_ad2[NN];
__device__ float g_m2[NN];
__device__ float g_den2[NN];
__device__ float g_e2[NE+NN];
__device__ float g_out2[NN*128];
__device__ float g_sums[NG*128];
__device__ float g_cnt[NG];
__device__ float g_drug[NG*256];
__device__ float g_T[3*22*64];
__device__ float g_p1[NB*LL*64];
__device__ float g_pmax[NB*128];
__device__ float g_prot[NB*256];

// ---------------- helpers ----------------
__device__ __forceinline__ void red_add_v4(float* addr, float4 v) {
    asm volatile("red.global.add.v4.f32 [%0], {%1, %2, %3, %4};"
                 :: "l"(addr), "f"(v.x), "f"(v.y), "f"(v.z), "f"(v.w) : "memory");
}
__device__ __forceinline__ void atomicMaxFloat(float* addr, float val) {
    if (val >= 0.f) atomicMax((int*)addr, __float_as_int(val));
    else            atomicMin((unsigned int*)addr, __float_as_uint(val));
}
__device__ __forceinline__ float warp_sum(float v) {
    #pragma unroll
    for (int off = 16; off; off >>= 1) v += __shfl_down_sync(0xffffffffu, v, off);
    return v;
}
__device__ __forceinline__ float elu1(float v) { return v > 0.f ? v : expm1f(v); }

__device__ __forceinline__ void mma_bf16(float* c, const uint32_t* a, const uint32_t* b) {
    asm volatile(
        "mma.sync.aligned.m16n8k16.row.col.f32.bf16.bf16.f32 "
        "{%0,%1,%2,%3}, {%4,%5,%6,%7}, {%8,%9}, {%0,%1,%2,%3};"
        : "+f"(c[0]), "+f"(c[1]), "+f"(c[2]), "+f"(c[3])
        : "r"(a[0]), "r"(a[1]), "r"(a[2]), "r"(a[3]), "r"(b[0]), "r"(b[1]));
}
__device__ __forceinline__ void ldsm_x4(uint32_t* r, uint32_t addr) {
    asm volatile("ldmatrix.sync.aligned.m8n8.x4.shared.b16 {%0,%1,%2,%3}, [%4];"
                 : "=r"(r[0]), "=r"(r[1]), "=r"(r[2]), "=r"(r[3]) : "r"(addr));
}
__device__ __forceinline__ uint32_t smem_u32(const void* p) {
    uint32_t a;
    asm("{ .reg .u64 t; cvta.to.shared.u64 t, %1; cvt.u32.u64 %0, t; }" : "=r"(a) : "l"(p));
    return a;
}

// ---------------- conv2 via HMMA + ldmatrix + reg double-buffer ----------------
// GEMM: M=128 l, N=128 o, K=320 (5 taps x 64 ch), im2col via A row overlap.
// A: 132 rows x 64 ch, stride 72 elems (144B, banks rows step 4 -> LDSM conflict-free).
// B: 128 o x 320 k, stride 328 elems (656B, same property).
#define C2_A_STRIDE 72
#define C2_AH 0
#define C2_AL 19584
#define C2_BH 39168
#define C2_B_STRIDE 328
#define C2_BL 123136
#define C2_SMEM 207104
#define C2_TILES (NB*8)

struct C2Frag {
    uint32_t ah[4][4];
    uint32_t al[4][4];
    uint32_t b[4][4];    // [nt] = {bh0, bh1, bl0, bl1}
};

__global__ void __launch_bounds__(256) k_conv2_hmma(const float* __restrict__ K2,
                                                    const float* __restrict__ bk2) {
    extern __shared__ char smem[];
    __nv_bfloat16* Bh = reinterpret_cast<__nv_bfloat16*>(smem + C2_BH);
    __nv_bfloat16* Bl = reinterpret_cast<__nv_bfloat16*>(smem + C2_BL);
    uint32_t* AhW = reinterpret_cast<uint32_t*>(smem + C2_AH);
    uint32_t* AlW = reinterpret_cast<uint32_t*>(smem + C2_AL);

    int tid = threadIdx.x, wid = tid >> 5, lane = tid & 31;
    int g = lane >> 2, q = lane & 3;
    int mw = (wid >> 2) * 64;
    int nw = (wid & 3) * 32;

    uint32_t sb = smem_u32(smem);
    uint32_t sbAh = sb + C2_AH, sbAl = sb + C2_AL, sbBh = sb + C2_BH;

    // ldmatrix per-lane address components
    // A x4: row = r0 + (lane&15), +16B for lanes 16-31
    uint32_t aoff = (uint32_t)(lane & 15) * 144u + ((lane & 16) ? 16u : 0u);
    // B x4 (bh|bl packed): lanes 0-7 Bh, 8-15 Bh+16B, 16-23 Bl, 24-31 Bl+16B
    uint32_t boff = (uint32_t)(lane & 7) * 656u + ((lane & 8) ? 16u : 0u)
                  + ((lane & 16) ? (uint32_t)(C2_BL - C2_BH) : 0u);

    // ---- B conversion (once per CTA) ----
    for (int idx = tid; idx < 128*320; idx += 256) {
        int n = idx / 320, k = idx - n*320;
        int t = k >> 6, i = k & 63;
        float v = K2[(n*64 + i)*5 + t];
        __nv_bfloat16 hb = __float2bfloat16_rn(v);
        __nv_bfloat16 lb = __float2bfloat16_rn(v - __bfloat162float(hb));
        Bh[n*C2_B_STRIDE + k] = hb;
        Bl[n*C2_B_STRIDE + k] = lb;
    }

    float bias[4][2];
    #pragma unroll
    for (int nt = 0; nt < 4; nt++) {
        int col = nw + nt*8 + q*2;
        bias[nt][0] = bk2[col];
        bias[nt][1] = bk2[col + 1];
    }

    for (int tile = blockIdx.x; tile < C2_TILES; tile += gridDim.x) {
        int b = tile >> 3, l0 = (tile & 7) * 125;
        __syncthreads();

        // ---- A load + hi/lo conversion ----
        for (int idx = tid; idx < 132*32; idx += 256) {
            int row = idx >> 5, p = idx & 31;
            int l = l0 + row - 2;
            float2 v = make_float2(0.f, 0.f);
            if (l >= 0 && l < LL)
                v = *reinterpret_cast<const float2*>(&g_p1[((size_t)b*LL + l)*64 + p*2]);
            __nv_bfloat162 h2 = __floats2bfloat162_rn(v.x, v.y);
            __nv_bfloat162 l2 = __floats2bfloat162_rn(v.x - __bfloat162float(h2.x),
                                                      v.y - __bfloat162float(h2.y));
            AhW[row*(C2_A_STRIDE/2) + p] = *reinterpret_cast<uint32_t*>(&h2);
            AlW[row*(C2_A_STRIDE/2) + p] = *reinterpret_cast<uint32_t*>(&l2);
        }
        __syncthreads();

        float acc[4][4][4];
        #pragma unroll
        for (int mt = 0; mt < 4; mt++)
            #pragma unroll
            for (int nt = 0; nt < 4; nt++)
                #pragma unroll
                for (int j = 0; j < 4; j++) acc[mt][nt][j] = 0.f;

        C2Frag f0, f1;

        auto load_frag = [&](C2Frag& f, int ks) {
            int t = ks >> 2;
            uint32_t kb = (uint32_t)((ks & 3) * 32);             // byte offset within row group
            uint32_t aBase = (uint32_t)((mw + t) * 144) + kb + aoff;
            #pragma unroll
            for (int mt = 0; mt < 4; mt++) {
                ldsm_x4(f.ah[mt], sbAh + aBase + (uint32_t)(mt*16*144));
                ldsm_x4(f.al[mt], sbAl + aBase + (uint32_t)(mt*16*144));
            }
            uint32_t bBase = (uint32_t)(nw * 656) + (uint32_t)(t * 128) + kb + boff;
            #pragma unroll
            for (int nt = 0; nt < 4; nt++)
                ldsm_x4(f.b[nt], sbBh + bBase + (uint32_t)(nt*8*656));
        };
        auto mma_frag = [&](C2Frag& f) {
            #pragma unroll
            for (int mt = 0; mt < 4; mt++)
                #pragma unroll
                for (int nt = 0; nt < 4; nt++) {
                    mma_bf16(acc[mt][nt], f.ah[mt], &f.b[nt][0]);   // ah*bh
                    mma_bf16(acc[mt][nt], f.ah[mt], &f.b[nt][2]);   // ah*bl
                    mma_bf16(acc[mt][nt], f.al[mt], &f.b[nt][0]);   // al*bh
                }
        };

        load_frag(f0, 0);
        #pragma unroll 1
        for (int ks = 0; ks < 20; ks += 2) {
            load_frag(f1, ks + 1);
            mma_frag(f0);
            if (ks + 2 < 20) load_frag(f0, ks + 2);
            mma_frag(f1);
        }

        // ---- epilogue: bias + elu + max over valid l ----
        float mx[4][2];
        #pragma unroll
        for (int nt = 0; nt < 4; nt++) { mx[nt][0] = -3.0e38f; mx[nt][1] = -3.0e38f; }
        #pragma unroll
        for (int mt = 0; mt < 4; mt++) {
            int lr = l0 + mw + mt*16 + g;
            bool v0 = lr < LL, v1 = (lr + 8) < LL;
            #pragma unroll
            for (int nt = 0; nt < 4; nt++) {
                if (v0) {
                    mx[nt][0] = fmaxf(mx[nt][0], elu1(acc[mt][nt][0] + bias[nt][0]));
                    mx[nt][1] = fmaxf(mx[nt][1], elu1(acc[mt][nt][1] + bias[nt][1]));
                }
                if (v1) {
                    mx[nt][0] = fmaxf(mx[nt][0], elu1(acc[mt][nt][2] + bias[nt][0]));
                    mx[nt][1] = fmaxf(mx[nt][1], elu1(acc[mt][nt][3] + bias[nt][1]));
                }
            }
        }
        #pragma unroll
        for (int nt = 0; nt < 4; nt++) {
            #pragma unroll
            for (int j = 0; j < 2; j++) {
                float v = mx[nt][j];
                v = fmaxf(v, __shfl_xor_sync(0xffffffffu, v, 4));
                v = fmaxf(v, __shfl_xor_sync(0xffffffffu, v, 8));
                v = fmaxf(v, __shfl_xor_sync(0xffffffffu, v, 16));
                if (lane < 4)
                    atomicMaxFloat(&g_pmax[b*128 + nw + nt*8 + lane*2 + j], v);
            }
        }
    }
}

// ---------------- conv1 token tables ----------------
__global__ void k_tab(const float* __restrict__ Pe, const float* __restrict__ K1,
                      const float* __restrict__ bk1) {
    int idx = blockIdx.x * blockDim.x + threadIdx.x;
    if (idx >= 3*22*64) return;
    int o = idx & 63, r = idx >> 6;
    int t = r % 22, k = r / 22;
    float acc = (k == 1) ? bk1[o] : 0.f;
    #pragma unroll 8
    for (int i = 0; i < 64; i++) acc += Pe[t*64 + i] * K1[(o*64 + i)*3 + k];
    g_T[idx] = acc;
}

// ---------------- conv1 apply ----------------
__global__ void __launch_bounds__(256) k_conv1_apply(const int* __restrict__ seq) {
    int b = blockIdx.y;
    int lofs = threadIdx.x >> 4, lq = threadIdx.x & 15;
    int l = blockIdx.x * 16 + lofs;
    if (l >= LL) return;
    int s1 = seq[b*LL + l];
    int c = lq * 4;
    float4 v = *reinterpret_cast<const float4*>(&g_T[(22 + s1)*64 + c]);
    if (l > 0) {
        int s0 = seq[b*LL + l - 1];
        float4 a = *reinterpret_cast<const float4*>(&g_T[s0*64 + c]);
        v.x += a.x; v.y += a.y; v.z += a.z; v.w += a.w;
    }
    if (l < LL-1) {
        int s2 = seq[b*LL + l + 1];
        float4 a = *reinterpret_cast<const float4*>(&g_T[(44 + s2)*64 + c]);
        v.x += a.x; v.y += a.y; v.z += a.z; v.w += a.w;
    }
    v.x = elu1(v.x); v.y = elu1(v.y); v.z = elu1(v.z); v.w = elu1(v.w);
    *reinterpret_cast<float4*>(&g_p1[((size_t)b*LL + l)*64 + c]) = v;
}

// ---------------- init ----------------
__global__ void k_init() {
    int i = blockIdx.x * blockDim.x + threadIdx.x;
    int stride = gridDim.x * blockDim.x;
    for (int idx = i; idx < NN*128; idx += stride) { g_out1[idx] = 0.f; g_out2[idx] = 0.f; }
    for (int idx = i; idx < NN*2; idx += stride) { g_m1[idx] = -3.0e38f; g_den1[idx] = 0.f; }
    for (int idx = i; idx < NN; idx += stride) { g_m2[idx] = -3.0e38f; g_den2[idx] = 0.f; }
    for (int idx = i; idx < NG*128; idx += stride) g_sums[idx] = 0.f;
    for (int idx = i; idx < NG; idx += stride) g_cnt[idx] = 0.f;
    for (int idx = i; idx < NB*128; idx += stride) g_pmax[idx] = -3.0e38f;
}

// ---------------- GAT1 GEMM ----------------
__global__ void k_gat1_mm(const float* __restrict__ x, const float* __restrict__ W1) {
    int idx = blockIdx.x * blockDim.x + threadIdx.x;
    if (idx >= NN*128) return;
    int n = idx >> 7, c = idx & 127;
    float acc = 0.f;
    #pragma unroll
    for (int f = 0; f < 5; f++) acc += x[n*5 + f] * W1[f*128 + c];
    g_h1[idx] = acc;
}

// attention scalars, 2 heads of 64
__global__ void k_att1(const float* __restrict__ att_s, const float* __restrict__ att_d) {
    int gw = (blockIdx.x * blockDim.x + threadIdx.x) >> 5;
    int lane = threadIdx.x & 31;
    if (gw >= NN) return;
    const float* hr = g_h1 + (size_t)gw * 128;
    float s0 = hr[lane]*att_s[lane] + hr[lane+32]*att_s[lane+32];
    float s1 = hr[lane+64]*att_s[lane+64] + hr[lane+96]*att_s[lane+96];
    float d0 = hr[lane]*att_d[lane] + hr[lane+32]*att_d[lane+32];
    float d1 = hr[lane+64]*att_d[lane+64] + hr[lane+96]*att_d[lane+96];
    s0 = warp_sum(s0); s1 = warp_sum(s1); d0 = warp_sum(d0); d1 = warp_sum(d1);
    if (lane == 0) {
        g_as1[gw*2] = s0; g_as1[gw*2+1] = s1;
        g_ad1[gw*2] = d0; g_ad1[gw*2+1] = d1;
    }
}

// attention scalars, 1 head of 128
__global__ void k_att2(const float* __restrict__ att_s, const float* __restrict__ att_d) {
    int gw = (blockIdx.x * blockDim.x + threadIdx.x) >> 5;
    int lane = threadIdx.x & 31;
    if (gw >= NN) return;
    const float* hr = g_h2 + (size_t)gw * 128;
    float s = 0.f, d = 0.f;
    #pragma unroll
    for (int t = 0; t < 4; t++) {
        int p = lane + 32*t;
        s += hr[p]*att_s[p];
        d += hr[p]*att_d[p];
    }
    s = warp_sum(s); d = warp_sum(d);
    if (lane == 0) { g_as2[gw] = s; g_ad2[gw] = d; }
}

// ---------------- edge passes ----------------
template<int H>
__global__ void k_edge_max(const int* __restrict__ ei) {
    int e = blockIdx.x * blockDim.x + threadIdx.x;
    const int ET = NE + NN;
    if (e >= ET) return;
    int src, dst;
    if (e < NE) { src = ei[e]; dst = ei[NE + e]; } else { src = dst = e - NE; }
    const float* as_ = (H == 2) ? g_as1 : g_as2;
    const float* ad_ = (H == 2) ? g_ad1 : g_ad2;
    float* m_ = (H == 2) ? g_m1 : g_m2;
    float* e_ = (H == 2) ? g_e1 : g_e2;
    #pragma unroll
    for (int h = 0; h < H; h++) {
        float v = as_[src*H+h] + ad_[dst*H+h];
        v = v > 0.f ? v : 0.2f * v;
        e_[e*H+h] = v;
        atomicMaxFloat(&m_[dst*H+h], v);
    }
}

template<int H>
__global__ void k_edge_den(const int* __restrict__ ei) {
    int e = blockIdx.x * blockDim.x + threadIdx.x;
    const int ET = NE + NN;
    if (e >= ET) return;
    int dst = (e < NE) ? ei[NE + e] : (e - NE);
    const float* m_ = (H == 2) ? g_m1 : g_m2;
    float* den_ = (H == 2) ? g_den1 : g_den2;
    float* e_ = (H == 2) ? g_e1 : g_e2;
    #pragma unroll
    for (int h = 0; h < H; h++) {
        float w = expf(e_[e*H+h] - m_[dst*H+h]);
        e_[e*H+h] = w;
        atomicAdd(&den_[dst*H+h], w);
    }
}

template<int H>
__global__ void k_edge_acc(const int* __restrict__ ei) {
    int gw = (blockIdx.x * blockDim.x + threadIdx.x) >> 5;
    int lane = threadIdx.x & 31;
    const int ET = NE + NN;
    if (gw >= ET) return;
    int src, dst;
    if (gw < NE) { src = ei[gw]; dst = ei[NE + gw]; } else { src = dst = gw - NE; }
    const float* den_ = (H == 2) ? g_den1 : g_den2;
    const float* e_ = (H == 2) ? g_e1 : g_e2;
    const float* hin = (H == 2) ? g_h1 : g_h2;
    float* outp = (H == 2) ? g_out1 : g_out2;
    int h = (H == 2 && lane >= 16) ? 1 : 0;
    float alpha = e_[gw*H + h] / (den_[dst*H + h] + 1e-16f);
    float4 v = *reinterpret_cast<const float4*>(&hin[(size_t)src*128 + lane*4]);
    v.x *= alpha; v.y *= alpha; v.z *= alpha; v.w *= alpha;
    red_add_v4(&outp[(size_t)dst*128 + lane*4], v);
}

template<int WHICH>
__global__ void k_bias_elu(const float* __restrict__ b) {
    int idx = blockIdx.x * blockDim.x + threadIdx.x;
    if (idx >= NN*128) return;
    float* o = (WHICH == 1) ? g_out1 : g_out2;
    o[idx] = elu1(o[idx] + b[idx & 127]);
}

// ---------------- GAT2 GEMM ----------------
__global__ void __launch_bounds__(256) k_gat2_mm(const float* __restrict__ W2) {
    extern __shared__ float sm[];
    float* sg = sm;
    float* sw = sm + 64*128;
    int base = blockIdx.x * 64;
    int tid = threadIdx.x;
    for (int idx = tid; idx < 64*128; idx += 256) sg[idx] = g_out1[(size_t)base*128 + idx];
    for (int idx = tid; idx < 128*128; idx += 256) sw[idx] = W2[idx];
    __syncthreads();
    int r0 = (tid >> 4) << 2;
    int c0 = (tid & 15) << 3;
    float acc[4][8];
    #pragma unroll
    for (int i = 0; i < 4; i++)
        #pragma unroll
        for (int j = 0; j < 8; j++) acc[i][j] = 0.f;
    #pragma unroll 4
    for (int k = 0; k < 128; k++) {
        float a[4];
        #pragma unroll
        for (int i = 0; i < 4; i++) a[i] = sg[(r0+i)*128 + k];
        float4 b0 = *reinterpret_cast<const float4*>(&sw[k*128 + c0]);
        float4 b1 = *reinterpret_cast<const float4*>(&sw[k*128 + c0 + 4]);
        #pragma unroll
        for (int i = 0; i < 4; i++) {
            acc[i][0] += a[i]*b0.x; acc[i][1] += a[i]*b0.y;
            acc[i][2] += a[i]*b0.z; acc[i][3] += a[i]*b0.w;
            acc[i][4] += a[i]*b1.x; acc[i][5] += a[i]*b1.y;
            acc[i][6] += a[i]*b1.z; acc[i][7] += a[i]*b1.w;
        }
    }
    #pragma unroll
    for (int i = 0; i < 4; i++) {
        float4 v0 = make_float4(acc[i][0], acc[i][1], acc[i][2], acc[i][3]);
        float4 v1 = make_float4(acc[i][4], acc[i][5], acc[i][6], acc[i][7]);
        *reinterpret_cast<float4*>(&g_h2[(size_t)(base+r0+i)*128 + c0]) = v0;
        *reinterpret_cast<float4*>(&g_h2[(size_t)(base+r0+i)*128 + c0 + 4]) = v1;
    }
}

// ---------------- pooling + dense ----------------
__global__ void k_pool(const int* __restrict__ batch) {
    int gw = (blockIdx.x * blockDim.x + threadIdx.x) >> 5;
    int lane = threadIdx.x & 31;
    if (gw >= NN) return;
    int g = batch[gw];
    float4 v = *reinterpret_cast<const float4*>(&g_out2[(size_t)gw*128 + lane*4]);
    red_add_v4(&g_sums[g*128 + lane*4], v);
    if (lane == 0) atomicAdd(&g_cnt[g], 1.0f);
}

__global__ void k_drug(const float* __restrict__ Wd, const float* __restrict__ bd) {
    int idx = blockIdx.x * blockDim.x + threadIdx.x;
    if (idx >= NG*256) return;
    int g = idx >> 8, j = idx & 255;
    float invc = 1.f / fmaxf(g_cnt[g], 1.f);
    const float* srow = g_sums + g*128;
    float acc = 0.f;
    #pragma unroll 4
    for (int k = 0; k < 128; k++) acc += srow[k] * Wd[k*256 + j];
    g_drug[idx] = fmaxf(acc * invc + bd[j], 0.f);
}

__global__ void k_prot(const float* __restrict__ Wp, const float* __restrict__ bp) {
    int idx = blockIdx.x * blockDim.x + threadIdx.x;
    if (idx >= NB*256) return;
    int g = idx >> 8, j = idx & 255;
    const float* srow = g_pmax + g*128;
    float acc = 0.f;
    #pragma unroll 4
    for (int k = 0; k < 128; k++) acc += srow[k] * Wp[k*256 + j];
    g_prot[idx] = fmaxf(acc + bp[j], 0.f);
}

// ---------------- head MLP ----------------
__global__ void __launch_bounds__(128) k_head(const float* __restrict__ Wf1, const float* __restrict__ bf1,
                                              const float* __restrict__ Wf2, const float* __restrict__ bf2,
                                              const float* __restrict__ Wo, const float* __restrict__ bo,
                                              float* __restrict__ out) {
    __shared__ float sh[512];
    __shared__ float s1[128];
    __shared__ float s2[64];
    int g = blockIdx.x, tid = threadIdx.x;
    for (int i = tid; i < 256; i += 128) {
        sh[i]       = g_drug[g*256 + i];
        sh[256 + i] = g_prot[g*256 + i];
    }
    __syncthreads();
    float acc = 0.f;
    #pragma unroll 8
    for (int k = 0; k < 512; k++) acc += sh[k] * Wf1[k*128 + tid];
    s1[tid] = fmaxf(acc + bf1[tid], 0.f);
    __syncthreads();
    if (tid < 64) {
        float a = 0.f;
        #pragma unroll 8
        for (int k = 0; k < 128; k++) a += s1[k] * Wf2[k*64 + tid];
        s2[tid] = fmaxf(a + bf2[tid], 0.f);
    }
    __syncthreads();
    if (tid < 32) {
        float a = s2[tid]*Wo[tid] + s2[tid+32]*Wo[tid+32];
        a = warp_sum(a);
        if (tid == 0) out[g] = a + bo[0];
    }
}

// ---------------- launch ----------------
extern "C" void kernel_launch(void* const* d_in, const int* in_sizes, int n_in,
                              void* d_out, int out_size) {
    const float* x        = (const float*)d_in[0];
    const int*   ei       = (const int*)d_in[1];
    const int*   batch    = (const int*)d_in[2];
    const int*   seq      = (const int*)d_in[3];
    const float* W1       = (const float*)d_in[4];
    const float* att_s1   = (const float*)d_in[5];
    const float* att_d1   = (const float*)d_in[6];
    const float* b1       = (const float*)d_in[7];
    const float* W2       = (const float*)d_in[8];
    const float* att_s2   = (const float*)d_in[9];
    const float* att_d2   = (const float*)d_in[10];
    const float* b2       = (const float*)d_in[11];
    const float* Wd       = (const float*)d_in[12];
    const float* bd       = (const float*)d_in[13];
    const float* Pe       = (const float*)d_in[14];
    const float* K1       = (const float*)d_in[15];
    const float* bk1      = (const float*)d_in[16];
    const float* K2       = (const float*)d_in[17];
    const float* bk2      = (const float*)d_in[18];
    const float* Wp       = (const float*)d_in[19];
    const float* bp       = (const float*)d_in[20];
    const float* Wf1      = (const float*)d_in[21];
    const float* bf1      = (const float*)d_in[22];
    const float* Wf2      = (const float*)d_in[23];
    const float* bf2      = (const float*)d_in[24];
    const float* Wo       = (const float*)d_in[25];
    const float* bo       = (const float*)d_in[26];
    float* out = (float*)d_out;

    cudaFuncSetAttribute(k_gat2_mm,    cudaFuncAttributeMaxDynamicSharedMemorySize, 98304);
    cudaFuncSetAttribute(k_conv2_hmma, cudaFuncAttributeMaxDynamicSharedMemorySize, C2_SMEM);

    const int ET = NE + NN;

    // protein branch
    k_tab<<<17, 256>>>(Pe, K1, bk1);                               // 0
    {
        dim3 grid((LL + 15)/16, NB);
        k_conv1_apply<<<grid, 256>>>(seq);                         // 1
    }
    k_init<<<2048, 256>>>();                                       // 2
    k_conv2_hmma<<<148, 256, C2_SMEM>>>(K2, bk2);                  // 3  <- profile target
    k_prot<<<(NB*256 + 255)/256, 256>>>(Wp, bp);                   // 4

    // drug branch: GAT layer 1
    k_gat1_mm<<<(NN*128 + 255)/256, 256>>>(x, W1);                 // 5
    k_att1<<<(NN*32 + 255)/256, 256>>>(att_s1, att_d1);
    k_edge_max<2><<<(ET + 255)/256, 256>>>(ei);
    k_edge_den<2><<<(ET + 255)/256, 256>>>(ei);
    k_edge_acc<2><<<(ET*32 + 255)/256, 256>>>(ei);
    k_bias_elu<1><<<(NN*128 + 255)/256, 256>>>(b1);

    // GAT layer 2
    k_gat2_mm<<<NN/64, 256, 98304>>>(W2);
    k_att2<<<(NN*32 + 255)/256, 256>>>(att_s2, att_d2);
    k_edge_max<1><<<(ET + 255)/256, 256>>>(ei);
    k_edge_den<1><<<(ET + 255)/256, 256>>>(ei);
    k_edge_acc<1><<<(ET*32 + 255)/256, 256>>>(ei);
    k_bias_elu<2><<<(NN*128 + 255)/256, 256>>>(b2);

    // pooling + drug dense
    k_pool<<<(NN*32 + 255)/256, 256>>>(batch);
    k_drug<<<(NG*256 + 255)/256, 256>>>(Wd, bd);

    // head
    k_head<<<NG, 128>>>(Wf1, bf1, Wf2, bf2, Wo, bo, out);
}

// round 8
// speedup vs baseline: 1.1547x; 1.1547x over previous
#include <cuda_runtime.h>
#include <cuda_bf16.h>
#include <cstdint>

#define NN 24576
#define NE 98304
#define NG 512
#define NB 512
#define LL 1000

// ---------------- scratch (device globals; runtime alloc forbidden) ----------------
__device__ float g_h1[NN*128];
__device__ float g_as1[NN*2];
__device__ float g_ad1[NN*2];
__device__ float g_m1[NN*2];
__device__ float g_den1[NN*2];
__device__ float g_e1[(NE+NN)*2];
__device__ float g_out1[NN*128];
__device__ float g_h2[NN*128];
__device__ float g_as2[NN];
__device__ float g_ad2[NN];
__device__ float g_m2[NN];
__device__ float g_den2[NN];
__device__ float g_e2[NE+NN];
__device__ float g_out2[NN*128];
__device__ float g_sums[NG*128];
__device__ float g_cnt[NG];
__device__ float g_drug[NG*256];
__device__ float g_T[3*22*64];
__device__ float g_p1[NB*LL*64];
__device__ float g_pmax[NB*128];
__device__ float g_prot[NB*256];

// ---------------- helpers ----------------
__device__ __forceinline__ void red_add_v4(float* addr, float4 v) {
    asm volatile("red.global.add.v4.f32 [%0], {%1, %2, %3, %4};"
                 :: "l"(addr), "f"(v.x), "f"(v.y), "f"(v.z), "f"(v.w) : "memory");
}
__device__ __forceinline__ void atomicMaxFloat(float* addr, float val) {
    if (val >= 0.f) atomicMax((int*)addr, __float_as_int(val));
    else            atomicMin((unsigned int*)addr, __float_as_uint(val));
}
__device__ __forceinline__ float warp_sum(float v) {
    #pragma unroll
    for (int off = 16; off; off >>= 1) v += __shfl_down_sync(0xffffffffu, v, off);
    return v;
}
__device__ __forceinline__ float elu1(float v) { return v > 0.f ? v : expm1f(v); }

__device__ __forceinline__ void mma_bf16(float* c, const uint32_t* a, const uint32_t* b) {
    asm volatile(
        "mma.sync.aligned.m16n8k16.row.col.f32.bf16.bf16.f32 "
        "{%0,%1,%2,%3}, {%4,%5,%6,%7}, {%8,%9}, {%0,%1,%2,%3};"
        : "+f"(c[0]), "+f"(c[1]), "+f"(c[2]), "+f"(c[3])
        : "r"(a[0]), "r"(a[1]), "r"(a[2]), "r"(a[3]), "r"(b[0]), "r"(b[1]));
}
__device__ __forceinline__ void ldsm_x4(uint32_t* r, uint32_t addr) {
    asm volatile("ldmatrix.sync.aligned.m8n8.x4.shared.b16 {%0,%1,%2,%3}, [%4];"
                 : "=r"(r[0]), "=r"(r[1]), "=r"(r[2]), "=r"(r[3]) : "r"(addr));
}
__device__ __forceinline__ uint32_t smem_u32(const void* p) {
    uint32_t a;
    asm("{ .reg .u64 t; cvta.to.shared.u64 t, %1; cvt.u32.u64 %0, t; }" : "=r"(a) : "l"(p));
    return a;
}

// ---------------- conv2 via HMMA, 512 threads (4 warps/SMSP) ----------------
// GEMM: M=128 l, N=128 o, K=320 (5 taps x 64 ch), im2col via A row overlap.
// A: 132 rows x 64 ch, stride 72 elems (144B -> LDSM conflict-free).
// B: 128 o x 320 k, stride 328 elems (656B -> LDSM conflict-free).
// 16 warps: warp tile 32(M) x 32(N).
#define C2_A_STRIDE 72
#define C2_AH 0
#define C2_AL 19584
#define C2_BH 39168
#define C2_B_STRIDE 328
#define C2_BL 123136
#define C2_SMEM 207104
#define C2_TILES (NB*8)

__global__ void __launch_bounds__(512) k_conv2_hmma(const float* __restrict__ K2,
                                                    const float* __restrict__ bk2) {
    extern __shared__ char smem[];
    __nv_bfloat16* Bh = reinterpret_cast<__nv_bfloat16*>(smem + C2_BH);
    __nv_bfloat16* Bl = reinterpret_cast<__nv_bfloat16*>(smem + C2_BL);
    uint32_t* AhW = reinterpret_cast<uint32_t*>(smem + C2_AH);
    uint32_t* AlW = reinterpret_cast<uint32_t*>(smem + C2_AL);

    int tid = threadIdx.x, wid = tid >> 5, lane = tid & 31;
    int g = lane >> 2, q = lane & 3;
    int mw = (wid >> 2) * 32;    // M group (0,32,64,96)
    int nw = (wid & 3) * 32;     // N group (0,32,64,96)

    uint32_t sb = smem_u32(smem);
    uint32_t sbAh = sb + C2_AH, sbAl = sb + C2_AL, sbBh = sb + C2_BH;

    // ldmatrix per-lane address components
    uint32_t aoff = (uint32_t)(lane & 15) * 144u + ((lane & 16) ? 16u : 0u);
    uint32_t boff = (uint32_t)(lane & 7) * 656u + ((lane & 8) ? 16u : 0u)
                  + ((lane & 16) ? (uint32_t)(C2_BL - C2_BH) : 0u);

    // ---- B conversion (once per CTA) ----
    for (int idx = tid; idx < 128*320; idx += 512) {
        int n = idx / 320, k = idx - n*320;
        int t = k >> 6, i = k & 63;
        float v = K2[(n*64 + i)*5 + t];
        __nv_bfloat16 hb = __float2bfloat16_rn(v);
        __nv_bfloat16 lb = __float2bfloat16_rn(v - __bfloat162float(hb));
        Bh[n*C2_B_STRIDE + k] = hb;
        Bl[n*C2_B_STRIDE + k] = lb;
    }

    float bias[4][2];
    #pragma unroll
    for (int nt = 0; nt < 4; nt++) {
        int col = nw + nt*8 + q*2;
        bias[nt][0] = bk2[col];
        bias[nt][1] = bk2[col + 1];
    }

    for (int tile = blockIdx.x; tile < C2_TILES; tile += gridDim.x) {
        int b = tile >> 3, l0 = (tile & 7) * 125;
        __syncthreads();

        // ---- A load + hi/lo conversion ----
        for (int idx = tid; idx < 132*32; idx += 512) {
            int row = idx >> 5, p = idx & 31;
            int l = l0 + row - 2;
            float2 v = make_float2(0.f, 0.f);
            if (l >= 0 && l < LL)
                v = *reinterpret_cast<const float2*>(&g_p1[((size_t)b*LL + l)*64 + p*2]);
            __nv_bfloat162 h2 = __floats2bfloat162_rn(v.x, v.y);
            __nv_bfloat162 l2 = __floats2bfloat162_rn(v.x - __bfloat162float(h2.x),
                                                      v.y - __bfloat162float(h2.y));
            AhW[row*(C2_A_STRIDE/2) + p] = *reinterpret_cast<uint32_t*>(&h2);
            AlW[row*(C2_A_STRIDE/2) + p] = *reinterpret_cast<uint32_t*>(&l2);
        }
        __syncthreads();

        float acc[2][4][4];
        #pragma unroll
        for (int mt = 0; mt < 2; mt++)
            #pragma unroll
            for (int nt = 0; nt < 4; nt++)
                #pragma unroll
                for (int j = 0; j < 4; j++) acc[mt][nt][j] = 0.f;

        #pragma unroll 1
        for (int ks = 0; ks < 20; ks++) {
            int t = ks >> 2;
            uint32_t kb = (uint32_t)((ks & 3) * 32);
            uint32_t aBase = (uint32_t)((mw + t) * 144) + kb + aoff;
            uint32_t ah[2][4], al[2][4], bb[4][4];
            #pragma unroll
            for (int mt = 0; mt < 2; mt++) {
                ldsm_x4(ah[mt], sbAh + aBase + (uint32_t)(mt*16*144));
                ldsm_x4(al[mt], sbAl + aBase + (uint32_t)(mt*16*144));
            }
            uint32_t bBase = (uint32_t)(nw * 656) + (uint32_t)(t * 128) + kb + boff;
            #pragma unroll
            for (int nt = 0; nt < 4; nt++)
                ldsm_x4(bb[nt], sbBh + bBase + (uint32_t)(nt*8*656));
            // term-outer ordering: consecutive MMAs hit different accumulators
            #pragma unroll
            for (int mt = 0; mt < 2; mt++)
                #pragma unroll
                for (int nt = 0; nt < 4; nt++)
                    mma_bf16(acc[mt][nt], ah[mt], &bb[nt][0]);   // ah*bh
            #pragma unroll
            for (int mt = 0; mt < 2; mt++)
                #pragma unroll
                for (int nt = 0; nt < 4; nt++)
                    mma_bf16(acc[mt][nt], ah[mt], &bb[nt][2]);   // ah*bl
            #pragma unroll
            for (int mt = 0; mt < 2; mt++)
                #pragma unroll
                for (int nt = 0; nt < 4; nt++)
                    mma_bf16(acc[mt][nt], al[mt], &bb[nt][0]);   // al*bh
        }

        // ---- epilogue: bias + elu + max over valid l ----
        float mx[4][2];
        #pragma unroll
        for (int nt = 0; nt < 4; nt++) { mx[nt][0] = -3.0e38f; mx[nt][1] = -3.0e38f; }
        #pragma unroll
        for (int mt = 0; mt < 2; mt++) {
            int lr = l0 + mw + mt*16 + g;
            bool v0 = lr < LL, v1 = (lr + 8) < LL;
            #pragma unroll
            for (int nt = 0; nt < 4; nt++) {
                if (v0) {
                    mx[nt][0] = fmaxf(mx[nt][0], elu1(acc[mt][nt][0] + bias[nt][0]));
                    mx[nt][1] = fmaxf(mx[nt][1], elu1(acc[mt][nt][1] + bias[nt][1]));
                }
                if (v1) {
                    mx[nt][0] = fmaxf(mx[nt][0], elu1(acc[mt][nt][2] + bias[nt][0]));
                    mx[nt][1] = fmaxf(mx[nt][1], elu1(acc[mt][nt][3] + bias[nt][1]));
                }
            }
        }
        #pragma unroll
        for (int nt = 0; nt < 4; nt++) {
            #pragma unroll
            for (int j = 0; j < 2; j++) {
                float v = mx[nt][j];
                v = fmaxf(v, __shfl_xor_sync(0xffffffffu, v, 4));
                v = fmaxf(v, __shfl_xor_sync(0xffffffffu, v, 8));
                v = fmaxf(v, __shfl_xor_sync(0xffffffffu, v, 16));
                if (lane < 4)
                    atomicMaxFloat(&g_pmax[b*128 + nw + nt*8 + lane*2 + j], v);
            }
        }
    }
}

// ---------------- conv1 token tables ----------------
__global__ void k_tab(const float* __restrict__ Pe, const float* __restrict__ K1,
                      const float* __restrict__ bk1) {
    int idx = blockIdx.x * blockDim.x + threadIdx.x;
    if (idx >= 3*22*64) return;
    int o = idx & 63, r = idx >> 6;
    int t = r % 22, k = r / 22;
    float acc = (k == 1) ? bk1[o] : 0.f;
    #pragma unroll 8
    for (int i = 0; i < 64; i++) acc += Pe[t*64 + i] * K1[(o*64 + i)*3 + k];
    g_T[idx] = acc;
}

// ---------------- conv1 apply ----------------
__global__ void __launch_bounds__(256) k_conv1_apply(const int* __restrict__ seq) {
    int b = blockIdx.y;
    int lofs = threadIdx.x >> 4, lq = threadIdx.x & 15;
    int l = blockIdx.x * 16 + lofs;
    if (l >= LL) return;
    int s1 = seq[b*LL + l];
    int c = lq * 4;
    float4 v = *reinterpret_cast<const float4*>(&g_T[(22 + s1)*64 + c]);
    if (l > 0) {
        int s0 = seq[b*LL + l - 1];
        float4 a = *reinterpret_cast<const float4*>(&g_T[s0*64 + c]);
        v.x += a.x; v.y += a.y; v.z += a.z; v.w += a.w;
    }
    if (l < LL-1) {
        int s2 = seq[b*LL + l + 1];
        float4 a = *reinterpret_cast<const float4*>(&g_T[(44 + s2)*64 + c]);
        v.x += a.x; v.y += a.y; v.z += a.z; v.w += a.w;
    }
    v.x = elu1(v.x); v.y = elu1(v.y); v.z = elu1(v.z); v.w = elu1(v.w);
    *reinterpret_cast<float4*>(&g_p1[((size_t)b*LL + l)*64 + c]) = v;
}

// ---------------- init ----------------
__global__ void k_init() {
    int i = blockIdx.x * blockDim.x + threadIdx.x;
    int stride = gridDim.x * blockDim.x;
    for (int idx = i; idx < NN*128; idx += stride) { g_out1[idx] = 0.f; g_out2[idx] = 0.f; }
    for (int idx = i; idx < NN*2; idx += stride) { g_m1[idx] = -3.0e38f; g_den1[idx] = 0.f; }
    for (int idx = i; idx < NN; idx += stride) { g_m2[idx] = -3.0e38f; g_den2[idx] = 0.f; }
    for (int idx = i; idx < NG*128; idx += stride) g_sums[idx] = 0.f;
    for (int idx = i; idx < NG; idx += stride) g_cnt[idx] = 0.f;
    for (int idx = i; idx < NB*128; idx += stride) g_pmax[idx] = -3.0e38f;
}

// ---------------- GAT1 GEMM ----------------
__global__ void k_gat1_mm(const float* __restrict__ x, const float* __restrict__ W1) {
    int idx = blockIdx.x * blockDim.x + threadIdx.x;
    if (idx >= NN*128) return;
    int n = idx >> 7, c = idx & 127;
    float acc = 0.f;
    #pragma unroll
    for (int f = 0; f < 5; f++) acc += x[n*5 + f] * W1[f*128 + c];
    g_h1[idx] = acc;
}

// attention scalars, 2 heads of 64
__global__ void k_att1(const float* __restrict__ att_s, const float* __restrict__ att_d) {
    int gw = (blockIdx.x * blockDim.x + threadIdx.x) >> 5;
    int lane = threadIdx.x & 31;
    if (gw >= NN) return;
    const float* hr = g_h1 + (size_t)gw * 128;
    float s0 = hr[lane]*att_s[lane] + hr[lane+32]*att_s[lane+32];
    float s1 = hr[lane+64]*att_s[lane+64] + hr[lane+96]*att_s[lane+96];
    float d0 = hr[lane]*att_d[lane] + hr[lane+32]*att_d[lane+32];
    float d1 = hr[lane+64]*att_d[lane+64] + hr[lane+96]*att_d[lane+96];
    s0 = warp_sum(s0); s1 = warp_sum(s1); d0 = warp_sum(d0); d1 = warp_sum(d1);
    if (lane == 0) {
        g_as1[gw*2] = s0; g_as1[gw*2+1] = s1;
        g_ad1[gw*2] = d0; g_ad1[gw*2+1] = d1;
    }
}

// attention scalars, 1 head of 128
__global__ void k_att2(const float* __restrict__ att_s, const float* __restrict__ att_d) {
    int gw = (blockIdx.x * blockDim.x + threadIdx.x) >> 5;
    int lane = threadIdx.x & 31;
    if (gw >= NN) return;
    const float* hr = g_h2 + (size_t)gw * 128;
    float s = 0.f, d = 0.f;
    #pragma unroll
    for (int t = 0; t < 4; t++) {
        int p = lane + 32*t;
        s += hr[p]*att_s[p];
        d += hr[p]*att_d[p];
    }
    s = warp_sum(s); d = warp_sum(d);
    if (lane == 0) { g_as2[gw] = s; g_ad2[gw] = d; }
}

// ---------------- edge passes ----------------
template<int H>
__global__ void k_edge_max(const int* __restrict__ ei) {
    int e = blockIdx.x * blockDim.x + threadIdx.x;
    const int ET = NE + NN;
    if (e >= ET) return;
    int src, dst;
    if (e < NE) { src = ei[e]; dst = ei[NE + e]; } else { src = dst = e - NE; }
    const float* as_ = (H == 2) ? g_as1 : g_as2;
    const float* ad_ = (H == 2) ? g_ad1 : g_ad2;
    float* m_ = (H == 2) ? g_m1 : g_m2;
    float* e_ = (H == 2) ? g_e1 : g_e2;
    #pragma unroll
    for (int h = 0; h < H; h++) {
        float v = as_[src*H+h] + ad_[dst*H+h];
        v = v > 0.f ? v : 0.2f * v;
        e_[e*H+h] = v;
        atomicMaxFloat(&m_[dst*H+h], v);
    }
}

template<int H>
__global__ void k_edge_den(const int* __restrict__ ei) {
    int e = blockIdx.x * blockDim.x + threadIdx.x;
    const int ET = NE + NN;
    if (e >= ET) return;
    int dst = (e < NE) ? ei[NE + e] : (e - NE);
    const float* m_ = (H == 2) ? g_m1 : g_m2;
    float* den_ = (H == 2) ? g_den1 : g_den2;
    float* e_ = (H == 2) ? g_e1 : g_e2;
    #pragma unroll
    for (int h = 0; h < H; h++) {
        float w = expf(e_[e*H+h] - m_[dst*H+h]);
        e_[e*H+h] = w;
        atomicAdd(&den_[dst*H+h], w);
    }
}

template<int H>
__global__ void k_edge_acc(const int* __restrict__ ei) {
    int gw = (blockIdx.x * blockDim.x + threadIdx.x) >> 5;
    int lane = threadIdx.x & 31;
    const int ET = NE + NN;
    if (gw >= ET) return;
    int src, dst;
    if (gw < NE) { src = ei[gw]; dst = ei[NE + gw]; } else { src = dst = gw - NE; }
    const float* den_ = (H == 2) ? g_den1 : g_den2;
    const float* e_ = (H == 2) ? g_e1 : g_e2;
    const float* hin = (H == 2) ? g_h1 : g_h2;
    float* outp = (H == 2) ? g_out1 : g_out2;
    int h = (H == 2 && lane >= 16) ? 1 : 0;
    float alpha = e_[gw*H + h] / (den_[dst*H + h] + 1e-16f);
    float4 v = *reinterpret_cast<const float4*>(&hin[(size_t)src*128 + lane*4]);
    v.x *= alpha; v.y *= alpha; v.z *= alpha; v.w *= alpha;
    red_add_v4(&outp[(size_t)dst*128 + lane*4], v);
}

template<int WHICH>
__global__ void k_bias_elu(const float* __restrict__ b) {
    int idx = blockIdx.x * blockDim.x + threadIdx.x;
    if (idx >= NN*128) return;
    float* o = (WHICH == 1) ? g_out1 : g_out2;
    o[idx] = elu1(o[idx] + b[idx & 127]);
}

// ---------------- GAT2 GEMM ----------------
__global__ void __launch_bounds__(256) k_gat2_mm(const float* __restrict__ W2) {
    extern __shared__ float sm[];
    float* sg = sm;
    float* sw = sm + 64*128;
    int base = blockIdx.x * 64;
    int tid = threadIdx.x;
    for (int idx = tid; idx < 64*128; idx += 256) sg[idx] = g_out1[(size_t)base*128 + idx];
    for (int idx = tid; idx < 128*128; idx += 256) sw[idx] = W2[idx];
    __syncthreads();
    int r0 = (tid >> 4) << 2;
    int c0 = (tid & 15) << 3;
    float acc[4][8];
    #pragma unroll
    for (int i = 0; i < 4; i++)
        #pragma unroll
        for (int j = 0; j < 8; j++) acc[i][j] = 0.f;
    #pragma unroll 4
    for (int k = 0; k < 128; k++) {
        float a[4];
        #pragma unroll
        for (int i = 0; i < 4; i++) a[i] = sg[(r0+i)*128 + k];
        float4 b0 = *reinterpret_cast<const float4*>(&sw[k*128 + c0]);
        float4 b1 = *reinterpret_cast<const float4*>(&sw[k*128 + c0 + 4]);
        #pragma unroll
        for (int i = 0; i < 4; i++) {
            acc[i][0] += a[i]*b0.x; acc[i][1] += a[i]*b0.y;
            acc[i][2] += a[i]*b0.z; acc[i][3] += a[i]*b0.w;
            acc[i][4] += a[i]*b1.x; acc[i][5] += a[i]*b1.y;
            acc[i][6] += a[i]*b1.z; acc[i][7] += a[i]*b1.w;
        }
    }
    #pragma unroll
    for (int i = 0; i < 4; i++) {
        float4 v0 = make_float4(acc[i][0], acc[i][1], acc[i][2], acc[i][3]);
        float4 v1 = make_float4(acc[i][4], acc[i][5], acc[i][6], acc[i][7]);
        *reinterpret_cast<float4*>(&g_h2[(size_t)(base+r0+i)*128 + c0]) = v0;
        *reinterpret_cast<float4*>(&g_h2[(size_t)(base+r0+i)*128 + c0 + 4]) = v1;
    }
}

// ---------------- pooling + dense ----------------
__global__ void k_pool(const int* __restrict__ batch) {
    int gw = (blockIdx.x * blockDim.x + threadIdx.x) >> 5;
    int lane = threadIdx.x & 31;
    if (gw >= NN) return;
    int g = batch[gw];
    float4 v = *reinterpret_cast<const float4*>(&g_out2[(size_t)gw*128 + lane*4]);
    red_add_v4(&g_sums[g*128 + lane*4], v);
    if (lane == 0) atomicAdd(&g_cnt[g], 1.0f);
}

__global__ void k_drug(const float* __restrict__ Wd, const float* __restrict__ bd) {
    int idx = blockIdx.x * blockDim.x + threadIdx.x;
    if (idx >= NG*256) return;
    int g = idx >> 8, j = idx & 255;
    float invc = 1.f / fmaxf(g_cnt[g], 1.f);
    const float* srow = g_sums + g*128;
    float acc = 0.f;
    #pragma unroll 4
    for (int k = 0; k < 128; k++) acc += srow[k] * Wd[k*256 + j];
    g_drug[idx] = fmaxf(acc * invc + bd[j], 0.f);
}

__global__ void k_prot(const float* __restrict__ Wp, const float* __restrict__ bp) {
    int idx = blockIdx.x * blockDim.x + threadIdx.x;
    if (idx >= NB*256) return;
    int g = idx >> 8, j = idx & 255;
    const float* srow = g_pmax + g*128;
    float acc = 0.f;
    #pragma unroll 4
    for (int k = 0; k < 128; k++) acc += srow[k] * Wp[k*256 + j];
    g_prot[idx] = fmaxf(acc + bp[j], 0.f);
}

// ---------------- head MLP ----------------
__global__ void __launch_bounds__(128) k_head(const float* __restrict__ Wf1, const float* __restrict__ bf1,
                                              const float* __restrict__ Wf2, const float* __restrict__ bf2,
                                              const float* __restrict__ Wo, const float* __restrict__ bo,
                                              float* __restrict__ out) {
    __shared__ float sh[512];
    __shared__ float s1[128];
    __shared__ float s2[64];
    int g = blockIdx.x, tid = threadIdx.x;
    for (int i = tid; i < 256; i += 128) {
        sh[i]       = g_drug[g*256 + i];
        sh[256 + i] = g_prot[g*256 + i];
    }
    __syncthreads();
    float acc = 0.f;
    #pragma unroll 8
    for (int k = 0; k < 512; k++) acc += sh[k] * Wf1[k*128 + tid];
    s1[tid] = fmaxf(acc + bf1[tid], 0.f);
    __syncthreads();
    if (tid < 64) {
        float a = 0.f;
        #pragma unroll 8
        for (int k = 0; k < 128; k++) a += s1[k] * Wf2[k*64 + tid];
        s2[tid] = fmaxf(a + bf2[tid], 0.f);
    }
    __syncthreads();
    if (tid < 32) {
        float a = s2[tid]*Wo[tid] + s2[tid+32]*Wo[tid+32];
        a = warp_sum(a);
        if (tid == 0) out[g] = a + bo[0];
    }
}

// ---------------- launch ----------------
extern "C" void kernel_launch(void* const* d_in, const int* in_sizes, int n_in,
                              void* d_out, int out_size) {
    const float* x        = (const float*)d_in[0];
    const int*   ei       = (const int*)d_in[1];
    const int*   batch    = (const int*)d_in[2];
    const int*   seq      = (const int*)d_in[3];
    const float* W1       = (const float*)d_in[4];
    const float* att_s1   = (const float*)d_in[5];
    const float* att_d1   = (const float*)d_in[6];
    const float* b1       = (const float*)d_in[7];
    const float* W2       = (const float*)d_in[8];
    const float* att_s2   = (const float*)d_in[9];
    const float* att_d2   = (const float*)d_in[10];
    const float* b2       = (const float*)d_in[11];
    const float* Wd       = (const float*)d_in[12];
    const float* bd       = (const float*)d_in[13];
    const float* Pe       = (const float*)d_in[14];
    const float* K1       = (const float*)d_in[15];
    const float* bk1      = (const float*)d_in[16];
    const float* K2       = (const float*)d_in[17];
    const float* bk2      = (const float*)d_in[18];
    const float* Wp       = (const float*)d_in[19];
    const float* bp       = (const float*)d_in[20];
    const float* Wf1      = (const float*)d_in[21];
    const float* bf1      = (const float*)d_in[22];
    const float* Wf2      = (const float*)d_in[23];
    const float* bf2      = (const float*)d_in[24];
    const float* Wo       = (const float*)d_in[25];
    const float* bo       = (const float*)d_in[26];
    float* out = (float*)d_out;

    cudaFuncSetAttribute(k_gat2_mm,    cudaFuncAttributeMaxDynamicSharedMemorySize, 98304);
    cudaFuncSetAttribute(k_conv2_hmma, cudaFuncAttributeMaxDynamicSharedMemorySize, C2_SMEM);

    const int ET = NE + NN;

    // protein branch
    k_tab<<<17, 256>>>(Pe, K1, bk1);                               // 0
    {
        dim3 grid((LL + 15)/16, NB);
        k_conv1_apply<<<grid, 256>>>(seq);                         // 1
    }
    k_init<<<2048, 256>>>();                                       // 2
    k_conv2_hmma<<<148, 512, C2_SMEM>>>(K2, bk2);                  // 3  <- profile target
    k_prot<<<(NB*256 + 255)/256, 256>>>(Wp, bp);                   // 4

    // drug branch: GAT layer 1
    k_gat1_mm<<<(NN*128 + 255)/256, 256>>>(x, W1);                 // 5
    k_att1<<<(NN*32 + 255)/256, 256>>>(att_s1, att_d1);
    k_edge_max<2><<<(ET + 255)/256, 256>>>(ei);
    k_edge_den<2><<<(ET + 255)/256, 256>>>(ei);
    k_edge_acc<2><<<(ET*32 + 255)/256, 256>>>(ei);
    k_bias_elu<1><<<(NN*128 + 255)/256, 256>>>(b1);

    // GAT layer 2
    k_gat2_mm<<<NN/64, 256, 98304>>>(W2);
    k_att2<<<(NN*32 + 255)/256, 256>>>(att_s2, att_d2);
    k_edge_max<1><<<(ET + 255)/256, 256>>>(ei);
    k_edge_den<1><<<(ET + 255)/256, 256>>>(ei);
    k_edge_acc<1><<<(ET*32 + 255)/256, 256>>>(ei);
    k_bias_elu<2><<<(NN*128 + 255)/256, 256>>>(b2);

    // pooling + drug dense
    k_pool<<<(NN*32 + 255)/256, 256>>>(batch);
    k_drug<<<(NG*256 + 255)/256, 256>>>(Wd, bd);

    // head
    k_head<<<NG, 128>>>(Wf1, bf1, Wf2, bf2, Wo, bo, out);
}

// round 9
// speedup vs baseline: 1.2225x; 1.0587x over previous
#include <cuda_runtime.h>
#include <cuda_bf16.h>
#include <cstdint>

#define NN 24576
#define NE 98304
#define NG 512
#define NB 512
#define LL 1000

// ---------------- scratch (device globals; runtime alloc forbidden) ----------------
__device__ float g_h1[NN*128];
__device__ float g_as1[NN*2];
__device__ float g_ad1[NN*2];
__device__ float g_m1[NN*2];
__device__ float g_den1[NN*2];
__device__ float g_e1[(NE+NN)*2];
__device__ float g_out1[NN*128];
__device__ float g_h2[NN*128];
__device__ float g_as2[NN];
__device__ float g_ad2[NN];
__device__ float g_m2[NN];
__device__ float g_den2[NN];
__device__ float g_e2[NE+NN];
__device__ float g_out2[NN*128];
__device__ float g_sums[NG*128];
__device__ float g_cnt[NG];
__device__ float g_drug[NG*256];
__device__ float g_T[3*22*64];
__device__ float g_p1[NB*LL*64];
__device__ float g_pmax[NB*128];
__device__ float g_prot[NB*256];

// ---------------- helpers ----------------
__device__ __forceinline__ void red_add_v4(float* addr, float4 v) {
    asm volatile("red.global.add.v4.f32 [%0], {%1, %2, %3, %4};"
                 :: "l"(addr), "f"(v.x), "f"(v.y), "f"(v.z), "f"(v.w) : "memory");
}
__device__ __forceinline__ void atomicMaxFloat(float* addr, float val) {
    if (val >= 0.f) atomicMax((int*)addr, __float_as_int(val));
    else            atomicMin((unsigned int*)addr, __float_as_uint(val));
}
__device__ __forceinline__ float warp_sum(float v) {
    #pragma unroll
    for (int off = 16; off; off >>= 1) v += __shfl_down_sync(0xffffffffu, v, off);
    return v;
}
__device__ __forceinline__ float elu1(float v) { return v > 0.f ? v : expm1f(v); }

__device__ __forceinline__ void mma_bf16(float* c, const uint32_t* a, const uint32_t* b) {
    asm volatile(
        "mma.sync.aligned.m16n8k16.row.col.f32.bf16.bf16.f32 "
        "{%0,%1,%2,%3}, {%4,%5,%6,%7}, {%8,%9}, {%0,%1,%2,%3};"
        : "+f"(c[0]), "+f"(c[1]), "+f"(c[2]), "+f"(c[3])
        : "r"(a[0]), "r"(a[1]), "r"(a[2]), "r"(a[3]), "r"(b[0]), "r"(b[1]));
}
__device__ __forceinline__ void ldsm_x4(uint32_t* r, uint32_t addr) {
    asm volatile("ldmatrix.sync.aligned.m8n8.x4.shared.b16 {%0,%1,%2,%3}, [%4];"
                 : "=r"(r[0]), "=r"(r[1]), "=r"(r[2]), "=r"(r[3]) : "r"(addr));
}
__device__ __forceinline__ uint32_t smem_u32(const void* p) {
    uint32_t a;
    asm("{ .reg .u64 t; cvta.to.shared.u64 t, %1; cvt.u32.u64 %0, t; }" : "=r"(a) : "l"(p));
    return a;
}

// ---------------- conv2 via HMMA, 512 threads, A software-pipelined across tiles ----------------
// GEMM: M=128 l, N=128 o, K=320 (5 taps x 64 ch), im2col via A row overlap.
// A: 132 rows x 64 ch, stride 72 elems (144B -> LDSM conflict-free).
// B: 128 o x 320 k, stride 328 elems (656B -> LDSM conflict-free).
#define C2_A_STRIDE 72
#define C2_AH 0
#define C2_AL 19584
#define C2_BH 39168
#define C2_B_STRIDE 328
#define C2_BL 123136
#define C2_SMEM 207104
#define C2_TILES (NB*8)

__global__ void __launch_bounds__(512) k_conv2_hmma(const float* __restrict__ K2,
                                                    const float* __restrict__ bk2) {
    extern __shared__ char smem[];
    __nv_bfloat16* Bh = reinterpret_cast<__nv_bfloat16*>(smem + C2_BH);
    __nv_bfloat16* Bl = reinterpret_cast<__nv_bfloat16*>(smem + C2_BL);
    uint32_t* AhW = reinterpret_cast<uint32_t*>(smem + C2_AH);
    uint32_t* AlW = reinterpret_cast<uint32_t*>(smem + C2_AL);

    int tid = threadIdx.x, wid = tid >> 5, lane = tid & 31;
    int g = lane >> 2, q = lane & 3;
    int mw = (wid >> 2) * 32;
    int nw = (wid & 3) * 32;

    uint32_t sb = smem_u32(smem);
    uint32_t sbAh = sb + C2_AH, sbAl = sb + C2_AL, sbBh = sb + C2_BH;

    uint32_t aoff = (uint32_t)(lane & 15) * 144u + ((lane & 16) ? 16u : 0u);
    uint32_t boff = (uint32_t)(lane & 7) * 656u + ((lane & 8) ? 16u : 0u)
                  + ((lane & 16) ? (uint32_t)(C2_BL - C2_BH) : 0u);

    // ---- B conversion (once per CTA) ----
    for (int idx = tid; idx < 128*320; idx += 512) {
        int n = idx / 320, k = idx - n*320;
        int t = k >> 6, i = k & 63;
        float v = K2[(n*64 + i)*5 + t];
        __nv_bfloat16 hb = __float2bfloat16_rn(v);
        __nv_bfloat16 lb = __float2bfloat16_rn(v - __bfloat162float(hb));
        Bh[n*C2_B_STRIDE + k] = hb;
        Bl[n*C2_B_STRIDE + k] = lb;
    }

    float bias[4][2];
    #pragma unroll
    for (int nt = 0; nt < 4; nt++) {
        int col = nw + nt*8 + q*2;
        bias[nt][0] = bk2[col];
        bias[nt][1] = bk2[col + 1];
    }

    // ---- A prefetch registers (132*32 = 4224 float2 slots, 9 per thread) ----
    float2 pref[9];
    auto load_A = [&](int tile_) {
        int b_ = tile_ >> 3, l0_ = (tile_ & 7) * 125;
        #pragma unroll
        for (int i = 0; i < 9; i++) {
            int idx = tid + i*512;
            float2 v = make_float2(0.f, 0.f);
            if (idx < 4224) {
                int row = idx >> 5, p = idx & 31;
                int l = l0_ + row - 2;
                if (l >= 0 && l < LL)
                    v = *reinterpret_cast<const float2*>(&g_p1[((size_t)b_*LL + l)*64 + p*2]);
            }
            pref[i] = v;
        }
    };
    auto store_A = [&]() {
        #pragma unroll
        for (int i = 0; i < 9; i++) {
            int idx = tid + i*512;
            if (idx < 4224) {
                int row = idx >> 5, p = idx & 31;
                float2 v = pref[i];
                __nv_bfloat162 h2 = __floats2bfloat162_rn(v.x, v.y);
                __nv_bfloat162 l2 = __floats2bfloat162_rn(v.x - __bfloat162float(h2.x),
                                                          v.y - __bfloat162float(h2.y));
                AhW[row*(C2_A_STRIDE/2) + p] = *reinterpret_cast<uint32_t*>(&h2);
                AlW[row*(C2_A_STRIDE/2) + p] = *reinterpret_cast<uint32_t*>(&l2);
            }
        }
    };

    int tile = blockIdx.x;
    if (tile < C2_TILES) load_A(tile);
    for (; tile < C2_TILES; tile += gridDim.x) {
        int b = tile >> 3, l0 = (tile & 7) * 125;
        __syncthreads();        // prior mainloop's smem A reads complete
        store_A();
        __syncthreads();
        if (tile + (int)gridDim.x < C2_TILES) load_A(tile + gridDim.x);  // hides under mainloop

        float acc[2][4][4];
        #pragma unroll
        for (int mt = 0; mt < 2; mt++)
            #pragma unroll
            for (int nt = 0; nt < 4; nt++)
                #pragma unroll
                for (int j = 0; j < 4; j++) acc[mt][nt][j] = 0.f;

        #pragma unroll 1
        for (int ks = 0; ks < 20; ks++) {
            int t = ks >> 2;
            uint32_t kb = (uint32_t)((ks & 3) * 32);
            uint32_t aBase = (uint32_t)((mw + t) * 144) + kb + aoff;
            uint32_t ah[2][4], al[2][4], bb[4][4];
            #pragma unroll
            for (int mt = 0; mt < 2; mt++) {
                ldsm_x4(ah[mt], sbAh + aBase + (uint32_t)(mt*16*144));
                ldsm_x4(al[mt], sbAl + aBase + (uint32_t)(mt*16*144));
            }
            uint32_t bBase = (uint32_t)(nw * 656) + (uint32_t)(t * 128) + kb + boff;
            #pragma unroll
            for (int nt = 0; nt < 4; nt++)
                ldsm_x4(bb[nt], sbBh + bBase + (uint32_t)(nt*8*656));
            #pragma unroll
            for (int mt = 0; mt < 2; mt++)
                #pragma unroll
                for (int nt = 0; nt < 4; nt++)
                    mma_bf16(acc[mt][nt], ah[mt], &bb[nt][0]);   // ah*bh
            #pragma unroll
            for (int mt = 0; mt < 2; mt++)
                #pragma unroll
                for (int nt = 0; nt < 4; nt++)
                    mma_bf16(acc[mt][nt], ah[mt], &bb[nt][2]);   // ah*bl
            #pragma unroll
            for (int mt = 0; mt < 2; mt++)
                #pragma unroll
                for (int nt = 0; nt < 4; nt++)
                    mma_bf16(acc[mt][nt], al[mt], &bb[nt][0]);   // al*bh
        }

        // ---- epilogue: bias + elu + max over valid l (regs + shfl only) ----
        float mx[4][2];
        #pragma unroll
        for (int nt = 0; nt < 4; nt++) { mx[nt][0] = -3.0e38f; mx[nt][1] = -3.0e38f; }
        #pragma unroll
        for (int mt = 0; mt < 2; mt++) {
            int lr = l0 + mw + mt*16 + g;
            bool v0 = lr < LL, v1 = (lr + 8) < LL;
            #pragma unroll
            for (int nt = 0; nt < 4; nt++) {
                if (v0) {
                    mx[nt][0] = fmaxf(mx[nt][0], elu1(acc[mt][nt][0] + bias[nt][0]));
                    mx[nt][1] = fmaxf(mx[nt][1], elu1(acc[mt][nt][1] + bias[nt][1]));
                }
                if (v1) {
                    mx[nt][0] = fmaxf(mx[nt][0], elu1(acc[mt][nt][2] + bias[nt][0]));
                    mx[nt][1] = fmaxf(mx[nt][1], elu1(acc[mt][nt][3] + bias[nt][1]));
                }
            }
        }
        #pragma unroll
        for (int nt = 0; nt < 4; nt++) {
            #pragma unroll
            for (int j = 0; j < 2; j++) {
                float v = mx[nt][j];
                v = fmaxf(v, __shfl_xor_sync(0xffffffffu, v, 4));
                v = fmaxf(v, __shfl_xor_sync(0xffffffffu, v, 8));
                v = fmaxf(v, __shfl_xor_sync(0xffffffffu, v, 16));
                if (lane < 4)
                    atomicMaxFloat(&g_pmax[b*128 + nw + nt*8 + lane*2 + j], v);
            }
        }
    }
}

// ---------------- conv1 token tables ----------------
__global__ void k_tab(const float* __restrict__ Pe, const float* __restrict__ K1,
                      const float* __restrict__ bk1) {
    int idx = blockIdx.x * blockDim.x + threadIdx.x;
    if (idx >= 3*22*64) return;
    int o = idx & 63, r = idx >> 6;
    int t = r % 22, k = r / 22;
    float acc = (k == 1) ? bk1[o] : 0.f;
    #pragma unroll 8
    for (int i = 0; i < 64; i++) acc += Pe[t*64 + i] * K1[(o*64 + i)*3 + k];
    g_T[idx] = acc;
}

// ---------------- conv1 apply ----------------
__global__ void __launch_bounds__(256) k_conv1_apply(const int* __restrict__ seq) {
    int b = blockIdx.y;
    int lofs = threadIdx.x >> 4, lq = threadIdx.x & 15;
    int l = blockIdx.x * 16 + lofs;
    if (l >= LL) return;
    int s1 = seq[b*LL + l];
    int c = lq * 4;
    float4 v = *reinterpret_cast<const float4*>(&g_T[(22 + s1)*64 + c]);
    if (l > 0) {
        int s0 = seq[b*LL + l - 1];
        float4 a = *reinterpret_cast<const float4*>(&g_T[s0*64 + c]);
        v.x += a.x; v.y += a.y; v.z += a.z; v.w += a.w;
    }
    if (l < LL-1) {
        int s2 = seq[b*LL + l + 1];
        float4 a = *reinterpret_cast<const float4*>(&g_T[(44 + s2)*64 + c]);
        v.x += a.x; v.y += a.y; v.z += a.z; v.w += a.w;
    }
    v.x = elu1(v.x); v.y = elu1(v.y); v.z = elu1(v.z); v.w = elu1(v.w);
    *reinterpret_cast<float4*>(&g_p1[((size_t)b*LL + l)*64 + c]) = v;
}

// ---------------- init ----------------
__global__ void k_init() {
    int i = blockIdx.x * blockDim.x + threadIdx.x;
    int stride = gridDim.x * blockDim.x;
    for (int idx = i; idx < NN*128; idx += stride) { g_out1[idx] = 0.f; g_out2[idx] = 0.f; }
    for (int idx = i; idx < NN*2; idx += stride) { g_m1[idx] = -3.0e38f; g_den1[idx] = 0.f; }
    for (int idx = i; idx < NN; idx += stride) { g_m2[idx] = -3.0e38f; g_den2[idx] = 0.f; }
    for (int idx = i; idx < NG*128; idx += stride) g_sums[idx] = 0.f;
    for (int idx = i; idx < NG; idx += stride) g_cnt[idx] = 0.f;
    for (int idx = i; idx < NB*128; idx += stride) g_pmax[idx] = -3.0e38f;
}

// ---------------- GAT1 GEMM ----------------
__global__ void k_gat1_mm(const float* __restrict__ x, const float* __restrict__ W1) {
    int idx = blockIdx.x * blockDim.x + threadIdx.x;
    if (idx >= NN*128) return;
    int n = idx >> 7, c = idx & 127;
    float acc = 0.f;
    #pragma unroll
    for (int f = 0; f < 5; f++) acc += x[n*5 + f] * W1[f*128 + c];
    g_h1[idx] = acc;
}

// attention scalars, 2 heads of 64
__global__ void k_att1(const float* __restrict__ att_s, const float* __restrict__ att_d) {
    int gw = (blockIdx.x * blockDim.x + threadIdx.x) >> 5;
    int lane = threadIdx.x & 31;
    if (gw >= NN) return;
    const float* hr = g_h1 + (size_t)gw * 128;
    float s0 = hr[lane]*att_s[lane] + hr[lane+32]*att_s[lane+32];
    float s1 = hr[lane+64]*att_s[lane+64] + hr[lane+96]*att_s[lane+96];
    float d0 = hr[lane]*att_d[lane] + hr[lane+32]*att_d[lane+32];
    float d1 = hr[lane+64]*att_d[lane+64] + hr[lane+96]*att_d[lane+96];
    s0 = warp_sum(s0); s1 = warp_sum(s1); d0 = warp_sum(d0); d1 = warp_sum(d1);
    if (lane == 0) {
        g_as1[gw*2] = s0; g_as1[gw*2+1] = s1;
        g_ad1[gw*2] = d0; g_ad1[gw*2+1] = d1;
    }
}

// attention scalars, 1 head of 128
__global__ void k_att2(const float* __restrict__ att_s, const float* __restrict__ att_d) {
    int gw = (blockIdx.x * blockDim.x + threadIdx.x) >> 5;
    int lane = threadIdx.x & 31;
    if (gw >= NN) return;
    const float* hr = g_h2 + (size_t)gw * 128;
    float s = 0.f, d = 0.f;
    #pragma unroll
    for (int t = 0; t < 4; t++) {
        int p = lane + 32*t;
        s += hr[p]*att_s[p];
        d += hr[p]*att_d[p];
    }
    s = warp_sum(s); d = warp_sum(d);
    if (lane == 0) { g_as2[gw] = s; g_ad2[gw] = d; }
}

// ---------------- edge passes ----------------
template<int H>
__global__ void k_edge_max(const int* __restrict__ ei) {
    int e = blockIdx.x * blockDim.x + threadIdx.x;
    const int ET = NE + NN;
    if (e >= ET) return;
    int src, dst;
    if (e < NE) { src = ei[e]; dst = ei[NE + e]; } else { src = dst = e - NE; }
    const float* as_ = (H == 2) ? g_as1 : g_as2;
    const float* ad_ = (H == 2) ? g_ad1 : g_ad2;
    float* m_ = (H == 2) ? g_m1 : g_m2;
    float* e_ = (H == 2) ? g_e1 : g_e2;
    #pragma unroll
    for (int h = 0; h < H; h++) {
        float v = as_[src*H+h] + ad_[dst*H+h];
        v = v > 0.f ? v : 0.2f * v;
        e_[e*H+h] = v;
        atomicMaxFloat(&m_[dst*H+h], v);
    }
}

template<int H>
__global__ void k_edge_den(const int* __restrict__ ei) {
    int e = blockIdx.x * blockDim.x + threadIdx.x;
    const int ET = NE + NN;
    if (e >= ET) return;
    int dst = (e < NE) ? ei[NE + e] : (e - NE);
    const float* m_ = (H == 2) ? g_m1 : g_m2;
    float* den_ = (H == 2) ? g_den1 : g_den2;
    float* e_ = (H == 2) ? g_e1 : g_e2;
    #pragma unroll
    for (int h = 0; h < H; h++) {
        float w = expf(e_[e*H+h] - m_[dst*H+h]);
        e_[e*H+h] = w;
        atomicAdd(&den_[dst*H+h], w);
    }
}

template<int H>
__global__ void k_edge_acc(const int* __restrict__ ei) {
    int gw = (blockIdx.x * blockDim.x + threadIdx.x) >> 5;
    int lane = threadIdx.x & 31;
    const int ET = NE + NN;
    if (gw >= ET) return;
    int src, dst;
    if (gw < NE) { src = ei[gw]; dst = ei[NE + gw]; } else { src = dst = gw - NE; }
    const float* den_ = (H == 2) ? g_den1 : g_den2;
    const float* e_ = (H == 2) ? g_e1 : g_e2;
    const float* hin = (H == 2) ? g_h1 : g_h2;
    float* outp = (H == 2) ? g_out1 : g_out2;
    int h = (H == 2 && lane >= 16) ? 1 : 0;
    float alpha = e_[gw*H + h] / (den_[dst*H + h] + 1e-16f);
    float4 v = *reinterpret_cast<const float4*>(&hin[(size_t)src*128 + lane*4]);
    v.x *= alpha; v.y *= alpha; v.z *= alpha; v.w *= alpha;
    red_add_v4(&outp[(size_t)dst*128 + lane*4], v);
}

// ---------------- GAT2 GEMM (bias1+elu fused on A-load) ----------------
__global__ void __launch_bounds__(256) k_gat2_mm(const float* __restrict__ W2,
                                                 const float* __restrict__ b1) {
    extern __shared__ float sm[];
    float* sg = sm;
    float* sw = sm + 64*128;
    int base = blockIdx.x * 64;
    int tid = threadIdx.x;
    for (int idx = tid; idx < 64*128; idx += 256)
        sg[idx] = elu1(g_out1[(size_t)base*128 + idx] + b1[idx & 127]);
    for (int idx = tid; idx < 128*128; idx += 256) sw[idx] = W2[idx];
    __syncthreads();
    int r0 = (tid >> 4) << 2;
    int c0 = (tid & 15) << 3;
    float acc[4][8];
    #pragma unroll
    for (int i = 0; i < 4; i++)
        #pragma unroll
        for (int j = 0; j < 8; j++) acc[i][j] = 0.f;
    #pragma unroll 4
    for (int k = 0; k < 128; k++) {
        float a[4];
        #pragma unroll
        for (int i = 0; i < 4; i++) a[i] = sg[(r0+i)*128 + k];
        float4 b0 = *reinterpret_cast<const float4*>(&sw[k*128 + c0]);
        float4 b1v = *reinterpret_cast<const float4*>(&sw[k*128 + c0 + 4]);
        #pragma unroll
        for (int i = 0; i < 4; i++) {
            acc[i][0] += a[i]*b0.x; acc[i][1] += a[i]*b0.y;
            acc[i][2] += a[i]*b0.z; acc[i][3] += a[i]*b0.w;
            acc[i][4] += a[i]*b1v.x; acc[i][5] += a[i]*b1v.y;
            acc[i][6] += a[i]*b1v.z; acc[i][7] += a[i]*b1v.w;
        }
    }
    #pragma unroll
    for (int i = 0; i < 4; i++) {
        float4 v0 = make_float4(acc[i][0], acc[i][1], acc[i][2], acc[i][3]);
        float4 v1 = make_float4(acc[i][4], acc[i][5], acc[i][6], acc[i][7]);
        *reinterpret_cast<float4*>(&g_h2[(size_t)(base+r0+i)*128 + c0]) = v0;
        *reinterpret_cast<float4*>(&g_h2[(size_t)(base+r0+i)*128 + c0 + 4]) = v1;
    }
}

// ---------------- pooling (bias2+elu fused) + dense ----------------
__global__ void k_pool(const int* __restrict__ batch, const float* __restrict__ b2) {
    int gw = (blockIdx.x * blockDim.x + threadIdx.x) >> 5;
    int lane = threadIdx.x & 31;
    if (gw >= NN) return;
    int g = batch[gw];
    int c = lane * 4;
    float4 v = *reinterpret_cast<const float4*>(&g_out2[(size_t)gw*128 + c]);
    v.x = elu1(v.x + b2[c]);
    v.y = elu1(v.y + b2[c+1]);
    v.z = elu1(v.z + b2[c+2]);
    v.w = elu1(v.w + b2[c+3]);
    red_add_v4(&g_sums[g*128 + c], v);
    if (lane == 0) atomicAdd(&g_cnt[g], 1.0f);
}

__global__ void k_drug(const float* __restrict__ Wd, const float* __restrict__ bd) {
    int idx = blockIdx.x * blockDim.x + threadIdx.x;
    if (idx >= NG*256) return;
    int g = idx >> 8, j = idx & 255;
    float invc = 1.f / fmaxf(g_cnt[g], 1.f);
    const float* srow = g_sums + g*128;
    float acc = 0.f;
    #pragma unroll 4
    for (int k = 0; k < 128; k++) acc += srow[k] * Wd[k*256 + j];
    g_drug[idx] = fmaxf(acc * invc + bd[j], 0.f);
}

__global__ void k_prot(const float* __restrict__ Wp, const float* __restrict__ bp) {
    int idx = blockIdx.x * blockDim.x + threadIdx.x;
    if (idx >= NB*256) return;
    int g = idx >> 8, j = idx & 255;
    const float* srow = g_pmax + g*128;
    float acc = 0.f;
    #pragma unroll 4
    for (int k = 0; k < 128; k++) acc += srow[k] * Wp[k*256 + j];
    g_prot[idx] = fmaxf(acc + bp[j], 0.f);
}

// ---------------- head MLP ----------------
__global__ void __launch_bounds__(128) k_head(const float* __restrict__ Wf1, const float* __restrict__ bf1,
                                              const float* __restrict__ Wf2, const float* __restrict__ bf2,
                                              const float* __restrict__ Wo, const float* __restrict__ bo,
                                              float* __restrict__ out) {
    __shared__ float sh[512];
    __shared__ float s1[128];
    __shared__ float s2[64];
    int g = blockIdx.x, tid = threadIdx.x;
    for (int i = tid; i < 256; i += 128) {
        sh[i]       = g_drug[g*256 + i];
        sh[256 + i] = g_prot[g*256 + i];
    }
    __syncthreads();
    float acc = 0.f;
    #pragma unroll 8
    for (int k = 0; k < 512; k++) acc += sh[k] * Wf1[k*128 + tid];
    s1[tid] = fmaxf(acc + bf1[tid], 0.f);
    __syncthreads();
    if (tid < 64) {
        float a = 0.f;
        #pragma unroll 8
        for (int k = 0; k < 128; k++) a += s1[k] * Wf2[k*64 + tid];
        s2[tid] = fmaxf(a + bf2[tid], 0.f);
    }
    __syncthreads();
    if (tid < 32) {
        float a = s2[tid]*Wo[tid] + s2[tid+32]*Wo[tid+32];
        a = warp_sum(a);
        if (tid == 0) out[g] = a + bo[0];
    }
}

// ---------------- launch ----------------
extern "C" void kernel_launch(void* const* d_in, const int* in_sizes, int n_in,
                              void* d_out, int out_size) {
    const float* x        = (const float*)d_in[0];
    const int*   ei       = (const int*)d_in[1];
    const int*   batch    = (const int*)d_in[2];
    const int*   seq      = (const int*)d_in[3];
    const float* W1       = (const float*)d_in[4];
    const float* att_s1   = (const float*)d_in[5];
    const float* att_d1   = (const float*)d_in[6];
    const float* b1       = (const float*)d_in[7];
    const float* W2       = (const float*)d_in[8];
    const float* att_s2   = (const float*)d_in[9];
    const float* att_d2   = (const float*)d_in[10];
    const float* b2       = (const float*)d_in[11];
    const float* Wd       = (const float*)d_in[12];
    const float* bd       = (const float*)d_in[13];
    const float* Pe       = (const float*)d_in[14];
    const float* K1       = (const float*)d_in[15];
    const float* bk1      = (const float*)d_in[16];
    const float* K2       = (const float*)d_in[17];
    const float* bk2      = (const float*)d_in[18];
    const float* Wp       = (const float*)d_in[19];
    const float* bp       = (const float*)d_in[20];
    const float* Wf1      = (const float*)d_in[21];
    const float* bf1      = (const float*)d_in[22];
    const float* Wf2      = (const float*)d_in[23];
    const float* bf2      = (const float*)d_in[24];
    const float* Wo       = (const float*)d_in[25];
    const float* bo       = (const float*)d_in[26];
    float* out = (float*)d_out;

    cudaFuncSetAttribute(k_gat2_mm,    cudaFuncAttributeMaxDynamicSharedMemorySize, 98304);
    cudaFuncSetAttribute(k_conv2_hmma, cudaFuncAttributeMaxDynamicSharedMemorySize, C2_SMEM);

    const int ET = NE + NN;

    // protein branch
    k_tab<<<17, 256>>>(Pe, K1, bk1);                               // 0
    {
        dim3 grid((LL + 15)/16, NB);
        k_conv1_apply<<<grid, 256>>>(seq);                         // 1
    }
    k_init<<<2048, 256>>>();                                       // 2
    k_conv2_hmma<<<148, 512, C2_SMEM>>>(K2, bk2);                  // 3  <- profile target
    k_prot<<<(NB*256 + 255)/256, 256>>>(Wp, bp);                   // 4

    // drug branch: GAT layer 1
    k_gat1_mm<<<(NN*128 + 255)/256, 256>>>(x, W1);                 // 5
    k_att1<<<(NN*32 + 255)/256, 256>>>(att_s1, att_d1);
    k_edge_max<2><<<(ET + 255)/256, 256>>>(ei);
    k_edge_den<2><<<(ET + 255)/256, 256>>>(ei);
    k_edge_acc<2><<<(ET*32 + 255)/256, 256>>>(ei);

    // GAT layer 2 (bias1+elu fused into the GEMM A-load)
    k_gat2_mm<<<NN/64, 256, 98304>>>(W2, b1);
    k_att2<<<(NN*32 + 255)/256, 256>>>(att_s2, att_d2);
    k_edge_max<1><<<(ET + 255)/256, 256>>>(ei);
    k_edge_den<1><<<(ET + 255)/256, 256>>>(ei);
    k_edge_acc<1><<<(ET*32 + 255)/256, 256>>>(ei);

    // pooling (bias2+elu fused) + drug dense
    k_pool<<<(NN*32 + 255)/256, 256>>>(batch, b2);
    k_drug<<<(NG*256 + 255)/256, 256>>>(Wd, bd);

    // head
    k_head<<<NG, 128>>>(Wf1, bf1, Wf2, bf2, Wo, bo, out);
}

// round 10
// speedup vs baseline: 1.3400x; 1.0961x over previous
#include <cuda_runtime.h>
#include <cuda_fp16.h>
#include <cstdint>

#define NN 24576
#define NE 98304
#define NG 512
#define NB 512
#define LL 1000

// ---------------- scratch (device globals; runtime alloc forbidden) ----------------
__device__ float g_h1[NN*128];
__device__ float g_as1[NN*2];
__device__ float g_ad1[NN*2];
__device__ float g_m1[NN*2];
__device__ float g_den1[NN*2];
__device__ float g_e1[(NE+NN)*2];
__device__ float g_out1[NN*128];
__device__ float g_h2[NN*128];
__device__ float g_as2[NN];
__device__ float g_ad2[NN];
__device__ float g_m2[NN];
__device__ float g_den2[NN];
__device__ float g_e2[NE+NN];
__device__ float g_out2[NN*128];
__device__ float g_sums[NG*128];
__device__ float g_cnt[NG];
__device__ float g_drug[NG*256];
__device__ float g_T[3*22*64];
__device__ float g_p1[NB*LL*64];
__device__ float g_pmax[NB*128];
__device__ float g_prot[NB*256];

// ---------------- helpers ----------------
__device__ __forceinline__ void red_add_v4(float* addr, float4 v) {
    asm volatile("red.global.add.v4.f32 [%0], {%1, %2, %3, %4};"
                 :: "l"(addr), "f"(v.x), "f"(v.y), "f"(v.z), "f"(v.w) : "memory");
}
__device__ __forceinline__ void atomicMaxFloat(float* addr, float val) {
    if (val >= 0.f) atomicMax((int*)addr, __float_as_int(val));
    else            atomicMin((unsigned int*)addr, __float_as_uint(val));
}
__device__ __forceinline__ float warp_sum(float v) {
    #pragma unroll
    for (int off = 16; off; off >>= 1) v += __shfl_down_sync(0xffffffffu, v, off);
    return v;
}
__device__ __forceinline__ float elu1(float v) { return v > 0.f ? v : expm1f(v); }

__device__ __forceinline__ void mma_fp16(float* c, const uint32_t* a, const uint32_t* b) {
    asm volatile(
        "mma.sync.aligned.m16n8k16.row.col.f32.f16.f16.f32 "
        "{%0,%1,%2,%3}, {%4,%5,%6,%7}, {%8,%9}, {%0,%1,%2,%3};"
        : "+f"(c[0]), "+f"(c[1]), "+f"(c[2]), "+f"(c[3])
        : "r"(a[0]), "r"(a[1]), "r"(a[2]), "r"(a[3]), "r"(b[0]), "r"(b[1]));
}
__device__ __forceinline__ void ldsm_x4(uint32_t* r, uint32_t addr) {
    asm volatile("ldmatrix.sync.aligned.m8n8.x4.shared.b16 {%0,%1,%2,%3}, [%4];"
                 : "=r"(r[0]), "=r"(r[1]), "=r"(r[2]), "=r"(r[3]) : "r"(addr));
}
__device__ __forceinline__ uint32_t smem_u32(const void* p) {
    uint32_t a;
    asm("{ .reg .u64 t; cvta.to.shared.u64 t, %1; cvt.u32.u64 %0, t; }" : "=r"(a) : "l"(p));
    return a;
}

// ---------------- conv2 via fp16 2-term HMMA, N-split across 2 CTAs/SM ----------------
// GEMM: M=128 l, N=64 o per CTA (half), K=320, im2col via A row overlap.
// a*b ~= ah*bh + al*bh (A error-compensated; B truncated to fp16: rel ~2^-12).
// A: 132 rows x 64 ch fp16, stride 72 elems (144B -> LDSM conflict-free).
// B: 64 o x 320 k fp16, stride 328 elems (656B -> LDSM conflict-free).
// smem 81KB -> 2 CTAs/SM; the peer CTA's mainloop hides this CTA's A-prep/epilogue.
#define C2_A_STRIDE 72
#define C2_AH 0
#define C2_AL 19584
#define C2_BH 39168
#define C2_B_STRIDE 328
#define C2_SMEM 81152
#define C2_WORK (NB*8*2)

__global__ void __launch_bounds__(256) k_conv2_hmma(const float* __restrict__ K2,
                                                    const float* __restrict__ bk2) {
    extern __shared__ char smem[];
    __half* BhS = reinterpret_cast<__half*>(smem + C2_BH);
    uint32_t* AhW = reinterpret_cast<uint32_t*>(smem + C2_AH);
    uint32_t* AlW = reinterpret_cast<uint32_t*>(smem + C2_AL);

    int tid = threadIdx.x, wid = tid >> 5, lane = tid & 31;
    int g = lane >> 2, q = lane & 3;
    int mw = (wid >> 1) * 32;          // M group: 0,32,64,96
    int nw = (wid & 1) * 32;           // N group within 64-half: 0,32
    int o_base = (blockIdx.x & 1) * 64;

    uint32_t sb = smem_u32(smem);
    uint32_t sbAh = sb + C2_AH, sbAl = sb + C2_AL, sbBh = sb + C2_BH;

    // A x4: 16 rows (lane&15), +16B for lanes 16-31
    uint32_t aoff = (uint32_t)(lane & 15) * 144u + ((lane & 16) ? 16u : 0u);
    // B x4 covering an nt-pair: lanes 0-7 rows r0..r0+7 (k0-7), 8-15 +16B (k8-15),
    // 16-23 rows +8 (next nt, k0-7), 24-31 rows +8 +16B.
    uint32_t boff = (uint32_t)(lane & 7) * 656u + ((lane & 8) ? 16u : 0u)
                  + ((lane & 16) ? 8u*656u : 0u);

    // ---- B conversion (once per CTA): this CTA's 64-row half, hi only ----
    for (int idx = tid; idx < 64*320; idx += 256) {
        int n = idx / 320, k = idx - n*320;
        int t = k >> 6, i = k & 63;
        BhS[n*C2_B_STRIDE + k] = __float2half_rn(K2[((o_base + n)*64 + i)*5 + t]);
    }

    float bias[4][2];
    #pragma unroll
    for (int nt = 0; nt < 4; nt++) {
        int col = o_base + nw + nt*8 + q*2;
        bias[nt][0] = bk2[col];
        bias[nt][1] = bk2[col + 1];
    }

    for (int work = blockIdx.x; work < C2_WORK; work += gridDim.x) {
        int tile = work >> 1;           // parity of work == blockIdx.x&1 (grid even)
        int b = tile >> 3, l0 = (tile & 7) * 125;
        __syncthreads();                // prior mainloop's A reads complete

        // ---- A load + fp16 hi/lo conversion ----
        for (int idx = tid; idx < 132*32; idx += 256) {
            int row = idx >> 5, p = idx & 31;
            int l = l0 + row - 2;
            float2 v = make_float2(0.f, 0.f);
            if (l >= 0 && l < LL)
                v = *reinterpret_cast<const float2*>(&g_p1[((size_t)b*LL + l)*64 + p*2]);
            __half2 h2 = __float22half2_rn(v);
            float2 hf = __half22float2(h2);
            __half2 l2 = __float22half2_rn(make_float2(v.x - hf.x, v.y - hf.y));
            AhW[row*36 + p] = *reinterpret_cast<uint32_t*>(&h2);
            AlW[row*36 + p] = *reinterpret_cast<uint32_t*>(&l2);
        }
        __syncthreads();

        float acc[2][4][4];
        #pragma unroll
        for (int mt = 0; mt < 2; mt++)
            #pragma unroll
            for (int nt = 0; nt < 4; nt++)
                #pragma unroll
                for (int j = 0; j < 4; j++) acc[mt][nt][j] = 0.f;

        #pragma unroll 1
        for (int ks = 0; ks < 20; ks++) {
            int t = ks >> 2;
            uint32_t kb = (uint32_t)((ks & 3) * 32);
            uint32_t ah[2][4], al[2][4], bb[2][4];
            uint32_t aBase = (uint32_t)((mw + t) * 144) + kb + aoff;
            #pragma unroll
            for (int mt = 0; mt < 2; mt++) {
                ldsm_x4(ah[mt], sbAh + aBase + (uint32_t)(mt*16*144));
                ldsm_x4(al[mt], sbAl + aBase + (uint32_t)(mt*16*144));
            }
            uint32_t bBase = (uint32_t)(nw * 656) + (uint32_t)(t * 128) + kb + boff;
            #pragma unroll
            for (int np = 0; np < 2; np++)
                ldsm_x4(bb[np], sbBh + bBase + (uint32_t)(np*16*656));
            #pragma unroll
            for (int mt = 0; mt < 2; mt++)
                #pragma unroll
                for (int nt = 0; nt < 4; nt++)
                    mma_fp16(acc[mt][nt], ah[mt], &bb[nt >> 1][(nt & 1)*2]);  // ah*bh
            #pragma unroll
            for (int mt = 0; mt < 2; mt++)
                #pragma unroll
                for (int nt = 0; nt < 4; nt++)
                    mma_fp16(acc[mt][nt], al[mt], &bb[nt >> 1][(nt & 1)*2]);  // al*bh
        }

        // ---- epilogue: bias + elu + max over valid l (regs + shfl only) ----
        float mx[4][2];
        #pragma unroll
        for (int nt = 0; nt < 4; nt++) { mx[nt][0] = -3.0e38f; mx[nt][1] = -3.0e38f; }
        #pragma unroll
        for (int mt = 0; mt < 2; mt++) {
            int lr = l0 + mw + mt*16 + g;
            bool v0 = lr < LL, v1 = (lr + 8) < LL;
            #pragma unroll
            for (int nt = 0; nt < 4; nt++) {
                if (v0) {
                    mx[nt][0] = fmaxf(mx[nt][0], elu1(acc[mt][nt][0] + bias[nt][0]));
                    mx[nt][1] = fmaxf(mx[nt][1], elu1(acc[mt][nt][1] + bias[nt][1]));
                }
                if (v1) {
                    mx[nt][0] = fmaxf(mx[nt][0], elu1(acc[mt][nt][2] + bias[nt][0]));
                    mx[nt][1] = fmaxf(mx[nt][1], elu1(acc[mt][nt][3] + bias[nt][1]));
                }
            }
        }
        #pragma unroll
        for (int nt = 0; nt < 4; nt++) {
            #pragma unroll
            for (int j = 0; j < 2; j++) {
                float v = mx[nt][j];
                v = fmaxf(v, __shfl_xor_sync(0xffffffffu, v, 4));
                v = fmaxf(v, __shfl_xor_sync(0xffffffffu, v, 8));
                v = fmaxf(v, __shfl_xor_sync(0xffffffffu, v, 16));
                if (lane < 4)
                    atomicMaxFloat(&g_pmax[b*128 + o_base + nw + nt*8 + lane*2 + j], v);
            }
        }
    }
}

// ---------------- conv1 token tables ----------------
__global__ void k_tab(const float* __restrict__ Pe, const float* __restrict__ K1,
                      const float* __restrict__ bk1) {
    int idx = blockIdx.x * blockDim.x + threadIdx.x;
    if (idx >= 3*22*64) return;
    int o = idx & 63, r = idx >> 6;
    int t = r % 22, k = r / 22;
    float acc = (k == 1) ? bk1[o] : 0.f;
    #pragma unroll 8
    for (int i = 0; i < 64; i++) acc += Pe[t*64 + i] * K1[(o*64 + i)*3 + k];
    g_T[idx] = acc;
}

// ---------------- conv1 apply ----------------
__global__ void __launch_bounds__(256) k_conv1_apply(const int* __restrict__ seq) {
    int b = blockIdx.y;
    int lofs = threadIdx.x >> 4, lq = threadIdx.x & 15;
    int l = blockIdx.x * 16 + lofs;
    if (l >= LL) return;
    int s1 = seq[b*LL + l];
    int c = lq * 4;
    float4 v = *reinterpret_cast<const float4*>(&g_T[(22 + s1)*64 + c]);
    if (l > 0) {
        int s0 = seq[b*LL + l - 1];
        float4 a = *reinterpret_cast<const float4*>(&g_T[s0*64 + c]);
        v.x += a.x; v.y += a.y; v.z += a.z; v.w += a.w;
    }
    if (l < LL-1) {
        int s2 = seq[b*LL + l + 1];
        float4 a = *reinterpret_cast<const float4*>(&g_T[(44 + s2)*64 + c]);
        v.x += a.x; v.y += a.y; v.z += a.z; v.w += a.w;
    }
    v.x = elu1(v.x); v.y = elu1(v.y); v.z = elu1(v.z); v.w = elu1(v.w);
    *reinterpret_cast<float4*>(&g_p1[((size_t)b*LL + l)*64 + c]) = v;
}

// ---------------- init ----------------
__global__ void k_init() {
    int i = blockIdx.x * blockDim.x + threadIdx.x;
    int stride = gridDim.x * blockDim.x;
    for (int idx = i; idx < NN*128; idx += stride) { g_out1[idx] = 0.f; g_out2[idx] = 0.f; }
    for (int idx = i; idx < NN*2; idx += stride) { g_m1[idx] = -3.0e38f; g_den1[idx] = 0.f; }
    for (int idx = i; idx < NN; idx += stride) { g_m2[idx] = -3.0e38f; g_den2[idx] = 0.f; }
    for (int idx = i; idx < NG*128; idx += stride) g_sums[idx] = 0.f;
    for (int idx = i; idx < NG; idx += stride) g_cnt[idx] = 0.f;
    for (int idx = i; idx < NB*128; idx += stride) g_pmax[idx] = -3.0e38f;
}

// ---------------- GAT1 GEMM ----------------
__global__ void k_gat1_mm(const float* __restrict__ x, const float* __restrict__ W1) {
    int idx = blockIdx.x * blockDim.x + threadIdx.x;
    if (idx >= NN*128) return;
    int n = idx >> 7, c = idx & 127;
    float acc = 0.f;
    #pragma unroll
    for (int f = 0; f < 5; f++) acc += x[n*5 + f] * W1[f*128 + c];
    g_h1[idx] = acc;
}

// attention scalars, 2 heads of 64
__global__ void k_att1(const float* __restrict__ att_s, const float* __restrict__ att_d) {
    int gw = (blockIdx.x * blockDim.x + threadIdx.x) >> 5;
    int lane = threadIdx.x & 31;
    if (gw >= NN) return;
    const float* hr = g_h1 + (size_t)gw * 128;
    float s0 = hr[lane]*att_s[lane] + hr[lane+32]*att_s[lane+32];
    float s1 = hr[lane+64]*att_s[lane+64] + hr[lane+96]*att_s[lane+96];
    float d0 = hr[lane]*att_d[lane] + hr[lane+32]*att_d[lane+32];
    float d1 = hr[lane+64]*att_d[lane+64] + hr[lane+96]*att_d[lane+96];
    s0 = warp_sum(s0); s1 = warp_sum(s1); d0 = warp_sum(d0); d1 = warp_sum(d1);
    if (lane == 0) {
        g_as1[gw*2] = s0; g_as1[gw*2+1] = s1;
        g_ad1[gw*2] = d0; g_ad1[gw*2+1] = d1;
    }
}

// attention scalars, 1 head of 128
__global__ void k_att2(const float* __restrict__ att_s, const float* __restrict__ att_d) {
    int gw = (blockIdx.x * blockDim.x + threadIdx.x) >> 5;
    int lane = threadIdx.x & 31;
    if (gw >= NN) return;
    const float* hr = g_h2 + (size_t)gw * 128;
    float s = 0.f, d = 0.f;
    #pragma unroll
    for (int t = 0; t < 4; t++) {
        int p = lane + 32*t;
        s += hr[p]*att_s[p];
        d += hr[p]*att_d[p];
    }
    s = warp_sum(s); d = warp_sum(d);
    if (lane == 0) { g_as2[gw] = s; g_ad2[gw] = d; }
}

// ---------------- edge passes ----------------
template<int H>
__global__ void k_edge_max(const int* __restrict__ ei) {
    int e = blockIdx.x * blockDim.x + threadIdx.x;
    const int ET = NE + NN;
    if (e >= ET) return;
    int src, dst;
    if (e < NE) { src = ei[e]; dst = ei[NE + e]; } else { src = dst = e - NE; }
    const float* as_ = (H == 2) ? g_as1 : g_as2;
    const float* ad_ = (H == 2) ? g_ad1 : g_ad2;
    float* m_ = (H == 2) ? g_m1 : g_m2;
    float* e_ = (H == 2) ? g_e1 : g_e2;
    #pragma unroll
    for (int h = 0; h < H; h++) {
        float v = as_[src*H+h] + ad_[dst*H+h];
        v = v > 0.f ? v : 0.2f * v;
        e_[e*H+h] = v;
        atomicMaxFloat(&m_[dst*H+h], v);
    }
}

template<int H>
__global__ void k_edge_den(const int* __restrict__ ei) {
    int e = blockIdx.x * blockDim.x + threadIdx.x;
    const int ET = NE + NN;
    if (e >= ET) return;
    int dst = (e < NE) ? ei[NE + e] : (e - NE);
    const float* m_ = (H == 2) ? g_m1 : g_m2;
    float* den_ = (H == 2) ? g_den1 : g_den2;
    float* e_ = (H == 2) ? g_e1 : g_e2;
    #pragma unroll
    for (int h = 0; h < H; h++) {
        float w = expf(e_[e*H+h] - m_[dst*H+h]);
        e_[e*H+h] = w;
        atomicAdd(&den_[dst*H+h], w);
    }
}

template<int H>
__global__ void k_edge_acc(const int* __restrict__ ei) {
    int gw = (blockIdx.x * blockDim.x + threadIdx.x) >> 5;
    int lane = threadIdx.x & 31;
    const int ET = NE + NN;
    if (gw >= ET) return;
    int src, dst;
    if (gw < NE) { src = ei[gw]; dst = ei[NE + gw]; } else { src = dst = gw - NE; }
    const float* den_ = (H == 2) ? g_den1 : g_den2;
    const float* e_ = (H == 2) ? g_e1 : g_e2;
    const float* hin = (H == 2) ? g_h1 : g_h2;
    float* outp = (H == 2) ? g_out1 : g_out2;
    int h = (H == 2 && lane >= 16) ? 1 : 0;
    float alpha = e_[gw*H + h] / (den_[dst*H + h] + 1e-16f);
    float4 v = *reinterpret_cast<const float4*>(&hin[(size_t)src*128 + lane*4]);
    v.x *= alpha; v.y *= alpha; v.z *= alpha; v.w *= alpha;
    red_add_v4(&outp[(size_t)dst*128 + lane*4], v);
}

// ---------------- GAT2 GEMM (bias1+elu fused on A-load) ----------------
__global__ void __launch_bounds__(256) k_gat2_mm(const float* __restrict__ W2,
                                                 const float* __restrict__ b1) {
    extern __shared__ float sm[];
    float* sg = sm;
    float* sw = sm + 64*128;
    int base = blockIdx.x * 64;
    int tid = threadIdx.x;
    for (int idx = tid; idx < 64*128; idx += 256)
        sg[idx] = elu1(g_out1[(size_t)base*128 + idx] + b1[idx & 127]);
    for (int idx = tid; idx < 128*128; idx += 256) sw[idx] = W2[idx];
    __syncthreads();
    int r0 = (tid >> 4) << 2;
    int c0 = (tid & 15) << 3;
    float acc[4][8];
    #pragma unroll
    for (int i = 0; i < 4; i++)
        #pragma unroll
        for (int j = 0; j < 8; j++) acc[i][j] = 0.f;
    #pragma unroll 4
    for (int k = 0; k < 128; k++) {
        float a[4];
        #pragma unroll
        for (int i = 0; i < 4; i++) a[i] = sg[(r0+i)*128 + k];
        float4 b0 = *reinterpret_cast<const float4*>(&sw[k*128 + c0]);
        float4 b1v = *reinterpret_cast<const float4*>(&sw[k*128 + c0 + 4]);
        #pragma unroll
        for (int i = 0; i < 4; i++) {
            acc[i][0] += a[i]*b0.x; acc[i][1] += a[i]*b0.y;
            acc[i][2] += a[i]*b0.z; acc[i][3] += a[i]*b0.w;
            acc[i][4] += a[i]*b1v.x; acc[i][5] += a[i]*b1v.y;
            acc[i][6] += a[i]*b1v.z; acc[i][7] += a[i]*b1v.w;
        }
    }
    #pragma unroll
    for (int i = 0; i < 4; i++) {
        float4 v0 = make_float4(acc[i][0], acc[i][1], acc[i][2], acc[i][3]);
        float4 v1 = make_float4(acc[i][4], acc[i][5], acc[i][6], acc[i][7]);
        *reinterpret_cast<float4*>(&g_h2[(size_t)(base+r0+i)*128 + c0]) = v0;
        *reinterpret_cast<float4*>(&g_h2[(size_t)(base+r0+i)*128 + c0 + 4]) = v1;
    }
}

// ---------------- pooling (bias2+elu fused) + dense ----------------
__global__ void k_pool(const int* __restrict__ batch, const float* __restrict__ b2) {
    int gw = (blockIdx.x * blockDim.x + threadIdx.x) >> 5;
    int lane = threadIdx.x & 31;
    if (gw >= NN) return;
    int g = batch[gw];
    int c = lane * 4;
    float4 v = *reinterpret_cast<const float4*>(&g_out2[(size_t)gw*128 + c]);
    v.x = elu1(v.x + b2[c]);
    v.y = elu1(v.y + b2[c+1]);
    v.z = elu1(v.z + b2[c+2]);
    v.w = elu1(v.w + b2[c+3]);
    red_add_v4(&g_sums[g*128 + c], v);
    if (lane == 0) atomicAdd(&g_cnt[g], 1.0f);
}

__global__ void k_drug(const float* __restrict__ Wd, const float* __restrict__ bd) {
    int idx = blockIdx.x * blockDim.x + threadIdx.x;
    if (idx >= NG*256) return;
    int g = idx >> 8, j = idx & 255;
    float invc = 1.f / fmaxf(g_cnt[g], 1.f);
    const float* srow = g_sums + g*128;
    float acc = 0.f;
    #pragma unroll 4
    for (int k = 0; k < 128; k++) acc += srow[k] * Wd[k*256 + j];
    g_drug[idx] = fmaxf(acc * invc + bd[j], 0.f);
}

__global__ void k_prot(const float* __restrict__ Wp, const float* __restrict__ bp) {
    int idx = blockIdx.x * blockDim.x + threadIdx.x;
    if (idx >= NB*256) return;
    int g = idx >> 8, j = idx & 255;
    const float* srow = g_pmax + g*128;
    float acc = 0.f;
    #pragma unroll 4
    for (int k = 0; k < 128; k++) acc += srow[k] * Wp[k*256 + j];
    g_prot[idx] = fmaxf(acc + bp[j], 0.f);
}

// ---------------- head MLP ----------------
__global__ void __launch_bounds__(128) k_head(const float* __restrict__ Wf1, const float* __restrict__ bf1,
                                              const float* __restrict__ Wf2, const float* __restrict__ bf2,
                                              const float* __restrict__ Wo, const float* __restrict__ bo,
                                              float* __restrict__ out) {
    __shared__ float sh[512];
    __shared__ float s1[128];
    __shared__ float s2[64];
    int g = blockIdx.x, tid = threadIdx.x;
    for (int i = tid; i < 256; i += 128) {
        sh[i]       = g_drug[g*256 + i];
        sh[256 + i] = g_prot[g*256 + i];
    }
    __syncthreads();
    float acc = 0.f;
    #pragma unroll 8
    for (int k = 0; k < 512; k++) acc += sh[k] * Wf1[k*128 + tid];
    s1[tid] = fmaxf(acc + bf1[tid], 0.f);
    __syncthreads();
    if (tid < 64) {
        float a = 0.f;
        #pragma unroll 8
        for (int k = 0; k < 128; k++) a += s1[k] * Wf2[k*64 + tid];
        s2[tid] = fmaxf(a + bf2[tid], 0.f);
    }
    __syncthreads();
    if (tid < 32) {
        float a = s2[tid]*Wo[tid] + s2[tid+32]*Wo[tid+32];
        a = warp_sum(a);
        if (tid == 0) out[g] = a + bo[0];
    }
}

// ---------------- launch ----------------
extern "C" void kernel_launch(void* const* d_in, const int* in_sizes, int n_in,
                              void* d_out, int out_size) {
    const float* x        = (const float*)d_in[0];
    const int*   ei       = (const int*)d_in[1];
    const int*   batch    = (const int*)d_in[2];
    const int*   seq      = (const int*)d_in[3];
    const float* W1       = (const float*)d_in[4];
    const float* att_s1   = (const float*)d_in[5];
    const float* att_d1   = (const float*)d_in[6];
    const float* b1       = (const float*)d_in[7];
    const float* W2       = (const float*)d_in[8];
    const float* att_s2   = (const float*)d_in[9];
    const float* att_d2   = (const float*)d_in[10];
    const float* b2       = (const float*)d_in[11];
    const float* Wd       = (const float*)d_in[12];
    const float* bd       = (const float*)d_in[13];
    const float* Pe       = (const float*)d_in[14];
    const float* K1       = (const float*)d_in[15];
    const float* bk1      = (const float*)d_in[16];
    const float* K2       = (const float*)d_in[17];
    const float* bk2      = (const float*)d_in[18];
    const float* Wp       = (const float*)d_in[19];
    const float* bp       = (const float*)d_in[20];
    const float* Wf1      = (const float*)d_in[21];
    const float* bf1      = (const float*)d_in[22];
    const float* Wf2      = (const float*)d_in[23];
    const float* bf2      = (const float*)d_in[24];
    const float* Wo       = (const float*)d_in[25];
    const float* bo       = (const float*)d_in[26];
    float* out = (float*)d_out;

    cudaFuncSetAttribute(k_gat2_mm,    cudaFuncAttributeMaxDynamicSharedMemorySize, 98304);
    cudaFuncSetAttribute(k_conv2_hmma, cudaFuncAttributeMaxDynamicSharedMemorySize, C2_SMEM);

    const int ET = NE + NN;

    // protein branch
    k_tab<<<17, 256>>>(Pe, K1, bk1);                               // 0
    {
        dim3 grid((LL + 15)/16, NB);
        k_conv1_apply<<<grid, 256>>>(seq);                         // 1
    }
    k_init<<<2048, 256>>>();                                       // 2
    k_conv2_hmma<<<296, 256, C2_SMEM>>>(K2, bk2);                  // 3  <- profile target
    k_prot<<<(NB*256 + 255)/256, 256>>>(Wp, bp);                   // 4

    // drug branch: GAT layer 1
    k_gat1_mm<<<(NN*128 + 255)/256, 256>>>(x, W1);                 // 5
    k_att1<<<(NN*32 + 255)/256, 256>>>(att_s1, att_d1);
    k_edge_max<2><<<(ET + 255)/256, 256>>>(ei);
    k_edge_den<2><<<(ET + 255)/256, 256>>>(ei);
    k_edge_acc<2><<<(ET*32 + 255)/256, 256>>>(ei);

    // GAT layer 2 (bias1+elu fused into the GEMM A-load)
    k_gat2_mm<<<NN/64, 256, 98304>>>(W2, b1);
    k_att2<<<(NN*32 + 255)/256, 256>>>(att_s2, att_d2);
    k_edge_max<1><<<(ET + 255)/256, 256>>>(ei);
    k_edge_den<1><<<(ET + 255)/256, 256>>>(ei);
    k_edge_acc<1><<<(ET*32 + 255)/256, 256>>>(ei);

    // pooling (bias2+elu fused) + drug dense
    k_pool<<<(NN*32 + 255)/256, 256>>>(batch, b2);
    k_drug<<<(NG*256 + 255)/256, 256>>>(Wd, bd);

    // head
    k_head<<<NG, 128>>>(Wf1, bf1, Wf2, bf2, Wo, bo, out);
}

// round 11
// speedup vs baseline: 1.4389x; 1.0738x over previous
#include <cuda_runtime.h>
#include <cuda_fp16.h>
#include <cstdint>

#define NN 24576
#define NE 98304
#define NG 512
#define NB 512
#define LL 1000

// ---------------- scratch (device globals; runtime alloc forbidden) ----------------
__device__ float g_h1[NN*128];
__device__ float g_as1[NN*2];
__device__ float g_ad1[NN*2];
__device__ float g_den1[NN*2];
__device__ float g_e1[(NE+NN)*2];
__device__ float g_out1[NN*128];
__device__ float g_h2[NN*128];
__device__ float g_as2[NN];
__device__ float g_ad2[NN];
__device__ float g_den2[NN];
__device__ float g_e2[NE+NN];
__device__ float g_out2[NN*128];
__device__ float g_sums[NG*128];
__device__ float g_cnt[NG];
__device__ float g_drug[NG*256];
__device__ float g_T[3*22*64];
__device__ __half g_p1h[NB*LL*64];   // conv1 output hi (fp16), [b][l][i]
__device__ __half g_p1l[NB*LL*64];   // conv1 output lo (fp16 residual)
__device__ float g_pmax[NB*128];
__device__ float g_prot[NB*256];

// ---------------- helpers ----------------
__device__ __forceinline__ void red_add_v4(float* addr, float4 v) {
    asm volatile("red.global.add.v4.f32 [%0], {%1, %2, %3, %4};"
                 :: "l"(addr), "f"(v.x), "f"(v.y), "f"(v.z), "f"(v.w) : "memory");
}
__device__ __forceinline__ void atomicMaxFloat(float* addr, float val) {
    if (val >= 0.f) atomicMax((int*)addr, __float_as_int(val));
    else            atomicMin((unsigned int*)addr, __float_as_uint(val));
}
__device__ __forceinline__ float warp_sum(float v) {
    #pragma unroll
    for (int off = 16; off; off >>= 1) v += __shfl_down_sync(0xffffffffu, v, off);
    return v;
}
__device__ __forceinline__ float elu1(float v) { return v > 0.f ? v : expm1f(v); }

__device__ __forceinline__ void mma_fp16(float* c, const uint32_t* a, const uint32_t* b) {
    asm volatile(
        "mma.sync.aligned.m16n8k16.row.col.f32.f16.f16.f32 "
        "{%0,%1,%2,%3}, {%4,%5,%6,%7}, {%8,%9}, {%0,%1,%2,%3};"
        : "+f"(c[0]), "+f"(c[1]), "+f"(c[2]), "+f"(c[3])
        : "r"(a[0]), "r"(a[1]), "r"(a[2]), "r"(a[3]), "r"(b[0]), "r"(b[1]));
}
__device__ __forceinline__ void ldsm_x4(uint32_t* r, uint32_t addr) {
    asm volatile("ldmatrix.sync.aligned.m8n8.x4.shared.b16 {%0,%1,%2,%3}, [%4];"
                 : "=r"(r[0]), "=r"(r[1]), "=r"(r[2]), "=r"(r[3]) : "r"(addr));
}
__device__ __forceinline__ uint32_t smem_u32(const void* p) {
    uint32_t a;
    asm("{ .reg .u64 t; cvta.to.shared.u64 t, %1; cvt.u32.u64 %0, t; }" : "=r"(a) : "l"(p));
    return a;
}

// ---------------- conv2 via fp16 2-term HMMA, M-split across 2 CTAs/SM ----------------
// GEMM: per CTA M=64 l (half, +4 halo rows), N=128 o, K=320.
// a*b ~= ah*bh + al*bh (A error-compensated; B truncated to fp16).
// A: 68 rows x 64 ch fp16, stride 72 elems (144B -> LDSM conflict-free), 2 terms.
// B: 128 o x 320 k fp16, stride 328 elems (656B -> LDSM conflict-free).
// A staged by cp.async from pre-converted g_p1h/g_p1l (no in-kernel conversion).
// smem ~103.5KB -> 2 CTAs/SM; peer CTA's mainloop hides A-stage/epilogue.
#define C2_AH 0
#define C2_AL 9792
#define C2_B  19584
#define C2_B_STRIDE 328
#define C2_SMEM 103552
#define C2_WORK (NB*8*2)

__global__ void __launch_bounds__(256) k_conv2_hmma(const float* __restrict__ K2,
                                                    const float* __restrict__ bk2) {
    extern __shared__ char smem[];
    __half* BhS = reinterpret_cast<__half*>(smem + C2_B);

    int tid = threadIdx.x, wid = tid >> 5, lane = tid & 31;
    int g = lane >> 2, q = lane & 3;
    int mw2 = (wid & 1) * 32;          // M group within 64-half: 0,32
    int nw4 = (wid >> 1) * 32;         // N group: 0,32,64,96
    int m_base = (blockIdx.x & 1) * 64;

    uint32_t sb = smem_u32(smem);
    uint32_t sbAh = sb + C2_AH, sbAl = sb + C2_AL, sbB = sb + C2_B;

    uint32_t aoff = (uint32_t)(lane & 15) * 144u + ((lane & 16) ? 16u : 0u);
    uint32_t boff = (uint32_t)(lane & 7) * 656u + ((lane & 8) ? 16u : 0u)
                  + ((lane & 16) ? 8u*656u : 0u);

    // ---- B conversion (once per CTA): full 128 rows, hi only ----
    for (int idx = tid; idx < 128*320; idx += 256) {
        int n = idx / 320, k = idx - n*320;
        int t = k >> 6, i = k & 63;
        BhS[n*C2_B_STRIDE + k] = __float2half_rn(K2[(n*64 + i)*5 + t]);
    }

    float bias[4][2];
    #pragma unroll
    for (int nt = 0; nt < 4; nt++) {
        int col = nw4 + nt*8 + q*2;
        bias[nt][0] = bk2[col];
        bias[nt][1] = bk2[col + 1];
    }

    for (int work = blockIdx.x; work < C2_WORK; work += gridDim.x) {
        int tile = work >> 1;           // parity of work == blockIdx.x & 1 (grid even)
        int b = tile >> 3, l0 = (tile & 7) * 125;
        __syncthreads();                // prior mainloop's A reads complete

        // ---- A stage via cp.async: 68 rows x 8 chunks x 2 terms = 1088 16B copies ----
        for (int idx = tid; idx < 1088; idx += 256) {
            int term = idx >= 544;
            int rr = idx - (term ? 544 : 0);
            int row = rr >> 3, c = rr & 7;
            int l = l0 + m_base - 2 + row;
            int lc = l < 0 ? 0 : (l >= LL ? LL-1 : l);
            const __half* gsrc = (term ? g_p1l : g_p1h) + ((size_t)b*LL + lc)*64 + c*8;
            uint32_t dst = (term ? sbAl : sbAh) + (uint32_t)(row*144 + c*16);
            int sz = (l >= 0 && l < LL) ? 16 : 0;
            asm volatile("cp.async.cg.shared.global [%0], [%1], 16, %2;"
                         :: "r"(dst), "l"(gsrc), "r"(sz));
        }
        asm volatile("cp.async.commit_group;" ::: "memory");
        asm volatile("cp.async.wait_group 0;" ::: "memory");
        __syncthreads();

        float acc[2][4][4];
        #pragma unroll
        for (int mt = 0; mt < 2; mt++)
            #pragma unroll
            for (int nt = 0; nt < 4; nt++)
                #pragma unroll
                for (int j = 0; j < 4; j++) acc[mt][nt][j] = 0.f;

        #pragma unroll 1
        for (int ks = 0; ks < 20; ks++) {
            int t = ks >> 2;
            uint32_t kb = (uint32_t)((ks & 3) * 32);
            uint32_t ah[2][4], al[2][4], bb[2][4];
            uint32_t aBase = (uint32_t)((mw2 + t) * 144) + kb + aoff;
            #pragma unroll
            for (int mt = 0; mt < 2; mt++) {
                ldsm_x4(ah[mt], sbAh + aBase + (uint32_t)(mt*16*144));
                ldsm_x4(al[mt], sbAl + aBase + (uint32_t)(mt*16*144));
            }
            uint32_t bBase = (uint32_t)(nw4 * 656) + (uint32_t)(t * 128) + kb + boff;
            #pragma unroll
            for (int np = 0; np < 2; np++)
                ldsm_x4(bb[np], sbB + bBase + (uint32_t)(np*16*656));
            #pragma unroll
            for (int mt = 0; mt < 2; mt++)
                #pragma unroll
                for (int nt = 0; nt < 4; nt++)
                    mma_fp16(acc[mt][nt], ah[mt], &bb[nt >> 1][(nt & 1)*2]);  // ah*bh
            #pragma unroll
            for (int mt = 0; mt < 2; mt++)
                #pragma unroll
                for (int nt = 0; nt < 4; nt++)
                    mma_fp16(acc[mt][nt], al[mt], &bb[nt >> 1][(nt & 1)*2]);  // al*bh
        }

        // ---- epilogue: bias + elu + max over valid l (regs + shfl only) ----
        float mx[4][2];
        #pragma unroll
        for (int nt = 0; nt < 4; nt++) { mx[nt][0] = -3.0e38f; mx[nt][1] = -3.0e38f; }
        #pragma unroll
        for (int mt = 0; mt < 2; mt++) {
            int lr = l0 + m_base + mw2 + mt*16 + g;
            bool v0 = lr < LL, v1 = (lr + 8) < LL;
            #pragma unroll
            for (int nt = 0; nt < 4; nt++) {
                if (v0) {
                    mx[nt][0] = fmaxf(mx[nt][0], elu1(acc[mt][nt][0] + bias[nt][0]));
                    mx[nt][1] = fmaxf(mx[nt][1], elu1(acc[mt][nt][1] + bias[nt][1]));
                }
                if (v1) {
                    mx[nt][0] = fmaxf(mx[nt][0], elu1(acc[mt][nt][2] + bias[nt][0]));
                    mx[nt][1] = fmaxf(mx[nt][1], elu1(acc[mt][nt][3] + bias[nt][1]));
                }
            }
        }
        #pragma unroll
        for (int nt = 0; nt < 4; nt++) {
            #pragma unroll
            for (int j = 0; j < 2; j++) {
                float v = mx[nt][j];
                v = fmaxf(v, __shfl_xor_sync(0xffffffffu, v, 4));
                v = fmaxf(v, __shfl_xor_sync(0xffffffffu, v, 8));
                v = fmaxf(v, __shfl_xor_sync(0xffffffffu, v, 16));
                if (lane < 4)
                    atomicMaxFloat(&g_pmax[b*128 + nw4 + nt*8 + lane*2 + j], v);
            }
        }
    }
}

// ---------------- conv1 token tables ----------------
__global__ void k_tab(const float* __restrict__ Pe, const float* __restrict__ K1,
                      const float* __restrict__ bk1) {
    int idx = blockIdx.x * blockDim.x + threadIdx.x;
    if (idx >= 3*22*64) return;
    int o = idx & 63, r = idx >> 6;
    int t = r % 22, k = r / 22;
    float acc = (k == 1) ? bk1[o] : 0.f;
    #pragma unroll 8
    for (int i = 0; i < 64; i++) acc += Pe[t*64 + i] * K1[(o*64 + i)*3 + k];
    g_T[idx] = acc;
}

// ---------------- conv1 apply: writes fp16 hi/lo directly ----------------
__global__ void __launch_bounds__(256) k_conv1_apply(const int* __restrict__ seq) {
    int b = blockIdx.y;
    int lofs = threadIdx.x >> 4, lq = threadIdx.x & 15;
    int l = blockIdx.x * 16 + lofs;
    if (l >= LL) return;
    int s1 = seq[b*LL + l];
    int c = lq * 4;
    float4 v = *reinterpret_cast<const float4*>(&g_T[(22 + s1)*64 + c]);
    if (l > 0) {
        int s0 = seq[b*LL + l - 1];
        float4 a = *reinterpret_cast<const float4*>(&g_T[s0*64 + c]);
        v.x += a.x; v.y += a.y; v.z += a.z; v.w += a.w;
    }
    if (l < LL-1) {
        int s2 = seq[b*LL + l + 1];
        float4 a = *reinterpret_cast<const float4*>(&g_T[(44 + s2)*64 + c]);
        v.x += a.x; v.y += a.y; v.z += a.z; v.w += a.w;
    }
    v.x = elu1(v.x); v.y = elu1(v.y); v.z = elu1(v.z); v.w = elu1(v.w);
    __half2 h0 = __floats2half2_rn(v.x, v.y);
    __half2 h1 = __floats2half2_rn(v.z, v.w);
    float2 f0 = __half22float2(h0), f1 = __half22float2(h1);
    __half2 l0h = __floats2half2_rn(v.x - f0.x, v.y - f0.y);
    __half2 l1h = __floats2half2_rn(v.z - f1.x, v.w - f1.y);
    size_t base = ((size_t)b*LL + l)*64 + c;
    *reinterpret_cast<__half2*>(&g_p1h[base])     = h0;
    *reinterpret_cast<__half2*>(&g_p1h[base + 2]) = h1;
    *reinterpret_cast<__half2*>(&g_p1l[base])     = l0h;
    *reinterpret_cast<__half2*>(&g_p1l[base + 2]) = l1h;
}

// ---------------- init ----------------
__global__ void k_init() {
    int i = blockIdx.x * blockDim.x + threadIdx.x;
    int stride = gridDim.x * blockDim.x;
    for (int idx = i; idx < NN*128; idx += stride) { g_out1[idx] = 0.f; g_out2[idx] = 0.f; }
    for (int idx = i; idx < NN*2; idx += stride) g_den1[idx] = 0.f;
    for (int idx = i; idx < NN; idx += stride) g_den2[idx] = 0.f;
    for (int idx = i; idx < NG*128; idx += stride) g_sums[idx] = 0.f;
    for (int idx = i; idx < NG; idx += stride) g_cnt[idx] = 0.f;
    for (int idx = i; idx < NB*128; idx += stride) g_pmax[idx] = -3.0e38f;
}

// ---------------- GAT1 GEMM ----------------
__global__ void k_gat1_mm(const float* __restrict__ x, const float* __restrict__ W1) {
    int idx = blockIdx.x * blockDim.x + threadIdx.x;
    if (idx >= NN*128) return;
    int n = idx >> 7, c = idx & 127;
    float acc = 0.f;
    #pragma unroll
    for (int f = 0; f < 5; f++) acc += x[n*5 + f] * W1[f*128 + c];
    g_h1[idx] = acc;
}

// attention scalars, 2 heads of 64
__global__ void k_att1(const float* __restrict__ att_s, const float* __restrict__ att_d) {
    int gw = (blockIdx.x * blockDim.x + threadIdx.x) >> 5;
    int lane = threadIdx.x & 31;
    if (gw >= NN) return;
    const float* hr = g_h1 + (size_t)gw * 128;
    float s0 = hr[lane]*att_s[lane] + hr[lane+32]*att_s[lane+32];
    float s1 = hr[lane+64]*att_s[lane+64] + hr[lane+96]*att_s[lane+96];
    float d0 = hr[lane]*att_d[lane] + hr[lane+32]*att_d[lane+32];
    float d1 = hr[lane+64]*att_d[lane+64] + hr[lane+96]*att_d[lane+96];
    s0 = warp_sum(s0); s1 = warp_sum(s1); d0 = warp_sum(d0); d1 = warp_sum(d1);
    if (lane == 0) {
        g_as1[gw*2] = s0; g_as1[gw*2+1] = s1;
        g_ad1[gw*2] = d0; g_ad1[gw*2+1] = d1;
    }
}

// attention scalars, 1 head of 128
__global__ void k_att2(const float* __restrict__ att_s, const float* __restrict__ att_d) {
    int gw = (blockIdx.x * blockDim.x + threadIdx.x) >> 5;
    int lane = threadIdx.x & 31;
    if (gw >= NN) return;
    const float* hr = g_h2 + (size_t)gw * 128;
    float s = 0.f, d = 0.f;
    #pragma unroll
    for (int t = 0; t < 4; t++) {
        int p = lane + 32*t;
        s += hr[p]*att_s[p];
        d += hr[p]*att_d[p];
    }
    s = warp_sum(s); d = warp_sum(d);
    if (lane == 0) { g_as2[gw] = s; g_ad2[gw] = d; }
}

// ---------------- edge passes (softmax without max-shift: scores are O(1)) ----------------
template<int H>
__global__ void k_edge_den(const int* __restrict__ ei) {
    int e = blockIdx.x * blockDim.x + threadIdx.x;
    const int ET = NE + NN;
    if (e >= ET) return;
    int src, dst;
    if (e < NE) { src = ei[e]; dst = ei[NE + e]; } else { src = dst = e - NE; }
    const float* as_ = (H == 2) ? g_as1 : g_as2;
    const float* ad_ = (H == 2) ? g_ad1 : g_ad2;
    float* den_ = (H == 2) ? g_den1 : g_den2;
    float* e_ = (H == 2) ? g_e1 : g_e2;
    #pragma unroll
    for (int h = 0; h < H; h++) {
        float v = as_[src*H+h] + ad_[dst*H+h];
        v = v > 0.f ? v : 0.2f * v;
        float w = expf(v);
        e_[e*H+h] = w;
        atomicAdd(&den_[dst*H+h], w);
    }
}

template<int H>
__global__ void k_edge_acc(const int* __restrict__ ei) {
    int gw = (blockIdx.x * blockDim.x + threadIdx.x) >> 5;
    int lane = threadIdx.x & 31;
    const int ET = NE + NN;
    if (gw >= ET) return;
    int src, dst;
    if (gw < NE) { src = ei[gw]; dst = ei[NE + gw]; } else { src = dst = gw - NE; }
    const float* den_ = (H == 2) ? g_den1 : g_den2;
    const float* e_ = (H == 2) ? g_e1 : g_e2;
    const float* hin = (H == 2) ? g_h1 : g_h2;
    float* outp = (H == 2) ? g_out1 : g_out2;
    int h = (H == 2 && lane >= 16) ? 1 : 0;
    float alpha = e_[gw*H + h] / (den_[dst*H + h] + 1e-16f);
    float4 v = *reinterpret_cast<const float4*>(&hin[(size_t)src*128 + lane*4]);
    v.x *= alpha; v.y *= alpha; v.z *= alpha; v.w *= alpha;
    red_add_v4(&outp[(size_t)dst*128 + lane*4], v);
}

// ---------------- GAT2 GEMM (bias1+elu fused on A-load) ----------------
__global__ void __launch_bounds__(256) k_gat2_mm(const float* __restrict__ W2,
                                                 const float* __restrict__ b1) {
    extern __shared__ float sm[];
    float* sg = sm;
    float* sw = sm + 64*128;
    int base = blockIdx.x * 64;
    int tid = threadIdx.x;
    for (int idx = tid; idx < 64*128; idx += 256)
        sg[idx] = elu1(g_out1[(size_t)base*128 + idx] + b1[idx & 127]);
    for (int idx = tid; idx < 128*128; idx += 256) sw[idx] = W2[idx];
    __syncthreads();
    int r0 = (tid >> 4) << 2;
    int c0 = (tid & 15) << 3;
    float acc[4][8];
    #pragma unroll
    for (int i = 0; i < 4; i++)
        #pragma unroll
        for (int j = 0; j < 8; j++) acc[i][j] = 0.f;
    #pragma unroll 4
    for (int k = 0; k < 128; k++) {
        float a[4];
        #pragma unroll
        for (int i = 0; i < 4; i++) a[i] = sg[(r0+i)*128 + k];
        float4 b0 = *reinterpret_cast<const float4*>(&sw[k*128 + c0]);
        float4 b1v = *reinterpret_cast<const float4*>(&sw[k*128 + c0 + 4]);
        #pragma unroll
        for (int i = 0; i < 4; i++) {
            acc[i][0] += a[i]*b0.x; acc[i][1] += a[i]*b0.y;
            acc[i][2] += a[i]*b0.z; acc[i][3] += a[i]*b0.w;
            acc[i][4] += a[i]*b1v.x; acc[i][5] += a[i]*b1v.y;
            acc[i][6] += a[i]*b1v.z; acc[i][7] += a[i]*b1v.w;
        }
    }
    #pragma unroll
    for (int i = 0; i < 4; i++) {
        float4 v0 = make_float4(acc[i][0], acc[i][1], acc[i][2], acc[i][3]);
        float4 v1 = make_float4(acc[i][4], acc[i][5], acc[i][6], acc[i][7]);
        *reinterpret_cast<float4*>(&g_h2[(size_t)(base+r0+i)*128 + c0]) = v0;
        *reinterpret_cast<float4*>(&g_h2[(size_t)(base+r0+i)*128 + c0 + 4]) = v1;
    }
}

// ---------------- pooling (bias2+elu fused) + dense ----------------
__global__ void k_pool(const int* __restrict__ batch, const float* __restrict__ b2) {
    int gw = (blockIdx.x * blockDim.x + threadIdx.x) >> 5;
    int lane = threadIdx.x & 31;
    if (gw >= NN) return;
    int g = batch[gw];
    int c = lane * 4;
    float4 v = *reinterpret_cast<const float4*>(&g_out2[(size_t)gw*128 + c]);
    v.x = elu1(v.x + b2[c]);
    v.y = elu1(v.y + b2[c+1]);
    v.z = elu1(v.z + b2[c+2]);
    v.w = elu1(v.w + b2[c+3]);
    red_add_v4(&g_sums[g*128 + c], v);
    if (lane == 0) atomicAdd(&g_cnt[g], 1.0f);
}

__global__ void k_drug(const float* __restrict__ Wd, const float* __restrict__ bd) {
    int idx = blockIdx.x * blockDim.x + threadIdx.x;
    if (idx >= NG*256) return;
    int g = idx >> 8, j = idx & 255;
    float invc = 1.f / fmaxf(g_cnt[g], 1.f);
    const float* srow = g_sums + g*128;
    float acc = 0.f;
    #pragma unroll 4
    for (int k = 0; k < 128; k++) acc += srow[k] * Wd[k*256 + j];
    g_drug[idx] = fmaxf(acc * invc + bd[j], 0.f);
}

__global__ void k_prot(const float* __restrict__ Wp, const float* __restrict__ bp) {
    int idx = blockIdx.x * blockDim.x + threadIdx.x;
    if (idx >= NB*256) return;
    int g = idx >> 8, j = idx & 255;
    const float* srow = g_pmax + g*128;
    float acc = 0.f;
    #pragma unroll 4
    for (int k = 0; k < 128; k++) acc += srow[k] * Wp[k*256 + j];
    g_prot[idx] = fmaxf(acc + bp[j], 0.f);
}

// ---------------- head MLP ----------------
__global__ void __launch_bounds__(128) k_head(const float* __restrict__ Wf1, const float* __restrict__ bf1,
                                              const float* __restrict__ Wf2, const float* __restrict__ bf2,
                                              const float* __restrict__ Wo, const float* __restrict__ bo,
                                              float* __restrict__ out) {
    __shared__ float sh[512];
    __shared__ float s1[128];
    __shared__ float s2[64];
    int g = blockIdx.x, tid = threadIdx.x;
    for (int i = tid; i < 256; i += 128) {
        sh[i]       = g_drug[g*256 + i];
        sh[256 + i] = g_prot[g*256 + i];
    }
    __syncthreads();
    float acc = 0.f;
    #pragma unroll 8
    for (int k = 0; k < 512; k++) acc += sh[k] * Wf1[k*128 + tid];
    s1[tid] = fmaxf(acc + bf1[tid], 0.f);
    __syncthreads();
    if (tid < 64) {
        float a = 0.f;
        #pragma unroll 8
        for (int k = 0; k < 128; k++) a += s1[k] * Wf2[k*64 + tid];
        s2[tid] = fmaxf(a + bf2[tid], 0.f);
    }
    __syncthreads();
    if (tid < 32) {
        float a = s2[tid]*Wo[tid] + s2[tid+32]*Wo[tid+32];
        a = warp_sum(a);
        if (tid == 0) out[g] = a + bo[0];
    }
}

// ---------------- launch ----------------
extern "C" void kernel_launch(void* const* d_in, const int* in_sizes, int n_in,
                              void* d_out, int out_size) {
    const float* x        = (const float*)d_in[0];
    const int*   ei       = (const int*)d_in[1];
    const int*   batch    = (const int*)d_in[2];
    const int*   seq      = (const int*)d_in[3];
    const float* W1       = (const float*)d_in[4];
    const float* att_s1   = (const float*)d_in[5];
    const float* att_d1   = (const float*)d_in[6];
    const float* b1       = (const float*)d_in[7];
    const float* W2       = (const float*)d_in[8];
    const float* att_s2   = (const float*)d_in[9];
    const float* att_d2   = (const float*)d_in[10];
    const float* b2       = (const float*)d_in[11];
    const float* Wd       = (const float*)d_in[12];
    const float* bd       = (const float*)d_in[13];
    const float* Pe       = (const float*)d_in[14];
    const float* K1       = (const float*)d_in[15];
    const float* bk1      = (const float*)d_in[16];
    const float* K2       = (const float*)d_in[17];
    const float* bk2      = (const float*)d_in[18];
    const float* Wp       = (const float*)d_in[19];
    const float* bp       = (const float*)d_in[20];
    const float* Wf1      = (const float*)d_in[21];
    const float* bf1      = (const float*)d_in[22];
    const float* Wf2      = (const float*)d_in[23];
    const float* bf2      = (const float*)d_in[24];
    const float* Wo       = (const float*)d_in[25];
    const float* bo       = (const float*)d_in[26];
    float* out = (float*)d_out;

    cudaFuncSetAttribute(k_gat2_mm,    cudaFuncAttributeMaxDynamicSharedMemorySize, 98304);
    cudaFuncSetAttribute(k_conv2_hmma, cudaFuncAttributeMaxDynamicSharedMemorySize, C2_SMEM);

    const int ET = NE + NN;

    // protein branch
    k_tab<<<17, 256>>>(Pe, K1, bk1);                               // 0
    {
        dim3 grid((LL + 15)/16, NB);
        k_conv1_apply<<<grid, 256>>>(seq);                         // 1
    }
    k_init<<<2048, 256>>>();                                       // 2
    k_conv2_hmma<<<296, 256, C2_SMEM>>>(K2, bk2);                  // 3  <- profile target
    k_prot<<<(NB*256 + 255)/256, 256>>>(Wp, bp);                   // 4

    // drug branch: GAT layer 1
    k_gat1_mm<<<(NN*128 + 255)/256, 256>>>(x, W1);                 // 5
    k_att1<<<(NN*32 + 255)/256, 256>>>(att_s1, att_d1);
    k_edge_den<2><<<(ET + 255)/256, 256>>>(ei);
    k_edge_acc<2><<<(ET*32 + 255)/256, 256>>>(ei);

    // GAT layer 2 (bias1+elu fused into the GEMM A-load)
    k_gat2_mm<<<NN/64, 256, 98304>>>(W2, b1);
    k_att2<<<(NN*32 + 255)/256, 256>>>(att_s2, att_d2);
    k_edge_den<1><<<(ET + 255)/256, 256>>>(ei);
    k_edge_acc<1><<<(ET*32 + 255)/256, 256>>>(ei);

    // pooling (bias2+elu fused) + drug dense
    k_pool<<<(NN*32 + 255)/256, 256>>>(batch, b2);
    k_drug<<<(NG*256 + 255)/256, 256>>>(Wd, bd);

    // head
    k_head<<<NG, 128>>>(Wf1, bf1, Wf2, bf2, Wo, bo, out);
}

// round 12
// speedup vs baseline: 1.6862x; 1.1719x over previous
#include <cuda_runtime.h>
#include <cuda_fp16.h>
#include <cstdint>

#define NN 24576
#define NE 98304
#define NG 512
#define NB 512
#define LL 1000

// ---------------- scratch (device globals; runtime alloc forbidden) ----------------
__device__ float g_h1[NN*128];
__device__ float g_as1[NN*2];
__device__ float g_ad1[NN*2];
__device__ float g_den1[NN*2];
__device__ float g_e1[(NE+NN)*2];
__device__ float g_out1[NN*128];
__device__ float g_h2[NN*128];
__device__ float g_as2[NN];
__device__ float g_ad2[NN];
__device__ float g_den2[NN];
__device__ float g_e2[NE+NN];
__device__ float g_out2[NN*128];
__device__ float g_sums[NG*128];
__device__ float g_cnt[NG];
__device__ float g_drug[NG*256];
__device__ float g_T[3*22*64];
__device__ __half g_p1h[NB*LL*64];   // conv1 output (fp16), [b][l][i]
__device__ float g_pmax[NB*128];
__device__ float g_prot[NB*256];

// ---------------- helpers ----------------
__device__ __forceinline__ void red_add_v4(float* addr, float4 v) {
    asm volatile("red.global.add.v4.f32 [%0], {%1, %2, %3, %4};"
                 :: "l"(addr), "f"(v.x), "f"(v.y), "f"(v.z), "f"(v.w) : "memory");
}
__device__ __forceinline__ void atomicMaxFloat(float* addr, float val) {
    if (val >= 0.f) atomicMax((int*)addr, __float_as_int(val));
    else            atomicMin((unsigned int*)addr, __float_as_uint(val));
}
__device__ __forceinline__ float warp_sum(float v) {
    #pragma unroll
    for (int off = 16; off; off >>= 1) v += __shfl_down_sync(0xffffffffu, v, off);
    return v;
}
__device__ __forceinline__ float elu1(float v) { return v > 0.f ? v : expm1f(v); }

__device__ __forceinline__ void mma_fp16(float* c, const uint32_t* a, const uint32_t* b) {
    asm volatile(
        "mma.sync.aligned.m16n8k16.row.col.f32.f16.f16.f32 "
        "{%0,%1,%2,%3}, {%4,%5,%6,%7}, {%8,%9}, {%0,%1,%2,%3};"
        : "+f"(c[0]), "+f"(c[1]), "+f"(c[2]), "+f"(c[3])
        : "r"(a[0]), "r"(a[1]), "r"(a[2]), "r"(a[3]), "r"(b[0]), "r"(b[1]));
}
__device__ __forceinline__ void ldsm_x4(uint32_t* r, uint32_t addr) {
    asm volatile("ldmatrix.sync.aligned.m8n8.x4.shared.b16 {%0,%1,%2,%3}, [%4];"
                 : "=r"(r[0]), "=r"(r[1]), "=r"(r[2]), "=r"(r[3]) : "r"(addr));
}
__device__ __forceinline__ uint32_t smem_u32(const void* p) {
    uint32_t a;
    asm("{ .reg .u64 t; cvta.to.shared.u64 t, %1; cvt.u32.u64 %0, t; }" : "=r"(a) : "l"(p));
    return a;
}

// ---------------- conv2 via single-term fp16 HMMA, M-split across 2 CTAs/SM ----------------
// GEMM: per CTA M=64 l (half, +4 halo rows), N=128 o, K=320. Plain fp16xfp16->fp32.
// A: 68 rows x 64 ch fp16, stride 72 elems (144B -> LDSM conflict-free).
// B: 128 o x 320 k fp16, stride 328 elems (656B -> LDSM conflict-free).
// A staged by cp.async from pre-converted g_p1h; NEXT tile's A issued after the
// mainloop and waited at loop top, so its latency hides under the epilogue.
#define C2_A  0
#define C2_B  9792
#define C2_B_STRIDE 328
#define C2_SMEM 93760
#define C2_WORK (NB*8*2)

__global__ void __launch_bounds__(256) k_conv2_hmma(const float* __restrict__ K2,
                                                    const float* __restrict__ bk2) {
    extern __shared__ char smem[];
    __half* BhS = reinterpret_cast<__half*>(smem + C2_B);

    int tid = threadIdx.x, wid = tid >> 5, lane = tid & 31;
    int g = lane >> 2, q = lane & 3;
    int mw2 = (wid & 1) * 32;          // M group within 64-half: 0,32
    int nw4 = (wid >> 1) * 32;         // N group: 0,32,64,96
    int m_base = (blockIdx.x & 1) * 64;

    uint32_t sb = smem_u32(smem);
    uint32_t sbA = sb + C2_A, sbB = sb + C2_B;

    uint32_t aoff = (uint32_t)(lane & 15) * 144u + ((lane & 16) ? 16u : 0u);
    uint32_t boff = (uint32_t)(lane & 7) * 656u + ((lane & 8) ? 16u : 0u)
                  + ((lane & 16) ? 8u*656u : 0u);

    // ---- B conversion (once per CTA): full 128 rows ----
    for (int idx = tid; idx < 128*320; idx += 256) {
        int n = idx / 320, k = idx - n*320;
        int t = k >> 6, i = k & 63;
        BhS[n*C2_B_STRIDE + k] = __float2half_rn(K2[(n*64 + i)*5 + t]);
    }

    float bias[4][2];
    #pragma unroll
    for (int nt = 0; nt < 4; nt++) {
        int col = nw4 + nt*8 + q*2;
        bias[nt][0] = bk2[col];
        bias[nt][1] = bk2[col + 1];
    }

    // A stage for a given work item: 68 rows x 8 chunks of 16B
    auto issue_A = [&](int work_) {
        int tile_ = work_ >> 1;
        int b_ = tile_ >> 3;
        int lbase = (tile_ & 7) * 125 + m_base - 2;
        for (int idx = tid; idx < 544; idx += 256) {
            int row = idx >> 3, c = idx & 7;
            int l = lbase + row;
            int lc = l < 0 ? 0 : (l >= LL ? LL-1 : l);
            const __half* gsrc = g_p1h + ((size_t)b_*LL + lc)*64 + c*8;
            uint32_t dst = sbA + (uint32_t)(row*144 + c*16);
            int sz = (l >= 0 && l < LL) ? 16 : 0;
            asm volatile("cp.async.cg.shared.global [%0], [%1], 16, %2;"
                         :: "r"(dst), "l"(gsrc), "r"(sz));
        }
        asm volatile("cp.async.commit_group;" ::: "memory");
    };

    issue_A(blockIdx.x);
    for (int work = blockIdx.x; work < C2_WORK; work += gridDim.x) {
        int tile = work >> 1;          // parity of work == blockIdx.x & 1 (grid even)
        int b = tile >> 3, l0 = (tile & 7) * 125;
        asm volatile("cp.async.wait_group 0;" ::: "memory");
        __syncthreads();               // A ready; also prior epilogue done

        float acc[2][4][4];
        #pragma unroll
        for (int mt = 0; mt < 2; mt++)
            #pragma unroll
            for (int nt = 0; nt < 4; nt++)
                #pragma unroll
                for (int j = 0; j < 4; j++) acc[mt][nt][j] = 0.f;

        #pragma unroll
        for (int ks = 0; ks < 20; ks++) {
            int t = ks >> 2;
            uint32_t kb = (uint32_t)((ks & 3) * 32);
            uint32_t ah[2][4], bb[2][4];
            uint32_t aBase = (uint32_t)((mw2 + t) * 144) + kb + aoff;
            #pragma unroll
            for (int mt = 0; mt < 2; mt++)
                ldsm_x4(ah[mt], sbA + aBase + (uint32_t)(mt*16*144));
            uint32_t bBase = (uint32_t)(nw4 * 656) + (uint32_t)(t * 128) + kb + boff;
            #pragma unroll
            for (int np = 0; np < 2; np++)
                ldsm_x4(bb[np], sbB + bBase + (uint32_t)(np*16*656));
            #pragma unroll
            for (int mt = 0; mt < 2; mt++)
                #pragma unroll
                for (int nt = 0; nt < 4; nt++)
                    mma_fp16(acc[mt][nt], ah[mt], &bb[nt >> 1][(nt & 1)*2]);
        }

        __syncthreads();               // all warps done reading A
        if (work + (int)gridDim.x < C2_WORK)
            issue_A(work + gridDim.x); // latency hides under epilogue

        // ---- epilogue: bias + elu + max over valid l (regs + shfl only) ----
        float mx[4][2];
        #pragma unroll
        for (int nt = 0; nt < 4; nt++) { mx[nt][0] = -3.0e38f; mx[nt][1] = -3.0e38f; }
        #pragma unroll
        for (int mt = 0; mt < 2; mt++) {
            int lr = l0 + m_base + mw2 + mt*16 + g;
            bool v0 = lr < LL, v1 = (lr + 8) < LL;
            #pragma unroll
            for (int nt = 0; nt < 4; nt++) {
                if (v0) {
                    mx[nt][0] = fmaxf(mx[nt][0], elu1(acc[mt][nt][0] + bias[nt][0]));
                    mx[nt][1] = fmaxf(mx[nt][1], elu1(acc[mt][nt][1] + bias[nt][1]));
                }
                if (v1) {
                    mx[nt][0] = fmaxf(mx[nt][0], elu1(acc[mt][nt][2] + bias[nt][0]));
                    mx[nt][1] = fmaxf(mx[nt][1], elu1(acc[mt][nt][3] + bias[nt][1]));
                }
            }
        }
        #pragma unroll
        for (int nt = 0; nt < 4; nt++) {
            #pragma unroll
            for (int j = 0; j < 2; j++) {
                float v = mx[nt][j];
                v = fmaxf(v, __shfl_xor_sync(0xffffffffu, v, 4));
                v = fmaxf(v, __shfl_xor_sync(0xffffffffu, v, 8));
                v = fmaxf(v, __shfl_xor_sync(0xffffffffu, v, 16));
                if (lane < 4)
                    atomicMaxFloat(&g_pmax[b*128 + nw4 + nt*8 + lane*2 + j], v);
            }
        }
    }
}

// ---------------- conv1 token tables ----------------
__global__ void k_tab(const float* __restrict__ Pe, const float* __restrict__ K1,
                      const float* __restrict__ bk1) {
    int idx = blockIdx.x * blockDim.x + threadIdx.x;
    if (idx >= 3*22*64) return;
    int o = idx & 63, r = idx >> 6;
    int t = r % 22, k = r / 22;
    float acc = (k == 1) ? bk1[o] : 0.f;
    #pragma unroll 8
    for (int i = 0; i < 64; i++) acc += Pe[t*64 + i] * K1[(o*64 + i)*3 + k];
    g_T[idx] = acc;
}

// ---------------- conv1 apply: writes fp16 directly ----------------
__global__ void __launch_bounds__(256) k_conv1_apply(const int* __restrict__ seq) {
    int b = blockIdx.y;
    int lofs = threadIdx.x >> 4, lq = threadIdx.x & 15;
    int l = blockIdx.x * 16 + lofs;
    if (l >= LL) return;
    int s1 = seq[b*LL + l];
    int c = lq * 4;
    float4 v = *reinterpret_cast<const float4*>(&g_T[(22 + s1)*64 + c]);
    if (l > 0) {
        int s0 = seq[b*LL + l - 1];
        float4 a = *reinterpret_cast<const float4*>(&g_T[s0*64 + c]);
        v.x += a.x; v.y += a.y; v.z += a.z; v.w += a.w;
    }
    if (l < LL-1) {
        int s2 = seq[b*LL + l + 1];
        float4 a = *reinterpret_cast<const float4*>(&g_T[(44 + s2)*64 + c]);
        v.x += a.x; v.y += a.y; v.z += a.z; v.w += a.w;
    }
    __half2 h0 = __floats2half2_rn(elu1(v.x), elu1(v.y));
    __half2 h1 = __floats2half2_rn(elu1(v.z), elu1(v.w));
    size_t base = ((size_t)b*LL + l)*64 + c;
    *reinterpret_cast<__half2*>(&g_p1h[base])     = h0;
    *reinterpret_cast<__half2*>(&g_p1h[base + 2]) = h1;
}

// ---------------- init ----------------
__global__ void k_init() {
    int i = blockIdx.x * blockDim.x + threadIdx.x;
    int stride = gridDim.x * blockDim.x;
    for (int idx = i; idx < NN*128; idx += stride) { g_out1[idx] = 0.f; g_out2[idx] = 0.f; }
    for (int idx = i; idx < NN*2; idx += stride) g_den1[idx] = 0.f;
    for (int idx = i; idx < NN; idx += stride) g_den2[idx] = 0.f;
    for (int idx = i; idx < NG*128; idx += stride) g_sums[idx] = 0.f;
    for (int idx = i; idx < NG; idx += stride) g_cnt[idx] = 0.f;
    for (int idx = i; idx < NB*128; idx += stride) g_pmax[idx] = -3.0e38f;
}

// ---------------- GAT1 GEMM ----------------
__global__ void k_gat1_mm(const float* __restrict__ x, const float* __restrict__ W1) {
    int idx = blockIdx.x * blockDim.x + threadIdx.x;
    if (idx >= NN*128) return;
    int n = idx >> 7, c = idx & 127;
    float acc = 0.f;
    #pragma unroll
    for (int f = 0; f < 5; f++) acc += x[n*5 + f] * W1[f*128 + c];
    g_h1[idx] = acc;
}

// attention scalars, 2 heads of 64
__global__ void k_att1(const float* __restrict__ att_s, const float* __restrict__ att_d) {
    int gw = (blockIdx.x * blockDim.x + threadIdx.x) >> 5;
    int lane = threadIdx.x & 31;
    if (gw >= NN) return;
    const float* hr = g_h1 + (size_t)gw * 128;
    float s0 = hr[lane]*att_s[lane] + hr[lane+32]*att_s[lane+32];
    float s1 = hr[lane+64]*att_s[lane+64] + hr[lane+96]*att_s[lane+96];
    float d0 = hr[lane]*att_d[lane] + hr[lane+32]*att_d[lane+32];
    float d1 = hr[lane+64]*att_d[lane+64] + hr[lane+96]*att_d[lane+96];
    s0 = warp_sum(s0); s1 = warp_sum(s1); d0 = warp_sum(d0); d1 = warp_sum(d1);
    if (lane == 0) {
        g_as1[gw*2] = s0; g_as1[gw*2+1] = s1;
        g_ad1[gw*2] = d0; g_ad1[gw*2+1] = d1;
    }
}

// attention scalars, 1 head of 128
__global__ void k_att2(const float* __restrict__ att_s, const float* __restrict__ att_d) {
    int gw = (blockIdx.x * blockDim.x + threadIdx.x) >> 5;
    int lane = threadIdx.x & 31;
    if (gw >= NN) return;
    const float* hr = g_h2 + (size_t)gw * 128;
    float s = 0.f, d = 0.f;
    #pragma unroll
    for (int t = 0; t < 4; t++) {
        int p = lane + 32*t;
        s += hr[p]*att_s[p];
        d += hr[p]*att_d[p];
    }
    s = warp_sum(s); d = warp_sum(d);
    if (lane == 0) { g_as2[gw] = s; g_ad2[gw] = d; }
}

// ---------------- edge passes (softmax without max-shift: scores are O(1)) ----------------
template<int H>
__global__ void k_edge_den(const int* __restrict__ ei) {
    int e = blockIdx.x * blockDim.x + threadIdx.x;
    const int ET = NE + NN;
    if (e >= ET) return;
    int src, dst;
    if (e < NE) { src = ei[e]; dst = ei[NE + e]; } else { src = dst = e - NE; }
    const float* as_ = (H == 2) ? g_as1 : g_as2;
    const float* ad_ = (H == 2) ? g_ad1 : g_ad2;
    float* den_ = (H == 2) ? g_den1 : g_den2;
    float* e_ = (H == 2) ? g_e1 : g_e2;
    #pragma unroll
    for (int h = 0; h < H; h++) {
        float v = as_[src*H+h] + ad_[dst*H+h];
        v = v > 0.f ? v : 0.2f * v;
        float w = expf(v);
        e_[e*H+h] = w;
        atomicAdd(&den_[dst*H+h], w);
    }
}

template<int H>
__global__ void k_edge_acc(const int* __restrict__ ei) {
    int gw = (blockIdx.x * blockDim.x + threadIdx.x) >> 5;
    int lane = threadIdx.x & 31;
    const int ET = NE + NN;
    if (gw >= ET) return;
    int src, dst;
    if (gw < NE) { src = ei[gw]; dst = ei[NE + gw]; } else { src = dst = gw - NE; }
    const float* den_ = (H == 2) ? g_den1 : g_den2;
    const float* e_ = (H == 2) ? g_e1 : g_e2;
    const float* hin = (H == 2) ? g_h1 : g_h2;
    float* outp = (H == 2) ? g_out1 : g_out2;
    int h = (H == 2 && lane >= 16) ? 1 : 0;
    float alpha = e_[gw*H + h] / (den_[dst*H + h] + 1e-16f);
    float4 v = *reinterpret_cast<const float4*>(&hin[(size_t)src*128 + lane*4]);
    v.x *= alpha; v.y *= alpha; v.z *= alpha; v.w *= alpha;
    red_add_v4(&outp[(size_t)dst*128 + lane*4], v);
}

// ---------------- GAT2 GEMM (bias1+elu fused on A-load) ----------------
__global__ void __launch_bounds__(256) k_gat2_mm(const float* __restrict__ W2,
                                                 const float* __restrict__ b1) {
    extern __shared__ float sm[];
    float* sg = sm;
    float* sw = sm + 64*128;
    int base = blockIdx.x * 64;
    int tid = threadIdx.x;
    for (int idx = tid; idx < 64*128; idx += 256)
        sg[idx] = elu1(g_out1[(size_t)base*128 + idx] + b1[idx & 127]);
    for (int idx = tid; idx < 128*128; idx += 256) sw[idx] = W2[idx];
    __syncthreads();
    int r0 = (tid >> 4) << 2;
    int c0 = (tid & 15) << 3;
    float acc[4][8];
    #pragma unroll
    for (int i = 0; i < 4; i++)
        #pragma unroll
        for (int j = 0; j < 8; j++) acc[i][j] = 0.f;
    #pragma unroll 4
    for (int k = 0; k < 128; k++) {
        float a[4];
        #pragma unroll
        for (int i = 0; i < 4; i++) a[i] = sg[(r0+i)*128 + k];
        float4 b0 = *reinterpret_cast<const float4*>(&sw[k*128 + c0]);
        float4 b1v = *reinterpret_cast<const float4*>(&sw[k*128 + c0 + 4]);
        #pragma unroll
        for (int i = 0; i < 4; i++) {
            acc[i][0] += a[i]*b0.x; acc[i][1] += a[i]*b0.y;
            acc[i][2] += a[i]*b0.z; acc[i][3] += a[i]*b0.w;
            acc[i][4] += a[i]*b1v.x; acc[i][5] += a[i]*b1v.y;
            acc[i][6] += a[i]*b1v.z; acc[i][7] += a[i]*b1v.w;
        }
    }
    #pragma unroll
    for (int i = 0; i < 4; i++) {
        float4 v0 = make_float4(acc[i][0], acc[i][1], acc[i][2], acc[i][3]);
        float4 v1 = make_float4(acc[i][4], acc[i][5], acc[i][6], acc[i][7]);
        *reinterpret_cast<float4*>(&g_h2[(size_t)(base+r0+i)*128 + c0]) = v0;
        *reinterpret_cast<float4*>(&g_h2[(size_t)(base+r0+i)*128 + c0 + 4]) = v1;
    }
}

// ---------------- pooling (bias2+elu fused) + dense ----------------
__global__ void k_pool(const int* __restrict__ batch, const float* __restrict__ b2) {
    int gw = (blockIdx.x * blockDim.x + threadIdx.x) >> 5;
    int lane = threadIdx.x & 31;
    if (gw >= NN) return;
    int g = batch[gw];
    int c = lane * 4;
    float4 v = *reinterpret_cast<const float4*>(&g_out2[(size_t)gw*128 + c]);
    v.x = elu1(v.x + b2[c]);
    v.y = elu1(v.y + b2[c+1]);
    v.z = elu1(v.z + b2[c+2]);
    v.w = elu1(v.w + b2[c+3]);
    red_add_v4(&g_sums[g*128 + c], v);
    if (lane == 0) atomicAdd(&g_cnt[g], 1.0f);
}

__global__ void k_drug(const float* __restrict__ Wd, const float* __restrict__ bd) {
    int idx = blockIdx.x * blockDim.x + threadIdx.x;
    if (idx >= NG*64) return;
    int g = idx >> 6, j4 = (idx & 63) * 4;
    float invc = 1.f / fmaxf(g_cnt[g], 1.f);
    const float* srow = g_sums + g*128;
    float4 a = make_float4(0.f, 0.f, 0.f, 0.f);
    #pragma unroll 8
    for (int k = 0; k < 128; k++) {
        float s = srow[k];
        float4 w = *reinterpret_cast<const float4*>(&Wd[k*256 + j4]);
        a.x += s*w.x; a.y += s*w.y; a.z += s*w.z; a.w += s*w.w;
    }
    float4 r;
    r.x = fmaxf(a.x * invc + bd[j4],     0.f);
    r.y = fmaxf(a.y * invc + bd[j4 + 1], 0.f);
    r.z = fmaxf(a.z * invc + bd[j4 + 2], 0.f);
    r.w = fmaxf(a.w * invc + bd[j4 + 3], 0.f);
    *reinterpret_cast<float4*>(&g_drug[g*256 + j4]) = r;
}

__global__ void k_prot(const float* __restrict__ Wp, const float* __restrict__ bp) {
    int idx = blockIdx.x * blockDim.x + threadIdx.x;
    if (idx >= NB*64) return;
    int g = idx >> 6, j4 = (idx & 63) * 4;
    const float* srow = g_pmax + g*128;
    float4 a = make_float4(0.f, 0.f, 0.f, 0.f);
    #pragma unroll 8
    for (int k = 0; k < 128; k++) {
        float s = srow[k];
        float4 w = *reinterpret_cast<const float4*>(&Wp[k*256 + j4]);
        a.x += s*w.x; a.y += s*w.y; a.z += s*w.z; a.w += s*w.w;
    }
    float4 r;
    r.x = fmaxf(a.x + bp[j4],     0.f);
    r.y = fmaxf(a.y + bp[j4 + 1], 0.f);
    r.z = fmaxf(a.z + bp[j4 + 2], 0.f);
    r.w = fmaxf(a.w + bp[j4 + 3], 0.f);
    *reinterpret_cast<float4*>(&g_prot[g*256 + j4]) = r;
}

// ---------------- head MLP ----------------
__global__ void __launch_bounds__(128) k_head(const float* __restrict__ Wf1, const float* __restrict__ bf1,
                                              const float* __restrict__ Wf2, const float* __restrict__ bf2,
                                              const float* __restrict__ Wo, const float* __restrict__ bo,
                                              float* __restrict__ out) {
    __shared__ float sh[512];
    __shared__ float s1[128];
    __shared__ float s2[64];
    int g = blockIdx.x, tid = threadIdx.x;
    for (int i = tid; i < 256; i += 128) {
        sh[i]       = g_drug[g*256 + i];
        sh[256 + i] = g_prot[g*256 + i];
    }
    __syncthreads();
    float acc = 0.f;
    #pragma unroll 8
    for (int k = 0; k < 512; k++) acc += sh[k] * Wf1[k*128 + tid];
    s1[tid] = fmaxf(acc + bf1[tid], 0.f);
    __syncthreads();
    if (tid < 64) {
        float a = 0.f;
        #pragma unroll 8
        for (int k = 0; k < 128; k++) a += s1[k] * Wf2[k*64 + tid];
        s2[tid] = fmaxf(a + bf2[tid], 0.f);
    }
    __syncthreads();
    if (tid < 32) {
        float a = s2[tid]*Wo[tid] + s2[tid+32]*Wo[tid+32];
        a = warp_sum(a);
        if (tid == 0) out[g] = a + bo[0];
    }
}

// ---------------- launch ----------------
extern "C" void kernel_launch(void* const* d_in, const int* in_sizes, int n_in,
                              void* d_out, int out_size) {
    const float* x        = (const float*)d_in[0];
    const int*   ei       = (const int*)d_in[1];
    const int*   batch    = (const int*)d_in[2];
    const int*   seq      = (const int*)d_in[3];
    const float* W1       = (const float*)d_in[4];
    const float* att_s1   = (const float*)d_in[5];
    const float* att_d1   = (const float*)d_in[6];
    const float* b1       = (const float*)d_in[7];
    const float* W2       = (const float*)d_in[8];
    const float* att_s2   = (const float*)d_in[9];
    const float* att_d2   = (const float*)d_in[10];
    const float* b2       = (const float*)d_in[11];
    const float* Wd       = (const float*)d_in[12];
    const float* bd       = (const float*)d_in[13];
    const float* Pe       = (const float*)d_in[14];
    const float* K1       = (const float*)d_in[15];
    const float* bk1      = (const float*)d_in[16];
    const float* K2       = (const float*)d_in[17];
    const float* bk2      = (const float*)d_in[18];
    const float* Wp       = (const float*)d_in[19];
    const float* bp       = (const float*)d_in[20];
    const float* Wf1      = (const float*)d_in[21];
    const float* bf1      = (const float*)d_in[22];
    const float* Wf2      = (const float*)d_in[23];
    const float* bf2      = (const float*)d_in[24];
    const float* Wo       = (const float*)d_in[25];
    const float* bo       = (const float*)d_in[26];
    float* out = (float*)d_out;

    cudaFuncSetAttribute(k_gat2_mm,    cudaFuncAttributeMaxDynamicSharedMemorySize, 98304);
    cudaFuncSetAttribute(k_conv2_hmma, cudaFuncAttributeMaxDynamicSharedMemorySize, C2_SMEM);

    const int ET = NE + NN;

    // protein branch
    k_tab<<<17, 256>>>(Pe, K1, bk1);                               // 0
    {
        dim3 grid((LL + 15)/16, NB);
        k_conv1_apply<<<grid, 256>>>(seq);                         // 1
    }
    k_init<<<2048, 256>>>();                                       // 2
    k_conv2_hmma<<<296, 256, C2_SMEM>>>(K2, bk2);                  // 3  <- profile target
    k_prot<<<(NB*64 + 255)/256, 256>>>(Wp, bp);                    // 4

    // drug branch: GAT layer 1
    k_gat1_mm<<<(NN*128 + 255)/256, 256>>>(x, W1);                 // 5
    k_att1<<<(NN*32 + 255)/256, 256>>>(att_s1, att_d1);
    k_edge_den<2><<<(ET + 255)/256, 256>>>(ei);
    k_edge_acc<2><<<(ET*32 + 255)/256, 256>>>(ei);

    // GAT layer 2 (bias1+elu fused into the GEMM A-load)
    k_gat2_mm<<<NN/64, 256, 98304>>>(W2, b1);
    k_att2<<<(NN*32 + 255)/256, 256>>>(att_s2, att_d2);
    k_edge_den<1><<<(ET + 255)/256, 256>>>(ei);
    k_edge_acc<1><<<(ET*32 + 255)/256, 256>>>(ei);

    // pooling (bias2+elu fused) + drug dense
    k_pool<<<(NN*32 + 255)/256, 256>>>(batch, b2);
    k_drug<<<(NG*64 + 255)/256, 256>>>(Wd, bd);

    // head
    k_head<<<NG, 128>>>(Wf1, bf1, Wf2, bf2, Wo, bo, out);
}

// round 13
// speedup vs baseline: 1.8591x; 1.1025x over previous
#include <cuda_runtime.h>
#include <cuda_fp16.h>
#include <cstdint>

#define NN 24576
#define NE 98304
#define NG 512
#define NB 512
#define LL 1000

// ---------------- scratch (device globals; runtime alloc forbidden) ----------------
__device__ float g_h1[NN*128];
__device__ float g_as1[NN*2];
__device__ float g_ad1[NN*2];
__device__ float g_den1[NN*2];
__device__ float g_e1[(NE+NN)*2];
__device__ float g_out1[NN*128];
__device__ float g_h2[NN*128];
__device__ float g_as2[NN];
__device__ float g_ad2[NN];
__device__ float g_den2[NN];
__device__ float g_e2[NE+NN];
__device__ float g_out2[NN*128];
__device__ float g_sums[NG*128];
__device__ float g_cnt[NG];
__device__ float g_drug[NG*256];
__device__ float g_T[3*22*64];
__device__ __half g_p1h[NB*LL*64];   // conv1 output (fp16), [b][l][i]
__device__ float g_pmax[NB*128];
__device__ float g_prot[NB*256];

// ---------------- helpers ----------------
__device__ __forceinline__ void red_add_v4(float* addr, float4 v) {
    asm volatile("red.global.add.v4.f32 [%0], {%1, %2, %3, %4};"
                 :: "l"(addr), "f"(v.x), "f"(v.y), "f"(v.z), "f"(v.w) : "memory");
}
__device__ __forceinline__ void atomicMaxFloat(float* addr, float val) {
    if (val >= 0.f) atomicMax((int*)addr, __float_as_int(val));
    else            atomicMin((unsigned int*)addr, __float_as_uint(val));
}
__device__ __forceinline__ float warp_sum(float v) {
    #pragma unroll
    for (int off = 16; off; off >>= 1) v += __shfl_down_sync(0xffffffffu, v, off);
    return v;
}
__device__ __forceinline__ float elu1(float v) { return v > 0.f ? v : expm1f(v); }

__device__ __forceinline__ void mma_fp16(float* c, const uint32_t* a, const uint32_t* b) {
    asm volatile(
        "mma.sync.aligned.m16n8k16.row.col.f32.f16.f16.f32 "
        "{%0,%1,%2,%3}, {%4,%5,%6,%7}, {%8,%9}, {%0,%1,%2,%3};"
        : "+f"(c[0]), "+f"(c[1]), "+f"(c[2]), "+f"(c[3])
        : "r"(a[0]), "r"(a[1]), "r"(a[2]), "r"(a[3]), "r"(b[0]), "r"(b[1]));
}
__device__ __forceinline__ void ldsm_x4(uint32_t* r, uint32_t addr) {
    asm volatile("ldmatrix.sync.aligned.m8n8.x4.shared.b16 {%0,%1,%2,%3}, [%4];"
                 : "=r"(r[0]), "=r"(r[1]), "=r"(r[2]), "=r"(r[3]) : "r"(addr));
}
__device__ __forceinline__ uint32_t smem_u32(const void* p) {
    uint32_t a;
    asm("{ .reg .u64 t; cvta.to.shared.u64 t, %1; cvt.u32.u64 %0, t; }" : "=r"(a) : "l"(p));
    return a;
}

// ---------------- conv2 via single-term fp16 HMMA, M-split across 2 CTAs/SM ----------------
#define C2_A  0
#define C2_B  9792
#define C2_B_STRIDE 328
#define C2_SMEM 93760
#define C2_WORK (NB*8*2)

__global__ void __launch_bounds__(256) k_conv2_hmma(const float* __restrict__ K2,
                                                    const float* __restrict__ bk2) {
    extern __shared__ char smem[];
    __half* BhS = reinterpret_cast<__half*>(smem + C2_B);

    int tid = threadIdx.x, wid = tid >> 5, lane = tid & 31;
    int g = lane >> 2, q = lane & 3;
    int mw2 = (wid & 1) * 32;
    int nw4 = (wid >> 1) * 32;
    int m_base = (blockIdx.x & 1) * 64;

    uint32_t sb = smem_u32(smem);
    uint32_t sbA = sb + C2_A, sbB = sb + C2_B;

    uint32_t aoff = (uint32_t)(lane & 15) * 144u + ((lane & 16) ? 16u : 0u);
    uint32_t boff = (uint32_t)(lane & 7) * 656u + ((lane & 8) ? 16u : 0u)
                  + ((lane & 16) ? 8u*656u : 0u);

    for (int idx = tid; idx < 128*320; idx += 256) {
        int n = idx / 320, k = idx - n*320;
        int t = k >> 6, i = k & 63;
        BhS[n*C2_B_STRIDE + k] = __float2half_rn(K2[(n*64 + i)*5 + t]);
    }

    float bias[4][2];
    #pragma unroll
    for (int nt = 0; nt < 4; nt++) {
        int col = nw4 + nt*8 + q*2;
        bias[nt][0] = bk2[col];
        bias[nt][1] = bk2[col + 1];
    }

    auto issue_A = [&](int work_) {
        int tile_ = work_ >> 1;
        int b_ = tile_ >> 3;
        int lbase = (tile_ & 7) * 125 + m_base - 2;
        for (int idx = tid; idx < 544; idx += 256) {
            int row = idx >> 3, c = idx & 7;
            int l = lbase + row;
            int lc = l < 0 ? 0 : (l >= LL ? LL-1 : l);
            const __half* gsrc = g_p1h + ((size_t)b_*LL + lc)*64 + c*8;
            uint32_t dst = sbA + (uint32_t)(row*144 + c*16);
            int sz = (l >= 0 && l < LL) ? 16 : 0;
            asm volatile("cp.async.cg.shared.global [%0], [%1], 16, %2;"
                         :: "r"(dst), "l"(gsrc), "r"(sz));
        }
        asm volatile("cp.async.commit_group;" ::: "memory");
    };

    issue_A(blockIdx.x);
    for (int work = blockIdx.x; work < C2_WORK; work += gridDim.x) {
        int tile = work >> 1;
        int b = tile >> 3, l0 = (tile & 7) * 125;
        asm volatile("cp.async.wait_group 0;" ::: "memory");
        __syncthreads();

        float acc[2][4][4];
        #pragma unroll
        for (int mt = 0; mt < 2; mt++)
            #pragma unroll
            for (int nt = 0; nt < 4; nt++)
                #pragma unroll
                for (int j = 0; j < 4; j++) acc[mt][nt][j] = 0.f;

        #pragma unroll
        for (int ks = 0; ks < 20; ks++) {
            int t = ks >> 2;
            uint32_t kb = (uint32_t)((ks & 3) * 32);
            uint32_t ah[2][4], bb[2][4];
            uint32_t aBase = (uint32_t)((mw2 + t) * 144) + kb + aoff;
            #pragma unroll
            for (int mt = 0; mt < 2; mt++)
                ldsm_x4(ah[mt], sbA + aBase + (uint32_t)(mt*16*144));
            uint32_t bBase = (uint32_t)(nw4 * 656) + (uint32_t)(t * 128) + kb + boff;
            #pragma unroll
            for (int np = 0; np < 2; np++)
                ldsm_x4(bb[np], sbB + bBase + (uint32_t)(np*16*656));
            #pragma unroll
            for (int mt = 0; mt < 2; mt++)
                #pragma unroll
                for (int nt = 0; nt < 4; nt++)
                    mma_fp16(acc[mt][nt], ah[mt], &bb[nt >> 1][(nt & 1)*2]);
        }

        __syncthreads();
        if (work + (int)gridDim.x < C2_WORK)
            issue_A(work + gridDim.x);

        float mx[4][2];
        #pragma unroll
        for (int nt = 0; nt < 4; nt++) { mx[nt][0] = -3.0e38f; mx[nt][1] = -3.0e38f; }
        #pragma unroll
        for (int mt = 0; mt < 2; mt++) {
            int lr = l0 + m_base + mw2 + mt*16 + g;
            bool v0 = lr < LL, v1 = (lr + 8) < LL;
            #pragma unroll
            for (int nt = 0; nt < 4; nt++) {
                if (v0) {
                    mx[nt][0] = fmaxf(mx[nt][0], elu1(acc[mt][nt][0] + bias[nt][0]));
                    mx[nt][1] = fmaxf(mx[nt][1], elu1(acc[mt][nt][1] + bias[nt][1]));
                }
                if (v1) {
                    mx[nt][0] = fmaxf(mx[nt][0], elu1(acc[mt][nt][2] + bias[nt][0]));
                    mx[nt][1] = fmaxf(mx[nt][1], elu1(acc[mt][nt][3] + bias[nt][1]));
                }
            }
        }
        #pragma unroll
        for (int nt = 0; nt < 4; nt++) {
            #pragma unroll
            for (int j = 0; j < 2; j++) {
                float v = mx[nt][j];
                v = fmaxf(v, __shfl_xor_sync(0xffffffffu, v, 4));
                v = fmaxf(v, __shfl_xor_sync(0xffffffffu, v, 8));
                v = fmaxf(v, __shfl_xor_sync(0xffffffffu, v, 16));
                if (lane < 4)
                    atomicMaxFloat(&g_pmax[b*128 + nw4 + nt*8 + lane*2 + j], v);
            }
        }
    }
}

// ---------------- conv1 token tables ----------------
__global__ void k_tab(const float* __restrict__ Pe, const float* __restrict__ K1,
                      const float* __restrict__ bk1) {
    int idx = blockIdx.x * blockDim.x + threadIdx.x;
    if (idx >= 3*22*64) return;
    int o = idx & 63, r = idx >> 6;
    int t = r % 22, k = r / 22;
    float acc = (k == 1) ? bk1[o] : 0.f;
    #pragma unroll 8
    for (int i = 0; i < 64; i++) acc += Pe[t*64 + i] * K1[(o*64 + i)*3 + k];
    g_T[idx] = acc;
}

// ---------------- conv1 apply: writes fp16 directly ----------------
__global__ void __launch_bounds__(256) k_conv1_apply(const int* __restrict__ seq) {
    int b = blockIdx.y;
    int lofs = threadIdx.x >> 4, lq = threadIdx.x & 15;
    int l = blockIdx.x * 16 + lofs;
    if (l >= LL) return;
    int s1 = seq[b*LL + l];
    int c = lq * 4;
    float4 v = *reinterpret_cast<const float4*>(&g_T[(22 + s1)*64 + c]);
    if (l > 0) {
        int s0 = seq[b*LL + l - 1];
        float4 a = *reinterpret_cast<const float4*>(&g_T[s0*64 + c]);
        v.x += a.x; v.y += a.y; v.z += a.z; v.w += a.w;
    }
    if (l < LL-1) {
        int s2 = seq[b*LL + l + 1];
        float4 a = *reinterpret_cast<const float4*>(&g_T[(44 + s2)*64 + c]);
        v.x += a.x; v.y += a.y; v.z += a.z; v.w += a.w;
    }
    __half2 h0 = __floats2half2_rn(elu1(v.x), elu1(v.y));
    __half2 h1 = __floats2half2_rn(elu1(v.z), elu1(v.w));
    size_t base = ((size_t)b*LL + l)*64 + c;
    *reinterpret_cast<__half2*>(&g_p1h[base])     = h0;
    *reinterpret_cast<__half2*>(&g_p1h[base + 2]) = h1;
}

// ---------------- init (split per branch) ----------------
__global__ void k_init_prot() {
    int i = blockIdx.x * blockDim.x + threadIdx.x;
    if (i < NB*128) g_pmax[i] = -3.0e38f;
}
__global__ void k_init_drug() {
    int i = blockIdx.x * blockDim.x + threadIdx.x;
    int stride = gridDim.x * blockDim.x;
    for (int idx = i; idx < NN*128; idx += stride) { g_out1[idx] = 0.f; g_out2[idx] = 0.f; }
    for (int idx = i; idx < NN*2; idx += stride) g_den1[idx] = 0.f;
    for (int idx = i; idx < NN; idx += stride) g_den2[idx] = 0.f;
    for (int idx = i; idx < NG*128; idx += stride) g_sums[idx] = 0.f;
    for (int idx = i; idx < NG; idx += stride) g_cnt[idx] = 0.f;
}

// ---------------- GAT1 GEMM ----------------
__global__ void k_gat1_mm(const float* __restrict__ x, const float* __restrict__ W1) {
    int idx = blockIdx.x * blockDim.x + threadIdx.x;
    if (idx >= NN*128) return;
    int n = idx >> 7, c = idx & 127;
    float acc = 0.f;
    #pragma unroll
    for (int f = 0; f < 5; f++) acc += x[n*5 + f] * W1[f*128 + c];
    g_h1[idx] = acc;
}

// attention scalars, 2 heads of 64
__global__ void k_att1(const float* __restrict__ att_s, const float* __restrict__ att_d) {
    int gw = (blockIdx.x * blockDim.x + threadIdx.x) >> 5;
    int lane = threadIdx.x & 31;
    if (gw >= NN) return;
    const float* hr = g_h1 + (size_t)gw * 128;
    float s0 = hr[lane]*att_s[lane] + hr[lane+32]*att_s[lane+32];
    float s1 = hr[lane+64]*att_s[lane+64] + hr[lane+96]*att_s[lane+96];
    float d0 = hr[lane]*att_d[lane] + hr[lane+32]*att_d[lane+32];
    float d1 = hr[lane+64]*att_d[lane+64] + hr[lane+96]*att_d[lane+96];
    s0 = warp_sum(s0); s1 = warp_sum(s1); d0 = warp_sum(d0); d1 = warp_sum(d1);
    if (lane == 0) {
        g_as1[gw*2] = s0; g_as1[gw*2+1] = s1;
        g_ad1[gw*2] = d0; g_ad1[gw*2+1] = d1;
    }
}

// attention scalars, 1 head of 128
__global__ void k_att2(const float* __restrict__ att_s, const float* __restrict__ att_d) {
    int gw = (blockIdx.x * blockDim.x + threadIdx.x) >> 5;
    int lane = threadIdx.x & 31;
    if (gw >= NN) return;
    const float* hr = g_h2 + (size_t)gw * 128;
    float s = 0.f, d = 0.f;
    #pragma unroll
    for (int t = 0; t < 4; t++) {
        int p = lane + 32*t;
        s += hr[p]*att_s[p];
        d += hr[p]*att_d[p];
    }
    s = warp_sum(s); d = warp_sum(d);
    if (lane == 0) { g_as2[gw] = s; g_ad2[gw] = d; }
}

// ---------------- edge passes (softmax without max-shift: scores are O(1)) ----------------
template<int H>
__global__ void k_edge_den(const int* __restrict__ ei) {
    int e = blockIdx.x * blockDim.x + threadIdx.x;
    const int ET = NE + NN;
    if (e >= ET) return;
    int src, dst;
    if (e < NE) { src = ei[e]; dst = ei[NE + e]; } else { src = dst = e - NE; }
    const float* as_ = (H == 2) ? g_as1 : g_as2;
    const float* ad_ = (H == 2) ? g_ad1 : g_ad2;
    float* den_ = (H == 2) ? g_den1 : g_den2;
    float* e_ = (H == 2) ? g_e1 : g_e2;
    #pragma unroll
    for (int h = 0; h < H; h++) {
        float v = as_[src*H+h] + ad_[dst*H+h];
        v = v > 0.f ? v : 0.2f * v;
        float w = expf(v);
        e_[e*H+h] = w;
        atomicAdd(&den_[dst*H+h], w);
    }
}

template<int H>
__global__ void k_edge_acc(const int* __restrict__ ei) {
    int gw = (blockIdx.x * blockDim.x + threadIdx.x) >> 5;
    int lane = threadIdx.x & 31;
    const int ET = NE + NN;
    if (gw >= ET) return;
    int src, dst;
    if (gw < NE) { src = ei[gw]; dst = ei[NE + gw]; } else { src = dst = gw - NE; }
    const float* den_ = (H == 2) ? g_den1 : g_den2;
    const float* e_ = (H == 2) ? g_e1 : g_e2;
    const float* hin = (H == 2) ? g_h1 : g_h2;
    float* outp = (H == 2) ? g_out1 : g_out2;
    int h = (H == 2 && lane >= 16) ? 1 : 0;
    float alpha = e_[gw*H + h] / (den_[dst*H + h] + 1e-16f);
    float4 v = *reinterpret_cast<const float4*>(&hin[(size_t)src*128 + lane*4]);
    v.x *= alpha; v.y *= alpha; v.z *= alpha; v.w *= alpha;
    red_add_v4(&outp[(size_t)dst*128 + lane*4], v);
}

// ---------------- GAT2 GEMM (bias1+elu fused on A-load) ----------------
__global__ void __launch_bounds__(256) k_gat2_mm(const float* __restrict__ W2,
                                                 const float* __restrict__ b1) {
    extern __shared__ float sm[];
    float* sg = sm;
    float* sw = sm + 64*128;
    int base = blockIdx.x * 64;
    int tid = threadIdx.x;
    for (int idx = tid; idx < 64*128; idx += 256)
        sg[idx] = elu1(g_out1[(size_t)base*128 + idx] + b1[idx & 127]);
    for (int idx = tid; idx < 128*128; idx += 256) sw[idx] = W2[idx];
    __syncthreads();
    int r0 = (tid >> 4) << 2;
    int c0 = (tid & 15) << 3;
    float acc[4][8];
    #pragma unroll
    for (int i = 0; i < 4; i++)
        #pragma unroll
        for (int j = 0; j < 8; j++) acc[i][j] = 0.f;
    #pragma unroll 4
    for (int k = 0; k < 128; k++) {
        float a[4];
        #pragma unroll
        for (int i = 0; i < 4; i++) a[i] = sg[(r0+i)*128 + k];
        float4 b0 = *reinterpret_cast<const float4*>(&sw[k*128 + c0]);
        float4 b1v = *reinterpret_cast<const float4*>(&sw[k*128 + c0 + 4]);
        #pragma unroll
        for (int i = 0; i < 4; i++) {
            acc[i][0] += a[i]*b0.x; acc[i][1] += a[i]*b0.y;
            acc[i][2] += a[i]*b0.z; acc[i][3] += a[i]*b0.w;
            acc[i][4] += a[i]*b1v.x; acc[i][5] += a[i]*b1v.y;
            acc[i][6] += a[i]*b1v.z; acc[i][7] += a[i]*b1v.w;
        }
    }
    #pragma unroll
    for (int i = 0; i < 4; i++) {
        float4 v0 = make_float4(acc[i][0], acc[i][1], acc[i][2], acc[i][3]);
        float4 v1 = make_float4(acc[i][4], acc[i][5], acc[i][6], acc[i][7]);
        *reinterpret_cast<float4*>(&g_h2[(size_t)(base+r0+i)*128 + c0]) = v0;
        *reinterpret_cast<float4*>(&g_h2[(size_t)(base+r0+i)*128 + c0 + 4]) = v1;
    }
}

// ---------------- pooling (bias2+elu fused) + dense ----------------
__global__ void k_pool(const int* __restrict__ batch, const float* __restrict__ b2) {
    int gw = (blockIdx.x * blockDim.x + threadIdx.x) >> 5;
    int lane = threadIdx.x & 31;
    if (gw >= NN) return;
    int g = batch[gw];
    int c = lane * 4;
    float4 v = *reinterpret_cast<const float4*>(&g_out2[(size_t)gw*128 + c]);
    v.x = elu1(v.x + b2[c]);
    v.y = elu1(v.y + b2[c+1]);
    v.z = elu1(v.z + b2[c+2]);
    v.w = elu1(v.w + b2[c+3]);
    red_add_v4(&g_sums[g*128 + c], v);
    if (lane == 0) atomicAdd(&g_cnt[g], 1.0f);
}

__global__ void k_drug(const float* __restrict__ Wd, const float* __restrict__ bd) {
    int idx = blockIdx.x * blockDim.x + threadIdx.x;
    if (idx >= NG*64) return;
    int g = idx >> 6, j4 = (idx & 63) * 4;
    float invc = 1.f / fmaxf(g_cnt[g], 1.f);
    const float* srow = g_sums + g*128;
    float4 a = make_float4(0.f, 0.f, 0.f, 0.f);
    #pragma unroll 8
    for (int k = 0; k < 128; k++) {
        float s = srow[k];
        float4 w = *reinterpret_cast<const float4*>(&Wd[k*256 + j4]);
        a.x += s*w.x; a.y += s*w.y; a.z += s*w.z; a.w += s*w.w;
    }
    float4 r;
    r.x = fmaxf(a.x * invc + bd[j4],     0.f);
    r.y = fmaxf(a.y * invc + bd[j4 + 1], 0.f);
    r.z = fmaxf(a.z * invc + bd[j4 + 2], 0.f);
    r.w = fmaxf(a.w * invc + bd[j4 + 3], 0.f);
    *reinterpret_cast<float4*>(&g_drug[g*256 + j4]) = r;
}

__global__ void k_prot(const float* __restrict__ Wp, const float* __restrict__ bp) {
    int idx = blockIdx.x * blockDim.x + threadIdx.x;
    if (idx >= NB*64) return;
    int g = idx >> 6, j4 = (idx & 63) * 4;
    const float* srow = g_pmax + g*128;
    float4 a = make_float4(0.f, 0.f, 0.f, 0.f);
    #pragma unroll 8
    for (int k = 0; k < 128; k++) {
        float s = srow[k];
        float4 w = *reinterpret_cast<const float4*>(&Wp[k*256 + j4]);
        a.x += s*w.x; a.y += s*w.y; a.z += s*w.z; a.w += s*w.w;
    }
    float4 r;
    r.x = fmaxf(a.x + bp[j4],     0.f);
    r.y = fmaxf(a.y + bp[j4 + 1], 0.f);
    r.z = fmaxf(a.z + bp[j4 + 2], 0.f);
    r.w = fmaxf(a.w + bp[j4 + 3], 0.f);
    *reinterpret_cast<float4*>(&g_prot[g*256 + j4]) = r;
}

// ---------------- head MLP ----------------
__global__ void __launch_bounds__(128) k_head(const float* __restrict__ Wf1, const float* __restrict__ bf1,
                                              const float* __restrict__ Wf2, const float* __restrict__ bf2,
                                              const float* __restrict__ Wo, const float* __restrict__ bo,
                                              float* __restrict__ out) {
    __shared__ float sh[512];
    __shared__ float s1[128];
    __shared__ float s2[64];
    int g = blockIdx.x, tid = threadIdx.x;
    for (int i = tid; i < 256; i += 128) {
        sh[i]       = g_drug[g*256 + i];
        sh[256 + i] = g_prot[g*256 + i];
    }
    __syncthreads();
    float acc = 0.f;
    #pragma unroll 8
    for (int k = 0; k < 512; k++) acc += sh[k] * Wf1[k*128 + tid];
    s1[tid] = fmaxf(acc + bf1[tid], 0.f);
    __syncthreads();
    if (tid < 64) {
        float a = 0.f;
        #pragma unroll 8
        for (int k = 0; k < 128; k++) a += s1[k] * Wf2[k*64 + tid];
        s2[tid] = fmaxf(a + bf2[tid], 0.f);
    }
    __syncthreads();
    if (tid < 32) {
        float a = s2[tid]*Wo[tid] + s2[tid+32]*Wo[tid+32];
        a = warp_sum(a);
        if (tid == 0) out[g] = a + bo[0];
    }
}

// ---------------- launch: protein branch forked onto a side stream ----------------
extern "C" void kernel_launch(void* const* d_in, const int* in_sizes, int n_in,
                              void* d_out, int out_size) {
    const float* x        = (const float*)d_in[0];
    const int*   ei       = (const int*)d_in[1];
    const int*   batch    = (const int*)d_in[2];
    const int*   seq      = (const int*)d_in[3];
    const float* W1       = (const float*)d_in[4];
    const float* att_s1   = (const float*)d_in[5];
    const float* att_d1   = (const float*)d_in[6];
    const float* b1       = (const float*)d_in[7];
    const float* W2       = (const float*)d_in[8];
    const float* att_s2   = (const float*)d_in[9];
    const float* att_d2   = (const float*)d_in[10];
    const float* b2       = (const float*)d_in[11];
    const float* Wd       = (const float*)d_in[12];
    const float* bd       = (const float*)d_in[13];
    const float* Pe       = (const float*)d_in[14];
    const float* K1       = (const float*)d_in[15];
    const float* bk1      = (const float*)d_in[16];
    const float* K2       = (const float*)d_in[17];
    const float* bk2      = (const float*)d_in[18];
    const float* Wp       = (const float*)d_in[19];
    const float* bp       = (const float*)d_in[20];
    const float* Wf1      = (const float*)d_in[21];
    const float* bf1      = (const float*)d_in[22];
    const float* Wf2      = (const float*)d_in[23];
    const float* bf2      = (const float*)d_in[24];
    const float* Wo       = (const float*)d_in[25];
    const float* bo       = (const float*)d_in[26];
    float* out = (float*)d_out;

    cudaFuncSetAttribute(k_gat2_mm,    cudaFuncAttributeMaxDynamicSharedMemorySize, 98304);
    cudaFuncSetAttribute(k_conv2_hmma, cudaFuncAttributeMaxDynamicSharedMemorySize, C2_SMEM);

    const int ET = NE + NN;

    cudaStream_t sp;
    cudaStreamCreateWithFlags(&sp, cudaStreamNonBlocking);
    cudaEvent_t e0, ep;
    cudaEventCreateWithFlags(&e0, cudaEventDisableTiming);
    cudaEventCreateWithFlags(&ep, cudaEventDisableTiming);

    // fork: side stream joins the capture via event dependency
    cudaEventRecord(e0, 0);
    cudaStreamWaitEvent(sp, e0, 0);

    // ---- protein branch on sp ----
    k_init_prot<<<(NB*128 + 255)/256, 256, 0, sp>>>();
    k_tab<<<17, 256, 0, sp>>>(Pe, K1, bk1);
    {
        dim3 grid((LL + 15)/16, NB);
        k_conv1_apply<<<grid, 256, 0, sp>>>(seq);
    }
    k_conv2_hmma<<<296, 256, C2_SMEM, sp>>>(K2, bk2);
    k_prot<<<(NB*64 + 255)/256, 256, 0, sp>>>(Wp, bp);
    cudaEventRecord(ep, sp);

    // ---- drug branch on the default (capture) stream ----
    k_init_drug<<<2048, 256>>>();
    k_gat1_mm<<<(NN*128 + 255)/256, 256>>>(x, W1);
    k_att1<<<(NN*32 + 255)/256, 256>>>(att_s1, att_d1);
    k_edge_den<2><<<(ET + 255)/256, 256>>>(ei);
    k_edge_acc<2><<<(ET*32 + 255)/256, 256>>>(ei);
    k_gat2_mm<<<NN/64, 256, 98304>>>(W2, b1);
    k_att2<<<(NN*32 + 255)/256, 256>>>(att_s2, att_d2);
    k_edge_den<1><<<(ET + 255)/256, 256>>>(ei);
    k_edge_acc<1><<<(ET*32 + 255)/256, 256>>>(ei);
    k_pool<<<(NN*32 + 255)/256, 256>>>(batch, b2);
    k_drug<<<(NG*64 + 255)/256, 256>>>(Wd, bd);

    // join: head needs both branches
    cudaStreamWaitEvent(0, ep, 0);
    k_head<<<NG, 128>>>(Wf1, bf1, Wf2, bf2, Wo, bo, out);
}

// round 14
// speedup vs baseline: 2.2284x; 1.1986x over previous
#include <cuda_runtime.h>
#include <cuda_fp16.h>
#include <cstdint>

#define NN 24576
#define NE 98304
#define NG 512
#define NB 512
#define LL 1000

// ---------------- scratch (device globals; runtime alloc forbidden) ----------------
__device__ float g_h1[NN*128];
__device__ float g_as1[NN*2];
__device__ float g_ad1[NN*2];
__device__ float g_den1[NN*2];
__device__ float g_e1[(NE+NN)*2];
__device__ float g_out1[NN*128];
__device__ float g_h2[NN*128];
__device__ float g_as2[NN];
__device__ float g_ad2[NN];
__device__ float g_den2[NN];
__device__ float g_e2[NE+NN];
__device__ float g_out2[NN*128];
__device__ float g_sums[NG*128];
__device__ float g_cnt[NG];
__device__ float g_drug[NG*256];
__device__ float g_T[3*22*64];
__device__ __half g_p1h[NB*LL*64];   // conv1 output (fp16), [b][l][i]
__device__ float g_pmax[NB*128];
__device__ float g_prot[NB*256];

// ---------------- helpers ----------------
__device__ __forceinline__ void red_add_v4(float* addr, float4 v) {
    asm volatile("red.global.add.v4.f32 [%0], {%1, %2, %3, %4};"
                 :: "l"(addr), "f"(v.x), "f"(v.y), "f"(v.z), "f"(v.w) : "memory");
}
__device__ __forceinline__ void atomicMaxFloat(float* addr, float val) {
    if (val >= 0.f) atomicMax((int*)addr, __float_as_int(val));
    else            atomicMin((unsigned int*)addr, __float_as_uint(val));
}
__device__ __forceinline__ float warp_sum(float v) {
    #pragma unroll
    for (int off = 16; off; off >>= 1) v += __shfl_down_sync(0xffffffffu, v, off);
    return v;
}
__device__ __forceinline__ float elu1(float v) { return v > 0.f ? v : expm1f(v); }

__device__ __forceinline__ void mma_fp16(float* c, const uint32_t* a, const uint32_t* b) {
    asm volatile(
        "mma.sync.aligned.m16n8k16.row.col.f32.f16.f16.f32 "
        "{%0,%1,%2,%3}, {%4,%5,%6,%7}, {%8,%9}, {%0,%1,%2,%3};"
        : "+f"(c[0]), "+f"(c[1]), "+f"(c[2]), "+f"(c[3])
        : "r"(a[0]), "r"(a[1]), "r"(a[2]), "r"(a[3]), "r"(b[0]), "r"(b[1]));
}
__device__ __forceinline__ void ldsm_x4(uint32_t* r, uint32_t addr) {
    asm volatile("ldmatrix.sync.aligned.m8n8.x4.shared.b16 {%0,%1,%2,%3}, [%4];"
                 : "=r"(r[0]), "=r"(r[1]), "=r"(r[2]), "=r"(r[3]) : "r"(addr));
}
__device__ __forceinline__ uint32_t smem_u32(const void* p) {
    uint32_t a;
    asm("{ .reg .u64 t; cvta.to.shared.u64 t, %1; cvt.u32.u64 %0, t; }" : "=r"(a) : "l"(p));
    return a;
}

// ---------------- conv2 via single-term fp16 HMMA, M-split across 2 CTAs/SM ----------------
#define C2_A  0
#define C2_B  9792
#define C2_B_STRIDE 328
#define C2_SMEM 93760
#define C2_WORK (NB*8*2)

__global__ void __launch_bounds__(256) k_conv2_hmma(const float* __restrict__ K2,
                                                    const float* __restrict__ bk2) {
    extern __shared__ char smem[];
    __half* BhS = reinterpret_cast<__half*>(smem + C2_B);

    int tid = threadIdx.x, wid = tid >> 5, lane = tid & 31;
    int g = lane >> 2, q = lane & 3;
    int mw2 = (wid & 1) * 32;
    int nw4 = (wid >> 1) * 32;
    int m_base = (blockIdx.x & 1) * 64;

    uint32_t sb = smem_u32(smem);
    uint32_t sbA = sb + C2_A, sbB = sb + C2_B;

    uint32_t aoff = (uint32_t)(lane & 15) * 144u + ((lane & 16) ? 16u : 0u);
    uint32_t boff = (uint32_t)(lane & 7) * 656u + ((lane & 8) ? 16u : 0u)
                  + ((lane & 16) ? 8u*656u : 0u);

    for (int idx = tid; idx < 128*320; idx += 256) {
        int n = idx / 320, k = idx - n*320;
        int t = k >> 6, i = k & 63;
        BhS[n*C2_B_STRIDE + k] = __float2half_rn(K2[(n*64 + i)*5 + t]);
    }

    float bias[4][2];
    #pragma unroll
    for (int nt = 0; nt < 4; nt++) {
        int col = nw4 + nt*8 + q*2;
        bias[nt][0] = bk2[col];
        bias[nt][1] = bk2[col + 1];
    }

    auto issue_A = [&](int work_) {
        int tile_ = work_ >> 1;
        int b_ = tile_ >> 3;
        int lbase = (tile_ & 7) * 125 + m_base - 2;
        for (int idx = tid; idx < 544; idx += 256) {
            int row = idx >> 3, c = idx & 7;
            int l = lbase + row;
            int lc = l < 0 ? 0 : (l >= LL ? LL-1 : l);
            const __half* gsrc = g_p1h + ((size_t)b_*LL + lc)*64 + c*8;
            uint32_t dst = sbA + (uint32_t)(row*144 + c*16);
            int sz = (l >= 0 && l < LL) ? 16 : 0;
            asm volatile("cp.async.cg.shared.global [%0], [%1], 16, %2;"
                         :: "r"(dst), "l"(gsrc), "r"(sz));
        }
        asm volatile("cp.async.commit_group;" ::: "memory");
    };

    issue_A(blockIdx.x);
    for (int work = blockIdx.x; work < C2_WORK; work += gridDim.x) {
        int tile = work >> 1;
        int b = tile >> 3, l0 = (tile & 7) * 125;
        asm volatile("cp.async.wait_group 0;" ::: "memory");
        __syncthreads();

        float acc[2][4][4];
        #pragma unroll
        for (int mt = 0; mt < 2; mt++)
            #pragma unroll
            for (int nt = 0; nt < 4; nt++)
                #pragma unroll
                for (int j = 0; j < 4; j++) acc[mt][nt][j] = 0.f;

        #pragma unroll
        for (int ks = 0; ks < 20; ks++) {
            int t = ks >> 2;
            uint32_t kb = (uint32_t)((ks & 3) * 32);
            uint32_t ah[2][4], bb[2][4];
            uint32_t aBase = (uint32_t)((mw2 + t) * 144) + kb + aoff;
            #pragma unroll
            for (int mt = 0; mt < 2; mt++)
                ldsm_x4(ah[mt], sbA + aBase + (uint32_t)(mt*16*144));
            uint32_t bBase = (uint32_t)(nw4 * 656) + (uint32_t)(t * 128) + kb + boff;
            #pragma unroll
            for (int np = 0; np < 2; np++)
                ldsm_x4(bb[np], sbB + bBase + (uint32_t)(np*16*656));
            #pragma unroll
            for (int mt = 0; mt < 2; mt++)
                #pragma unroll
                for (int nt = 0; nt < 4; nt++)
                    mma_fp16(acc[mt][nt], ah[mt], &bb[nt >> 1][(nt & 1)*2]);
        }

        __syncthreads();
        if (work + (int)gridDim.x < C2_WORK)
            issue_A(work + gridDim.x);

        // ---- epilogue: RAW max over valid l, then elu(max + bias) once (elu monotonic) ----
        float mx[4][2];
        #pragma unroll
        for (int nt = 0; nt < 4; nt++) { mx[nt][0] = -3.0e38f; mx[nt][1] = -3.0e38f; }
        #pragma unroll
        for (int mt = 0; mt < 2; mt++) {
            int lr = l0 + m_base + mw2 + mt*16 + g;
            bool v0 = lr < LL, v1 = (lr + 8) < LL;
            #pragma unroll
            for (int nt = 0; nt < 4; nt++) {
                if (v0) {
                    mx[nt][0] = fmaxf(mx[nt][0], acc[mt][nt][0]);
                    mx[nt][1] = fmaxf(mx[nt][1], acc[mt][nt][1]);
                }
                if (v1) {
                    mx[nt][0] = fmaxf(mx[nt][0], acc[mt][nt][2]);
                    mx[nt][1] = fmaxf(mx[nt][1], acc[mt][nt][3]);
                }
            }
        }
        #pragma unroll
        for (int nt = 0; nt < 4; nt++) {
            #pragma unroll
            for (int j = 0; j < 2; j++) {
                float v = mx[nt][j];
                v = fmaxf(v, __shfl_xor_sync(0xffffffffu, v, 4));
                v = fmaxf(v, __shfl_xor_sync(0xffffffffu, v, 8));
                v = fmaxf(v, __shfl_xor_sync(0xffffffffu, v, 16));
                if (lane < 4)
                    atomicMaxFloat(&g_pmax[b*128 + nw4 + nt*8 + lane*2 + j],
                                   elu1(v + bias[nt][j]));
            }
        }
    }
}

// ---------------- conv1 token tables ----------------
__global__ void k_tab(const float* __restrict__ Pe, const float* __restrict__ K1,
                      const float* __restrict__ bk1) {
    int idx = blockIdx.x * blockDim.x + threadIdx.x;
    if (idx >= 3*22*64) return;
    int o = idx & 63, r = idx >> 6;
    int t = r % 22, k = r / 22;
    float acc = (k == 1) ? bk1[o] : 0.f;
    #pragma unroll 8
    for (int i = 0; i < 64; i++) acc += Pe[t*64 + i] * K1[(o*64 + i)*3 + k];
    g_T[idx] = acc;
}

// ---------------- conv1 apply: writes fp16 directly ----------------
__global__ void __launch_bounds__(256) k_conv1_apply(const int* __restrict__ seq) {
    int b = blockIdx.y;
    int lofs = threadIdx.x >> 4, lq = threadIdx.x & 15;
    int l = blockIdx.x * 16 + lofs;
    if (l >= LL) return;
    int s1 = seq[b*LL + l];
    int c = lq * 4;
    float4 v = *reinterpret_cast<const float4*>(&g_T[(22 + s1)*64 + c]);
    if (l > 0) {
        int s0 = seq[b*LL + l - 1];
        float4 a = *reinterpret_cast<const float4*>(&g_T[s0*64 + c]);
        v.x += a.x; v.y += a.y; v.z += a.z; v.w += a.w;
    }
    if (l < LL-1) {
        int s2 = seq[b*LL + l + 1];
        float4 a = *reinterpret_cast<const float4*>(&g_T[(44 + s2)*64 + c]);
        v.x += a.x; v.y += a.y; v.z += a.z; v.w += a.w;
    }
    __half2 h0 = __floats2half2_rn(elu1(v.x), elu1(v.y));
    __half2 h1 = __floats2half2_rn(elu1(v.z), elu1(v.w));
    size_t base = ((size_t)b*LL + l)*64 + c;
    *reinterpret_cast<__half2*>(&g_p1h[base])     = h0;
    *reinterpret_cast<__half2*>(&g_p1h[base + 2]) = h1;
}

// ---------------- init (split per branch) ----------------
__global__ void k_init_prot() {
    int i = blockIdx.x * blockDim.x + threadIdx.x;
    if (i < NB*128) g_pmax[i] = -3.0e38f;
}
__global__ void k_init_drug() {
    int i = blockIdx.x * blockDim.x + threadIdx.x;
    int stride = gridDim.x * blockDim.x;
    for (int idx = i; idx < NN*128; idx += stride) { g_out1[idx] = 0.f; g_out2[idx] = 0.f; }
    for (int idx = i; idx < NN*2; idx += stride) g_den1[idx] = 0.f;
    for (int idx = i; idx < NN; idx += stride) g_den2[idx] = 0.f;
    for (int idx = i; idx < NG*128; idx += stride) g_sums[idx] = 0.f;
    for (int idx = i; idx < NG; idx += stride) g_cnt[idx] = 0.f;
}

// ---------------- GAT1 GEMM + fused attention scalars (warp per node) ----------------
__global__ void k_gat1(const float* __restrict__ x, const float* __restrict__ W1,
                       const float* __restrict__ att_s, const float* __restrict__ att_d) {
    int gw = (blockIdx.x * blockDim.x + threadIdx.x) >> 5;
    int lane = threadIdx.x & 31;
    if (gw >= NN) return;
    float xv[5];
    #pragma unroll
    for (int f = 0; f < 5; f++) xv[f] = x[gw*5 + f];
    int c = lane * 4;
    float4 h;
    float* hp = reinterpret_cast<float*>(&h);
    #pragma unroll
    for (int j = 0; j < 4; j++) {
        float a = 0.f;
        #pragma unroll
        for (int f = 0; f < 5; f++) a += xv[f] * W1[f*128 + c + j];
        hp[j] = a;
    }
    *reinterpret_cast<float4*>(&g_h1[(size_t)gw*128 + c]) = h;
    float s = 0.f, d = 0.f;
    #pragma unroll
    for (int j = 0; j < 4; j++) { s += hp[j]*att_s[c + j]; d += hp[j]*att_d[c + j]; }
    float s0 = (lane < 16) ? s : 0.f, s1 = (lane < 16) ? 0.f : s;
    float d0 = (lane < 16) ? d : 0.f, d1 = (lane < 16) ? 0.f : d;
    s0 = warp_sum(s0); s1 = warp_sum(s1); d0 = warp_sum(d0); d1 = warp_sum(d1);
    if (lane == 0) {
        g_as1[gw*2] = s0; g_as1[gw*2+1] = s1;
        g_ad1[gw*2] = d0; g_ad1[gw*2+1] = d1;
    }
}

// ---------------- edge passes (softmax without max-shift: scores are O(1)) ----------------
template<int H>
__global__ void k_edge_den(const int* __restrict__ ei) {
    int e = blockIdx.x * blockDim.x + threadIdx.x;
    const int ET = NE + NN;
    if (e >= ET) return;
    int src, dst;
    if (e < NE) { src = ei[e]; dst = ei[NE + e]; } else { src = dst = e - NE; }
    const float* as_ = (H == 2) ? g_as1 : g_as2;
    const float* ad_ = (H == 2) ? g_ad1 : g_ad2;
    float* den_ = (H == 2) ? g_den1 : g_den2;
    float* e_ = (H == 2) ? g_e1 : g_e2;
    #pragma unroll
    for (int h = 0; h < H; h++) {
        float v = as_[src*H+h] + ad_[dst*H+h];
        v = v > 0.f ? v : 0.2f * v;
        float w = expf(v);
        e_[e*H+h] = w;
        atomicAdd(&den_[dst*H+h], w);
    }
}

template<int H>
__global__ void k_edge_acc(const int* __restrict__ ei) {
    int gw = (blockIdx.x * blockDim.x + threadIdx.x) >> 5;
    int lane = threadIdx.x & 31;
    const int ET = NE + NN;
    if (gw >= ET) return;
    int src, dst;
    if (gw < NE) { src = ei[gw]; dst = ei[NE + gw]; } else { src = dst = gw - NE; }
    const float* den_ = (H == 2) ? g_den1 : g_den2;
    const float* e_ = (H == 2) ? g_e1 : g_e2;
    const float* hin = (H == 2) ? g_h1 : g_h2;
    float* outp = (H == 2) ? g_out1 : g_out2;
    int h = (H == 2 && lane >= 16) ? 1 : 0;
    float alpha = e_[gw*H + h] / (den_[dst*H + h] + 1e-16f);
    float4 v = *reinterpret_cast<const float4*>(&hin[(size_t)src*128 + lane*4]);
    v.x *= alpha; v.y *= alpha; v.z *= alpha; v.w *= alpha;
    red_add_v4(&outp[(size_t)dst*128 + lane*4], v);
}

// ---------------- GAT2 GEMM (bias1+elu fused on A-load; att2 fused in epilogue) ----------------
__global__ void __launch_bounds__(256) k_gat2_mm(const float* __restrict__ W2,
                                                 const float* __restrict__ b1,
                                                 const float* __restrict__ att_s,
                                                 const float* __restrict__ att_d) {
    extern __shared__ float sm[];
    float* sg = sm;
    float* sw = sm + 64*128;
    int base = blockIdx.x * 64;
    int tid = threadIdx.x;
    for (int idx = tid; idx < 64*128; idx += 256)
        sg[idx] = elu1(g_out1[(size_t)base*128 + idx] + b1[idx & 127]);
    for (int idx = tid; idx < 128*128; idx += 256) sw[idx] = W2[idx];
    __syncthreads();
    int r0 = (tid >> 4) << 2;
    int c0 = (tid & 15) << 3;
    float acc[4][8];
    #pragma unroll
    for (int i = 0; i < 4; i++)
        #pragma unroll
        for (int j = 0; j < 8; j++) acc[i][j] = 0.f;
    #pragma unroll 4
    for (int k = 0; k < 128; k++) {
        float a[4];
        #pragma unroll
        for (int i = 0; i < 4; i++) a[i] = sg[(r0+i)*128 + k];
        float4 b0 = *reinterpret_cast<const float4*>(&sw[k*128 + c0]);
        float4 b1v = *reinterpret_cast<const float4*>(&sw[k*128 + c0 + 4]);
        #pragma unroll
        for (int i = 0; i < 4; i++) {
            acc[i][0] += a[i]*b0.x; acc[i][1] += a[i]*b0.y;
            acc[i][2] += a[i]*b0.z; acc[i][3] += a[i]*b0.w;
            acc[i][4] += a[i]*b1v.x; acc[i][5] += a[i]*b1v.y;
            acc[i][6] += a[i]*b1v.z; acc[i][7] += a[i]*b1v.w;
        }
    }
    #pragma unroll
    for (int i = 0; i < 4; i++) {
        float4 v0 = make_float4(acc[i][0], acc[i][1], acc[i][2], acc[i][3]);
        float4 v1 = make_float4(acc[i][4], acc[i][5], acc[i][6], acc[i][7]);
        *reinterpret_cast<float4*>(&g_h2[(size_t)(base+r0+i)*128 + c0]) = v0;
        *reinterpret_cast<float4*>(&g_h2[(size_t)(base+r0+i)*128 + c0 + 4]) = v1;
    }
    // fused att2: per-row dots, reduced across the 16 threads covering the row
    float ps[4], pd[4];
    #pragma unroll
    for (int i = 0; i < 4; i++) {
        float s = 0.f, d = 0.f;
        #pragma unroll
        for (int j = 0; j < 8; j++) {
            float as_ = att_s[c0 + j], ad_ = att_d[c0 + j];
            s += acc[i][j] * as_;
            d += acc[i][j] * ad_;
        }
        ps[i] = s; pd[i] = d;
    }
    #pragma unroll
    for (int i = 0; i < 4; i++) {
        #pragma unroll
        for (int off = 8; off; off >>= 1) {
            ps[i] += __shfl_down_sync(0xffffffffu, ps[i], off, 16);
            pd[i] += __shfl_down_sync(0xffffffffu, pd[i], off, 16);
        }
    }
    if ((tid & 15) == 0) {
        #pragma unroll
        for (int i = 0; i < 4; i++) {
            g_as2[base + r0 + i] = ps[i];
            g_ad2[base + r0 + i] = pd[i];
        }
    }
}

// ---------------- pooling (bias2+elu fused) + dense ----------------
__global__ void k_pool(const int* __restrict__ batch, const float* __restrict__ b2) {
    int gw = (blockIdx.x * blockDim.x + threadIdx.x) >> 5;
    int lane = threadIdx.x & 31;
    if (gw >= NN) return;
    int g = batch[gw];
    int c = lane * 4;
    float4 v = *reinterpret_cast<const float4*>(&g_out2[(size_t)gw*128 + c]);
    v.x = elu1(v.x + b2[c]);
    v.y = elu1(v.y + b2[c+1]);
    v.z = elu1(v.z + b2[c+2]);
    v.w = elu1(v.w + b2[c+3]);
    red_add_v4(&g_sums[g*128 + c], v);
    if (lane == 0) atomicAdd(&g_cnt[g], 1.0f);
}

__global__ void k_drug(const float* __restrict__ Wd, const float* __restrict__ bd) {
    int idx = blockIdx.x * blockDim.x + threadIdx.x;
    if (idx >= NG*64) return;
    int g = idx >> 6, j4 = (idx & 63) * 4;
    float invc = 1.f / fmaxf(g_cnt[g], 1.f);
    const float* srow = g_sums + g*128;
    float4 a = make_float4(0.f, 0.f, 0.f, 0.f);
    #pragma unroll 8
    for (int k = 0; k < 128; k++) {
        float s = srow[k];
        float4 w = *reinterpret_cast<const float4*>(&Wd[k*256 + j4]);
        a.x += s*w.x; a.y += s*w.y; a.z += s*w.z; a.w += s*w.w;
    }
    float4 r;
    r.x = fmaxf(a.x * invc + bd[j4],     0.f);
    r.y = fmaxf(a.y * invc + bd[j4 + 1], 0.f);
    r.z = fmaxf(a.z * invc + bd[j4 + 2], 0.f);
    r.w = fmaxf(a.w * invc + bd[j4 + 3], 0.f);
    *reinterpret_cast<float4*>(&g_drug[g*256 + j4]) = r;
}

__global__ void k_prot(const float* __restrict__ Wp, const float* __restrict__ bp) {
    int idx = blockIdx.x * blockDim.x + threadIdx.x;
    if (idx >= NB*64) return;
    int g = idx >> 6, j4 = (idx & 63) * 4;
    const float* srow = g_pmax + g*128;
    float4 a = make_float4(0.f, 0.f, 0.f, 0.f);
    #pragma unroll 8
    for (int k = 0; k < 128; k++) {
        float s = srow[k];
        float4 w = *reinterpret_cast<const float4*>(&Wp[k*256 + j4]);
        a.x += s*w.x; a.y += s*w.y; a.z += s*w.z; a.w += s*w.w;
    }
    float4 r;
    r.x = fmaxf(a.x + bp[j4],     0.f);
    r.y = fmaxf(a.y + bp[j4 + 1], 0.f);
    r.z = fmaxf(a.z + bp[j4 + 2], 0.f);
    r.w = fmaxf(a.w + bp[j4 + 3], 0.f);
    *reinterpret_cast<float4*>(&g_prot[g*256 + j4]) = r;
}

// ---------------- head MLP ----------------
__global__ void __launch_bounds__(128) k_head(const float* __restrict__ Wf1, const float* __restrict__ bf1,
                                              const float* __restrict__ Wf2, const float* __restrict__ bf2,
                                              const float* __restrict__ Wo, const float* __restrict__ bo,
                                              float* __restrict__ out) {
    __shared__ float sh[512];
    __shared__ float s1[128];
    __shared__ float s2[64];
    int g = blockIdx.x, tid = threadIdx.x;
    for (int i = tid; i < 256; i += 128) {
        sh[i]       = g_drug[g*256 + i];
        sh[256 + i] = g_prot[g*256 + i];
    }
    __syncthreads();
    float acc = 0.f;
    #pragma unroll 8
    for (int k = 0; k < 512; k++) acc += sh[k] * Wf1[k*128 + tid];
    s1[tid] = fmaxf(acc + bf1[tid], 0.f);
    __syncthreads();
    if (tid < 64) {
        float a = 0.f;
        #pragma unroll 8
        for (int k = 0; k < 128; k++) a += s1[k] * Wf2[k*64 + tid];
        s2[tid] = fmaxf(a + bf2[tid], 0.f);
    }
    __syncthreads();
    if (tid < 32) {
        float a = s2[tid]*Wo[tid] + s2[tid+32]*Wo[tid+32];
        a = warp_sum(a);
        if (tid == 0) out[g] = a + bo[0];
    }
}

// ---------------- launch: protein branch forked onto a side stream ----------------
extern "C" void kernel_launch(void* const* d_in, const int* in_sizes, int n_in,
                              void* d_out, int out_size) {
    const float* x        = (const float*)d_in[0];
    const int*   ei       = (const int*)d_in[1];
    const int*   batch    = (const int*)d_in[2];
    const int*   seq      = (const int*)d_in[3];
    const float* W1       = (const float*)d_in[4];
    const float* att_s1   = (const float*)d_in[5];
    const float* att_d1   = (const float*)d_in[6];
    const float* b1       = (const float*)d_in[7];
    const float* W2       = (const float*)d_in[8];
    const float* att_s2   = (const float*)d_in[9];
    const float* att_d2   = (const float*)d_in[10];
    const float* b2       = (const float*)d_in[11];
    const float* Wd       = (const float*)d_in[12];
    const float* bd       = (const float*)d_in[13];
    const float* Pe       = (const float*)d_in[14];
    const float* K1       = (const float*)d_in[15];
    const float* bk1      = (const float*)d_in[16];
    const float* K2       = (const float*)d_in[17];
    const float* bk2      = (const float*)d_in[18];
    const float* Wp       = (const float*)d_in[19];
    const float* bp       = (const float*)d_in[20];
    const float* Wf1      = (const float*)d_in[21];
    const float* bf1      = (const float*)d_in[22];
    const float* Wf2      = (const float*)d_in[23];
    const float* bf2      = (const float*)d_in[24];
    const float* Wo       = (const float*)d_in[25];
    const float* bo       = (const float*)d_in[26];
    float* out = (float*)d_out;

    cudaFuncSetAttribute(k_gat2_mm,    cudaFuncAttributeMaxDynamicSharedMemorySize, 98304);
    cudaFuncSetAttribute(k_conv2_hmma, cudaFuncAttributeMaxDynamicSharedMemorySize, C2_SMEM);

    const int ET = NE + NN;

    cudaStream_t sp;
    cudaStreamCreateWithFlags(&sp, cudaStreamNonBlocking);
    cudaEvent_t e0, ep;
    cudaEventCreateWithFlags(&e0, cudaEventDisableTiming);
    cudaEventCreateWithFlags(&ep, cudaEventDisableTiming);

    cudaEventRecord(e0, 0);
    cudaStreamWaitEvent(sp, e0, 0);

    // ---- protein branch on sp ----
    k_init_prot<<<(NB*128 + 255)/256, 256, 0, sp>>>();
    k_tab<<<17, 256, 0, sp>>>(Pe, K1, bk1);
    {
        dim3 grid((LL + 15)/16, NB);
        k_conv1_apply<<<grid, 256, 0, sp>>>(seq);
    }
    k_conv2_hmma<<<296, 256, C2_SMEM, sp>>>(K2, bk2);
    k_prot<<<(NB*64 + 255)/256, 256, 0, sp>>>(Wp, bp);
    cudaEventRecord(ep, sp);

    // ---- drug branch on the default (capture) stream ----
    k_init_drug<<<2048, 256>>>();
    k_gat1<<<(NN*32 + 255)/256, 256>>>(x, W1, att_s1, att_d1);
    k_edge_den<2><<<(ET + 255)/256, 256>>>(ei);
    k_edge_acc<2><<<(ET*32 + 255)/256, 256>>>(ei);
    k_gat2_mm<<<NN/64, 256, 98304>>>(W2, b1, att_s2, att_d2);
    k_edge_den<1><<<(ET + 255)/256, 256>>>(ei);
    k_edge_acc<1><<<(ET*32 + 255)/256, 256>>>(ei);
    k_pool<<<(NN*32 + 255)/256, 256>>>(batch, b2);
    k_drug<<<(NG*64 + 255)/256, 256>>>(Wd, bd);

    // join: head needs both branches
    cudaStreamWaitEvent(0, ep, 0);
    k_head<<<NG, 128>>>(Wf1, bf1, Wf2, bf2, Wo, bo, out);
}

// round 15
// speedup vs baseline: 2.2805x; 1.0234x over previous
#include <cuda_runtime.h>
#include <cuda_fp16.h>
#include <cstdint>

#define NN 24576
#define NE 98304
#define NG 512
#define NB 512
#define LL 1000

// ---------------- scratch (device globals; runtime alloc forbidden) ----------------
__device__ float g_h1[NN*128];
__device__ float g_as1[NN*2];
__device__ float g_ad1[NN*2];
__device__ float g_den1[NN*2];
__device__ float g_e1[(NE+NN)*2];
__device__ float g_out1[NN*128];
__device__ float g_h2[NN*128];
__device__ float g_as2[NN];
__device__ float g_ad2[NN];
__device__ float g_den2[NN];
__device__ float g_e2[NE+NN];
__device__ float g_out2[NN*128];
__device__ float g_sums[NG*128];
__device__ float g_cnt[NG];
__device__ float g_drug[NG*256];
__device__ float g_T[3*22*64];
__device__ __half g_p1h[NB*LL*64];   // conv1 output (fp16), [b][l][i]
__device__ float g_pmax[NB*128];
__device__ float g_prot[NB*256];

// ---------------- helpers ----------------
__device__ __forceinline__ void red_add_v4(float* addr, float4 v) {
    asm volatile("red.global.add.v4.f32 [%0], {%1, %2, %3, %4};"
                 :: "l"(addr), "f"(v.x), "f"(v.y), "f"(v.z), "f"(v.w) : "memory");
}
__device__ __forceinline__ void atomicMaxFloat(float* addr, float val) {
    if (val >= 0.f) atomicMax((int*)addr, __float_as_int(val));
    else            atomicMin((unsigned int*)addr, __float_as_uint(val));
}
__device__ __forceinline__ float warp_sum(float v) {
    #pragma unroll
    for (int off = 16; off; off >>= 1) v += __shfl_down_sync(0xffffffffu, v, off);
    return v;
}
__device__ __forceinline__ float elu1(float v) { return v > 0.f ? v : expm1f(v); }

__device__ __forceinline__ void mma_fp16(float* c, const uint32_t* a, const uint32_t* b) {
    asm volatile(
        "mma.sync.aligned.m16n8k16.row.col.f32.f16.f16.f32 "
        "{%0,%1,%2,%3}, {%4,%5,%6,%7}, {%8,%9}, {%0,%1,%2,%3};"
        : "+f"(c[0]), "+f"(c[1]), "+f"(c[2]), "+f"(c[3])
        : "r"(a[0]), "r"(a[1]), "r"(a[2]), "r"(a[3]), "r"(b[0]), "r"(b[1]));
}
__device__ __forceinline__ void ldsm_x4(uint32_t* r, uint32_t addr) {
    asm volatile("ldmatrix.sync.aligned.m8n8.x4.shared.b16 {%0,%1,%2,%3}, [%4];"
                 : "=r"(r[0]), "=r"(r[1]), "=r"(r[2]), "=r"(r[3]) : "r"(addr));
}
__device__ __forceinline__ uint32_t smem_u32(const void* p) {
    uint32_t a;
    asm("{ .reg .u64 t; cvta.to.shared.u64 t, %1; cvt.u32.u64 %0, t; }" : "=r"(a) : "l"(p));
    return a;
}

// ---------------- conv2: fp16 HMMA, M-split 2 CTAs/SM, double-buffered A ----------------
#define C2_A0 0
#define C2_A1 9792
#define C2_B  19584
#define C2_B_STRIDE 328
#define C2_SMEM 103552
#define C2_WORK (NB*8*2)

__global__ void __launch_bounds__(256) k_conv2_hmma(const float* __restrict__ K2,
                                                    const float* __restrict__ bk2) {
    extern __shared__ char smem[];
    __half* BhS = reinterpret_cast<__half*>(smem + C2_B);

    int tid = threadIdx.x, wid = tid >> 5, lane = tid & 31;
    int g = lane >> 2, q = lane & 3;
    int mw2 = (wid & 1) * 32;
    int nw4 = (wid >> 1) * 32;
    int m_base = (blockIdx.x & 1) * 64;

    uint32_t sb = smem_u32(smem);
    uint32_t sbB = sb + C2_B;

    uint32_t aoff = (uint32_t)(lane & 15) * 144u + ((lane & 16) ? 16u : 0u);
    uint32_t boff = (uint32_t)(lane & 7) * 656u + ((lane & 8) ? 16u : 0u)
                  + ((lane & 16) ? 8u*656u : 0u);

    for (int idx = tid; idx < 128*320; idx += 256) {
        int n = idx / 320, k = idx - n*320;
        int t = k >> 6, i = k & 63;
        BhS[n*C2_B_STRIDE + k] = __float2half_rn(K2[(n*64 + i)*5 + t]);
    }

    float bias[4][2];
    #pragma unroll
    for (int nt = 0; nt < 4; nt++) {
        int col = nw4 + nt*8 + q*2;
        bias[nt][0] = bk2[col];
        bias[nt][1] = bk2[col + 1];
    }

    auto issue_A = [&](int work_, int buf_) {
        int tile_ = work_ >> 1;
        int b_ = tile_ >> 3;
        int lbase = (tile_ & 7) * 125 + m_base - 2;
        uint32_t sbA_ = sb + (buf_ ? C2_A1 : C2_A0);
        for (int idx = tid; idx < 544; idx += 256) {
            int row = idx >> 3, c = idx & 7;
            int l = lbase + row;
            int lc = l < 0 ? 0 : (l >= LL ? LL-1 : l);
            const __half* gsrc = g_p1h + ((size_t)b_*LL + lc)*64 + c*8;
            uint32_t dst = sbA_ + (uint32_t)(row*144 + c*16);
            int sz = (l >= 0 && l < LL) ? 16 : 0;
            asm volatile("cp.async.cg.shared.global [%0], [%1], 16, %2;"
                         :: "r"(dst), "l"(gsrc), "r"(sz));
        }
        asm volatile("cp.async.commit_group;" ::: "memory");
    };

    issue_A(blockIdx.x, 0);
    int p = 0;
    for (int work = blockIdx.x; work < C2_WORK; work += gridDim.x) {
        int tile = work >> 1;
        int b = tile >> 3, l0 = (tile & 7) * 125;
        int nxt = work + gridDim.x;
        if (nxt < C2_WORK) {
            issue_A(nxt, p ^ 1);                       // buf p^1 free since t-1's post-mainloop barrier
            asm volatile("cp.async.wait_group 1;" ::: "memory");   // A(t) complete
        } else {
            asm volatile("cp.async.wait_group 0;" ::: "memory");
        }
        __syncthreads();
        uint32_t sbA = sb + (p ? C2_A1 : C2_A0);

        float acc[2][4][4];
        #pragma unroll
        for (int mt = 0; mt < 2; mt++)
            #pragma unroll
            for (int nt = 0; nt < 4; nt++)
                #pragma unroll
                for (int j = 0; j < 4; j++) acc[mt][nt][j] = 0.f;

        #pragma unroll
        for (int ks = 0; ks < 20; ks++) {
            int t = ks >> 2;
            uint32_t kb = (uint32_t)((ks & 3) * 32);
            uint32_t ah[2][4], bb[2][4];
            uint32_t aBase = (uint32_t)((mw2 + t) * 144) + kb + aoff;
            #pragma unroll
            for (int mt = 0; mt < 2; mt++)
                ldsm_x4(ah[mt], sbA + aBase + (uint32_t)(mt*16*144));
            uint32_t bBase = (uint32_t)(nw4 * 656) + (uint32_t)(t * 128) + kb + boff;
            #pragma unroll
            for (int np = 0; np < 2; np++)
                ldsm_x4(bb[np], sbB + bBase + (uint32_t)(np*16*656));
            #pragma unroll
            for (int mt = 0; mt < 2; mt++)
                #pragma unroll
                for (int nt = 0; nt < 4; nt++)
                    mma_fp16(acc[mt][nt], ah[mt], &bb[nt >> 1][(nt & 1)*2]);
        }
        __syncthreads();               // all threads done reading buf p (reused at t+1 issue)

        // epilogue: raw max over valid l, elu applied once at the end (monotonic)
        float mx[4][2];
        #pragma unroll
        for (int nt = 0; nt < 4; nt++) { mx[nt][0] = -3.0e38f; mx[nt][1] = -3.0e38f; }
        #pragma unroll
        for (int mt = 0; mt < 2; mt++) {
            int lr = l0 + m_base + mw2 + mt*16 + g;
            bool v0 = lr < LL, v1 = (lr + 8) < LL;
            #pragma unroll
            for (int nt = 0; nt < 4; nt++) {
                if (v0) {
                    mx[nt][0] = fmaxf(mx[nt][0], acc[mt][nt][0]);
                    mx[nt][1] = fmaxf(mx[nt][1], acc[mt][nt][1]);
                }
                if (v1) {
                    mx[nt][0] = fmaxf(mx[nt][0], acc[mt][nt][2]);
                    mx[nt][1] = fmaxf(mx[nt][1], acc[mt][nt][3]);
                }
            }
        }
        #pragma unroll
        for (int nt = 0; nt < 4; nt++) {
            #pragma unroll
            for (int j = 0; j < 2; j++) {
                float v = mx[nt][j];
                v = fmaxf(v, __shfl_xor_sync(0xffffffffu, v, 4));
                v = fmaxf(v, __shfl_xor_sync(0xffffffffu, v, 8));
                v = fmaxf(v, __shfl_xor_sync(0xffffffffu, v, 16));
                if (lane < 4)
                    atomicMaxFloat(&g_pmax[b*128 + nw4 + nt*8 + lane*2 + j],
                                   elu1(v + bias[nt][j]));
            }
        }
        p ^= 1;
    }
}

// ---------------- conv1 token tables ----------------
__global__ void k_tab(const float* __restrict__ Pe, const float* __restrict__ K1,
                      const float* __restrict__ bk1) {
    int idx = blockIdx.x * blockDim.x + threadIdx.x;
    if (idx >= 3*22*64) return;
    int o = idx & 63, r = idx >> 6;
    int t = r % 22, k = r / 22;
    float acc = (k == 1) ? bk1[o] : 0.f;
    #pragma unroll 8
    for (int i = 0; i < 64; i++) acc += Pe[t*64 + i] * K1[(o*64 + i)*3 + k];
    g_T[idx] = acc;
}

// ---------------- conv1 apply: writes fp16 directly ----------------
__global__ void __launch_bounds__(256) k_conv1_apply(const int* __restrict__ seq) {
    int b = blockIdx.y;
    int lofs = threadIdx.x >> 4, lq = threadIdx.x & 15;
    int l = blockIdx.x * 16 + lofs;
    if (l >= LL) return;
    int s1 = seq[b*LL + l];
    int c = lq * 4;
    float4 v = *reinterpret_cast<const float4*>(&g_T[(22 + s1)*64 + c]);
    if (l > 0) {
        int s0 = seq[b*LL + l - 1];
        float4 a = *reinterpret_cast<const float4*>(&g_T[s0*64 + c]);
        v.x += a.x; v.y += a.y; v.z += a.z; v.w += a.w;
    }
    if (l < LL-1) {
        int s2 = seq[b*LL + l + 1];
        float4 a = *reinterpret_cast<const float4*>(&g_T[(44 + s2)*64 + c]);
        v.x += a.x; v.y += a.y; v.z += a.z; v.w += a.w;
    }
    __half2 h0 = __floats2half2_rn(elu1(v.x), elu1(v.y));
    __half2 h1 = __floats2half2_rn(elu1(v.z), elu1(v.w));
    size_t base = ((size_t)b*LL + l)*64 + c;
    *reinterpret_cast<__half2*>(&g_p1h[base])     = h0;
    *reinterpret_cast<__half2*>(&g_p1h[base + 2]) = h1;
}

// ---------------- init ----------------
__global__ void k_init_prot() {
    int i = blockIdx.x * blockDim.x + threadIdx.x;
    if (i < NB*128) g_pmax[i] = -3.0e38f;
}

// ---------------- GAT1 GEMM + fused attention scalars (warp per node) ----------------
__global__ void k_gat1(const float* __restrict__ x, const float* __restrict__ W1,
                       const float* __restrict__ att_s, const float* __restrict__ att_d) {
    int gw = (blockIdx.x * blockDim.x + threadIdx.x) >> 5;
    int lane = threadIdx.x & 31;
    if (gw >= NN) return;
    float xv[5];
    #pragma unroll
    for (int f = 0; f < 5; f++) xv[f] = x[gw*5 + f];
    int c = lane * 4;
    float4 h;
    float* hp = reinterpret_cast<float*>(&h);
    #pragma unroll
    for (int j = 0; j < 4; j++) {
        float a = 0.f;
        #pragma unroll
        for (int f = 0; f < 5; f++) a += xv[f] * W1[f*128 + c + j];
        hp[j] = a;
    }
    *reinterpret_cast<float4*>(&g_h1[(size_t)gw*128 + c]) = h;
    float s = 0.f, d = 0.f;
    #pragma unroll
    for (int j = 0; j < 4; j++) { s += hp[j]*att_s[c + j]; d += hp[j]*att_d[c + j]; }
    float s0 = (lane < 16) ? s : 0.f, s1 = (lane < 16) ? 0.f : s;
    float d0 = (lane < 16) ? d : 0.f, d1 = (lane < 16) ? 0.f : d;
    s0 = warp_sum(s0); s1 = warp_sum(s1); d0 = warp_sum(d0); d1 = warp_sum(d1);
    if (lane == 0) {
        g_as1[gw*2] = s0; g_as1[gw*2+1] = s1;
        g_ad1[gw*2] = d0; g_ad1[gw*2+1] = d1;
    }
}

// ---------------- edge passes (softmax without max-shift: scores are O(1)) ----------------
template<int H>
__global__ void k_edge_den(const int* __restrict__ ei) {
    int e = blockIdx.x * blockDim.x + threadIdx.x;
    const int ET = NE + NN;
    if (e >= ET) return;
    int src, dst;
    if (e < NE) { src = ei[e]; dst = ei[NE + e]; } else { src = dst = e - NE; }
    const float* as_ = (H == 2) ? g_as1 : g_as2;
    const float* ad_ = (H == 2) ? g_ad1 : g_ad2;
    float* den_ = (H == 2) ? g_den1 : g_den2;
    float* e_ = (H == 2) ? g_e1 : g_e2;
    #pragma unroll
    for (int h = 0; h < H; h++) {
        float v = as_[src*H+h] + ad_[dst*H+h];
        v = v > 0.f ? v : 0.2f * v;
        float w = expf(v);
        e_[e*H+h] = w;
        atomicAdd(&den_[dst*H+h], w);
    }
}

template<int H>
__global__ void k_edge_acc(const int* __restrict__ ei) {
    int gw = (blockIdx.x * blockDim.x + threadIdx.x) >> 5;
    int lane = threadIdx.x & 31;
    const int ET = NE + NN;
    if (gw >= ET) return;
    int src, dst;
    if (gw < NE) { src = ei[gw]; dst = ei[NE + gw]; } else { src = dst = gw - NE; }
    const float* den_ = (H == 2) ? g_den1 : g_den2;
    const float* e_ = (H == 2) ? g_e1 : g_e2;
    const float* hin = (H == 2) ? g_h1 : g_h2;
    float* outp = (H == 2) ? g_out1 : g_out2;
    int h = (H == 2 && lane >= 16) ? 1 : 0;
    float alpha = e_[gw*H + h] / (den_[dst*H + h] + 1e-16f);
    float4 v = *reinterpret_cast<const float4*>(&hin[(size_t)src*128 + lane*4]);
    v.x *= alpha; v.y *= alpha; v.z *= alpha; v.w *= alpha;
    red_add_v4(&outp[(size_t)dst*128 + lane*4], v);
}

// ---------------- GAT2 GEMM (bias1+elu fused on A-load; att2 fused in epilogue) ----------------
__global__ void __launch_bounds__(256) k_gat2_mm(const float* __restrict__ W2,
                                                 const float* __restrict__ b1,
                                                 const float* __restrict__ att_s,
                                                 const float* __restrict__ att_d) {
    extern __shared__ float sm[];
    float* sg = sm;
    float* sw = sm + 64*128;
    int base = blockIdx.x * 64;
    int tid = threadIdx.x;
    for (int idx = tid; idx < 64*128; idx += 256)
        sg[idx] = elu1(g_out1[(size_t)base*128 + idx] + b1[idx & 127]);
    for (int idx = tid; idx < 128*128; idx += 256) sw[idx] = W2[idx];
    __syncthreads();
    int r0 = (tid >> 4) << 2;
    int c0 = (tid & 15) << 3;
    float acc[4][8];
    #pragma unroll
    for (int i = 0; i < 4; i++)
        #pragma unroll
        for (int j = 0; j < 8; j++) acc[i][j] = 0.f;
    #pragma unroll 4
    for (int k = 0; k < 128; k++) {
        float a[4];
        #pragma unroll
        for (int i = 0; i < 4; i++) a[i] = sg[(r0+i)*128 + k];
        float4 b0 = *reinterpret_cast<const float4*>(&sw[k*128 + c0]);
        float4 b1v = *reinterpret_cast<const float4*>(&sw[k*128 + c0 + 4]);
        #pragma unroll
        for (int i = 0; i < 4; i++) {
            acc[i][0] += a[i]*b0.x; acc[i][1] += a[i]*b0.y;
            acc[i][2] += a[i]*b0.z; acc[i][3] += a[i]*b0.w;
            acc[i][4] += a[i]*b1v.x; acc[i][5] += a[i]*b1v.y;
            acc[i][6] += a[i]*b1v.z; acc[i][7] += a[i]*b1v.w;
        }
    }
    #pragma unroll
    for (int i = 0; i < 4; i++) {
        float4 v0 = make_float4(acc[i][0], acc[i][1], acc[i][2], acc[i][3]);
        float4 v1 = make_float4(acc[i][4], acc[i][5], acc[i][6], acc[i][7]);
        *reinterpret_cast<float4*>(&g_h2[(size_t)(base+r0+i)*128 + c0]) = v0;
        *reinterpret_cast<float4*>(&g_h2[(size_t)(base+r0+i)*128 + c0 + 4]) = v1;
    }
    float ps[4], pd[4];
    #pragma unroll
    for (int i = 0; i < 4; i++) {
        float s = 0.f, d = 0.f;
        #pragma unroll
        for (int j = 0; j < 8; j++) {
            s += acc[i][j] * att_s[c0 + j];
            d += acc[i][j] * att_d[c0 + j];
        }
        ps[i] = s; pd[i] = d;
    }
    #pragma unroll
    for (int i = 0; i < 4; i++) {
        #pragma unroll
        for (int off = 8; off; off >>= 1) {
            ps[i] += __shfl_down_sync(0xffffffffu, ps[i], off, 16);
            pd[i] += __shfl_down_sync(0xffffffffu, pd[i], off, 16);
        }
    }
    if ((tid & 15) == 0) {
        #pragma unroll
        for (int i = 0; i < 4; i++) {
            g_as2[base + r0 + i] = ps[i];
            g_ad2[base + r0 + i] = pd[i];
        }
    }
}

// ---------------- pooling (bias2+elu fused) + dense ----------------
__global__ void k_pool(const int* __restrict__ batch, const float* __restrict__ b2) {
    int gw = (blockIdx.x * blockDim.x + threadIdx.x) >> 5;
    int lane = threadIdx.x & 31;
    if (gw >= NN) return;
    int g = batch[gw];
    int c = lane * 4;
    float4 v = *reinterpret_cast<const float4*>(&g_out2[(size_t)gw*128 + c]);
    v.x = elu1(v.x + b2[c]);
    v.y = elu1(v.y + b2[c+1]);
    v.z = elu1(v.z + b2[c+2]);
    v.w = elu1(v.w + b2[c+3]);
    red_add_v4(&g_sums[g*128 + c], v);
    if (lane == 0) atomicAdd(&g_cnt[g], 1.0f);
}

__global__ void k_drug(const float* __restrict__ Wd, const float* __restrict__ bd) {
    int idx = blockIdx.x * blockDim.x + threadIdx.x;
    if (idx >= NG*64) return;
    int g = idx >> 6, j4 = (idx & 63) * 4;
    float invc = 1.f / fmaxf(g_cnt[g], 1.f);
    const float* srow = g_sums + g*128;
    float4 a = make_float4(0.f, 0.f, 0.f, 0.f);
    #pragma unroll 8
    for (int k = 0; k < 128; k++) {
        float s = srow[k];
        float4 w = *reinterpret_cast<const float4*>(&Wd[k*256 + j4]);
        a.x += s*w.x; a.y += s*w.y; a.z += s*w.z; a.w += s*w.w;
    }
    float4 r;
    r.x = fmaxf(a.x * invc + bd[j4],     0.f);
    r.y = fmaxf(a.y * invc + bd[j4 + 1], 0.f);
    r.z = fmaxf(a.z * invc + bd[j4 + 2], 0.f);
    r.w = fmaxf(a.w * invc + bd[j4 + 3], 0.f);
    *reinterpret_cast<float4*>(&g_drug[g*256 + j4]) = r;
}

__global__ void k_prot(const float* __restrict__ Wp, const float* __restrict__ bp) {
    int idx = blockIdx.x * blockDim.x + threadIdx.x;
    if (idx >= NB*64) return;
    int g = idx >> 6, j4 = (idx & 63) * 4;
    const float* srow = g_pmax + g*128;
    float4 a = make_float4(0.f, 0.f, 0.f, 0.f);
    #pragma unroll 8
    for (int k = 0; k < 128; k++) {
        float s = srow[k];
        float4 w = *reinterpret_cast<const float4*>(&Wp[k*256 + j4]);
        a.x += s*w.x; a.y += s*w.y; a.z += s*w.z; a.w += s*w.w;
    }
    float4 r;
    r.x = fmaxf(a.x + bp[j4],     0.f);
    r.y = fmaxf(a.y + bp[j4 + 1], 0.f);
    r.z = fmaxf(a.z + bp[j4 + 2], 0.f);
    r.w = fmaxf(a.w + bp[j4 + 3], 0.f);
    *reinterpret_cast<float4*>(&g_prot[g*256 + j4]) = r;
}

// ---------------- head MLP ----------------
__global__ void __launch_bounds__(128) k_head(const float* __restrict__ Wf1, const float* __restrict__ bf1,
                                              const float* __restrict__ Wf2, const float* __restrict__ bf2,
                                              const float* __restrict__ Wo, const float* __restrict__ bo,
                                              float* __restrict__ out) {
    __shared__ float sh[512];
    __shared__ float s1[128];
    __shared__ float s2[64];
    int g = blockIdx.x, tid = threadIdx.x;
    for (int i = tid; i < 256; i += 128) {
        sh[i]       = g_drug[g*256 + i];
        sh[256 + i] = g_prot[g*256 + i];
    }
    __syncthreads();
    float acc = 0.f;
    #pragma unroll 8
    for (int k = 0; k < 512; k++) acc += sh[k] * Wf1[k*128 + tid];
    s1[tid] = fmaxf(acc + bf1[tid], 0.f);
    __syncthreads();
    if (tid < 64) {
        float a = 0.f;
        #pragma unroll 8
        for (int k = 0; k < 128; k++) a += s1[k] * Wf2[k*64 + tid];
        s2[tid] = fmaxf(a + bf2[tid], 0.f);
    }
    __syncthreads();
    if (tid < 32) {
        float a = s2[tid]*Wo[tid] + s2[tid+32]*Wo[tid+32];
        a = warp_sum(a);
        if (tid == 0) out[g] = a + bo[0];
    }
}

// ---------------- launch: protein branch forked onto a low-priority side stream ----------------
extern "C" void kernel_launch(void* const* d_in, const int* in_sizes, int n_in,
                              void* d_out, int out_size) {
    const float* x        = (const float*)d_in[0];
    const int*   ei       = (const int*)d_in[1];
    const int*   batch    = (const int*)d_in[2];
    const int*   seq      = (const int*)d_in[3];
    const float* W1       = (const float*)d_in[4];
    const float* att_s1   = (const float*)d_in[5];
    const float* att_d1   = (const float*)d_in[6];
    const float* b1       = (const float*)d_in[7];
    const float* W2       = (const float*)d_in[8];
    const float* att_s2   = (const float*)d_in[9];
    const float* att_d2   = (const float*)d_in[10];
    const float* b2       = (const float*)d_in[11];
    const float* Wd       = (const float*)d_in[12];
    const float* bd       = (const float*)d_in[13];
    const float* Pe       = (const float*)d_in[14];
    const float* K1       = (const float*)d_in[15];
    const float* bk1      = (const float*)d_in[16];
    const float* K2       = (const float*)d_in[17];
    const float* bk2      = (const float*)d_in[18];
    const float* Wp       = (const float*)d_in[19];
    const float* bp       = (const float*)d_in[20];
    const float* Wf1      = (const float*)d_in[21];
    const float* bf1      = (const float*)d_in[22];
    const float* Wf2      = (const float*)d_in[23];
    const float* bf2      = (const float*)d_in[24];
    const float* Wo       = (const float*)d_in[25];
    const float* bo       = (const float*)d_in[26];
    float* out = (float*)d_out;

    cudaFuncSetAttribute(k_gat2_mm,    cudaFuncAttributeMaxDynamicSharedMemorySize, 98304);
    cudaFuncSetAttribute(k_conv2_hmma, cudaFuncAttributeMaxDynamicSharedMemorySize, C2_SMEM);

    const int ET = NE + NN;

    int prLo = 0, prHi = 0;
    cudaDeviceGetStreamPriorityRange(&prLo, &prHi);
    cudaStream_t sp;
    cudaStreamCreateWithPriority(&sp, cudaStreamNonBlocking, prLo);  // protein = low priority
    cudaEvent_t e0, ep;
    cudaEventCreateWithFlags(&e0, cudaEventDisableTiming);
    cudaEventCreateWithFlags(&ep, cudaEventDisableTiming);

    cudaEventRecord(e0, 0);
    cudaStreamWaitEvent(sp, e0, 0);

    // ---- protein branch on sp ----
    k_init_prot<<<(NB*128 + 255)/256, 256, 0, sp>>>();
    k_tab<<<17, 256, 0, sp>>>(Pe, K1, bk1);
    {
        dim3 grid((LL + 15)/16, NB);
        k_conv1_apply<<<grid, 256, 0, sp>>>(seq);
    }
    k_conv2_hmma<<<296, 256, C2_SMEM, sp>>>(K2, bk2);
    k_prot<<<(NB*64 + 255)/256, 256, 0, sp>>>(Wp, bp);
    cudaEventRecord(ep, sp);

    // ---- drug branch on the default (capture) stream ----
    {
        void* p;
        cudaGetSymbolAddress(&p, g_out1);  cudaMemsetAsync(p, 0, sizeof(float)*NN*128, 0);
        cudaGetSymbolAddress(&p, g_out2);  cudaMemsetAsync(p, 0, sizeof(float)*NN*128, 0);
        cudaGetSymbolAddress(&p, g_den1);  cudaMemsetAsync(p, 0, sizeof(float)*NN*2, 0);
        cudaGetSymbolAddress(&p, g_den2);  cudaMemsetAsync(p, 0, sizeof(float)*NN, 0);
        cudaGetSymbolAddress(&p, g_sums);  cudaMemsetAsync(p, 0, sizeof(float)*NG*128, 0);
        cudaGetSymbolAddress(&p, g_cnt);   cudaMemsetAsync(p, 0, sizeof(float)*NG, 0);
    }
    k_gat1<<<(NN*32 + 255)/256, 256>>>(x, W1, att_s1, att_d1);
    k_edge_den<2><<<(ET + 255)/256, 256>>>(ei);
    k_edge_acc<2><<<(ET*32 + 255)/256, 256>>>(ei);
    k_gat2_mm<<<NN/64, 256, 98304>>>(W2, b1, att_s2, att_d2);
    k_edge_den<1><<<(ET + 255)/256, 256>>>(ei);
    k_edge_acc<1><<<(ET*32 + 255)/256, 256>>>(ei);
    k_pool<<<(NN*32 + 255)/256, 256>>>(batch, b2);
    k_drug<<<(NG*64 + 255)/256, 256>>>(Wd, bd);

    // join: head needs both branches
    cudaStreamWaitEvent(0, ep, 0);
    k_head<<<NG, 128>>>(Wf1, bf1, Wf2, bf2, Wo, bo, out);
}